// round 2
// baseline (speedup 1.0000x reference)
#include <cuda_runtime.h>
#include <math.h>

#define HH 56
#define WW 56
#define WS 7
#define SH 3
#define NHEAD 4
#define HD 32
#define CDIM 128
#define NTOK 49
#define NWIN 64           // windows per image
#define BIMG 64           // batch
#define MROWS (BIMG * NWIN * NTOK)   // 200704
#define LSEQ (HH * WW)
#define EPS 1e-5f

// ---------------- scratch (static device arrays; no allocs) ----------------
__device__ float g_xw[(size_t)MROWS * CDIM];     // LN1+partitioned tokens; reused for h2
__device__ float g_qkv[(size_t)MROWS * 3 * CDIM];
__device__ float g_att[(size_t)MROWS * CDIM];    // attention output (window order)
__device__ float g_hid[(size_t)MROWS * 512];     // MLP hidden

// ---------------- LN helpers ----------------
__device__ __forceinline__ float block128_sum(float v, float* red, int tid) {
    // 128 threads = 4 warps
    float s = v;
    #pragma unroll
    for (int o = 16; o; o >>= 1) s += __shfl_xor_sync(0xffffffffu, s, o);
    int wid = tid >> 5, lane = tid & 31;
    if (lane == 0) red[wid] = s;
    __syncthreads();
    return red[0] + red[1] + red[2] + red[3];
}

// Kernel 1: LN1 + roll(-SH) + window partition.
// Output row r = b*3136 + win*49 + n  (window order)
__global__ void ln1_partition(const float* __restrict__ x,
                              const float* __restrict__ g,
                              const float* __restrict__ b,
                              float* __restrict__ out) {
    __shared__ float red1[4];
    __shared__ float red2[4];
    int r = blockIdx.x;
    int tid = threadIdx.x;

    int bi  = r / (NWIN * NTOK);
    int t   = r % (NWIN * NTOK);
    int win = t / NTOK;
    int n   = t % NTOK;
    int hh = (win / 8) * WS + n / WS;   // shifted-image coords
    int ww = (win % 8) * WS + n % WS;
    int hs = (hh + SH) % HH;            // source in original image
    int ws = (ww + SH) % WW;
    long src = ((long)bi * LSEQ + hs * WW + ws) * CDIM;

    float v = x[src + tid];
    float tot = block128_sum(v, red1, tid);
    float mu = tot * (1.f / CDIM);
    float d = v - mu;
    float tot2 = block128_sum(d * d, red2, tid);
    float inv = rsqrtf(tot2 * (1.f / CDIM) + EPS);
    out[(long)r * CDIM + tid] = d * inv * g[tid] + b[tid];
}

// Kernel 5: plain LN (row-identity)
__global__ void ln_plain(const float* __restrict__ x,
                         const float* __restrict__ g,
                         const float* __restrict__ b,
                         float* __restrict__ out) {
    __shared__ float red1[4];
    __shared__ float red2[4];
    int r = blockIdx.x;
    int tid = threadIdx.x;
    float v = x[(long)r * CDIM + tid];
    float tot = block128_sum(v, red1, tid);
    float mu = tot * (1.f / CDIM);
    float d = v - mu;
    float tot2 = block128_sum(d * d, red2, tid);
    float inv = rsqrtf(tot2 * (1.f / CDIM) + EPS);
    out[(long)r * CDIM + tid] = d * inv * g[tid] + b[tid];
}

// ---------------- generic SGEMM: C(MROWS x N) = A(MROWS x K) @ B(K x N) + bias ----------------
// BM=BN=64, BK=16, 256 threads, 4x4 microtile.
// EPI: 0 plain, 1 proj(scatter+residual), 2 gelu, 3 residual add
template<int N, int K, int EPI>
__global__ void gemm64(const float* __restrict__ A, const float* __restrict__ B,
                       const float* __restrict__ bias, float* __restrict__ C,
                       const float* __restrict__ res) {
    __shared__ float As[16][64];
    __shared__ float Bs[16][64];
    int tid = threadIdx.x;
    int tx = tid & 15, ty = tid >> 4;
    int m0 = blockIdx.x * 64;
    int n0 = blockIdx.y * 64;

    float acc[4][4] = {};

    int ar = tid >> 2;            // 0..63
    int ac = (tid & 3) * 4;       // 0,4,8,12
    int br = tid >> 4;            // 0..15
    int bc = (tid & 15) * 4;      // 0..60

    for (int k0 = 0; k0 < K; k0 += 16) {
        float4 av = *(const float4*)&A[((long)(m0 + ar)) * K + k0 + ac];
        As[ac + 0][ar] = av.x;
        As[ac + 1][ar] = av.y;
        As[ac + 2][ar] = av.z;
        As[ac + 3][ar] = av.w;
        *(float4*)&Bs[br][bc] = *(const float4*)&B[(long)(k0 + br) * N + n0 + bc];
        __syncthreads();
        #pragma unroll
        for (int k = 0; k < 16; k++) {
            float4 a4 = *(const float4*)&As[k][ty * 4];
            float4 b4 = *(const float4*)&Bs[k][tx * 4];
            acc[0][0] += a4.x * b4.x; acc[0][1] += a4.x * b4.y; acc[0][2] += a4.x * b4.z; acc[0][3] += a4.x * b4.w;
            acc[1][0] += a4.y * b4.x; acc[1][1] += a4.y * b4.y; acc[1][2] += a4.y * b4.z; acc[1][3] += a4.y * b4.w;
            acc[2][0] += a4.z * b4.x; acc[2][1] += a4.z * b4.y; acc[2][2] += a4.z * b4.z; acc[2][3] += a4.z * b4.w;
            acc[3][0] += a4.w * b4.x; acc[3][1] += a4.w * b4.y; acc[3][2] += a4.w * b4.z; acc[3][3] += a4.w * b4.w;
        }
        __syncthreads();
    }

    #pragma unroll
    for (int i = 0; i < 4; i++) {
        int row = m0 + ty * 4 + i;
        long drow = row;
        if (EPI == 1) {
            int bi  = row / (NWIN * NTOK);
            int t   = row % (NWIN * NTOK);
            int win = t / NTOK;
            int n   = t % NTOK;
            int hh = (win / 8) * WS + n / WS;
            int ww = (win % 8) * WS + n % WS;
            int hd2 = (hh + SH) % HH;
            int wd2 = (ww + SH) % WW;
            drow = (long)bi * LSEQ + hd2 * WW + wd2;
        }
        #pragma unroll
        for (int j = 0; j < 4; j++) {
            int col = n0 + tx * 4 + j;
            float v = acc[i][j] + bias[col];
            if (EPI == 0) {
                C[(long)row * N + col] = v;
            } else if (EPI == 1) {
                C[drow * N + col] = res[drow * N + col] + v;
            } else if (EPI == 2) {
                v = 0.5f * v * (1.0f + erff(v * 0.70710678118654752f));
                C[(long)row * N + col] = v;
            } else { // 3
                C[(long)row * N + col] = res[(long)row * N + col] + v;
            }
        }
    }
}

// ---------------- attention: one block per (window, head) ----------------
__global__ void attn_kernel(const float* __restrict__ qkv,
                            const float* __restrict__ rpb,
                            float* __restrict__ out) {
    const int wg = blockIdx.x;      // global window [0, 4096)
    const int head = blockIdx.y;    // [0, 4)
    const int tid = threadIdx.x;    // 256 threads
    const float scale = rsqrtf((float)HD);

    __shared__ float qs[NTOK * HD];
    __shared__ float ks[NTOK * HD];
    __shared__ float vs[NTOK * HD];
    __shared__ float S[NTOK * NTOK];
    __shared__ int lab[NTOK];

    // region labels for shift mask (window within image)
    if (tid < NTOK) {
        int wi = wg & (NWIN - 1);
        int h = (wi / 8) * WS + tid / WS;
        int w = (wi % 8) * WS + tid % WS;
        int rh = (h < HH - WS) ? 0 : ((h < HH - SH) ? 1 : 2);
        int rw = (w < WW - WS) ? 0 : ((w < WW - SH) ? 1 : 2);
        lab[tid] = rh * 3 + rw;
    }

    for (int i = tid; i < NTOK * HD; i += 256) {
        int n = i / HD, d = i % HD;
        long base = ((long)wg * NTOK + n) * (3 * CDIM) + head * HD + d;
        qs[i] = qkv[base] * scale;
        ks[i] = qkv[base + CDIM];
        vs[i] = qkv[base + 2 * CDIM];
    }
    __syncthreads();

    // S = q k^T + bias + mask
    for (int idx = tid; idx < NTOK * NTOK; idx += 256) {
        int n = idx / NTOK, m = idx % NTOK;
        float acc = 0.f;
        #pragma unroll
        for (int d = 0; d < HD; d++) acc += qs[n * HD + d] * ks[m * HD + d];
        int rn = n / WS, cn = n % WS, rm = m / WS, cm = m % WS;
        int ridx = (rn - rm + WS - 1) * (2 * WS - 1) + (cn - cm + WS - 1);
        acc += rpb[ridx * NHEAD + head];
        if (lab[n] != lab[m]) acc -= 100.0f;
        S[idx] = acc;
    }
    __syncthreads();

    // softmax: warp per row
    int wid = tid >> 5, lane = tid & 31;
    for (int n = wid; n < NTOK; n += 8) {
        float mx = -1e30f;
        for (int m = lane; m < NTOK; m += 32) mx = fmaxf(mx, S[n * NTOK + m]);
        #pragma unroll
        for (int o = 16; o; o >>= 1) mx = fmaxf(mx, __shfl_xor_sync(0xffffffffu, mx, o));
        float sum = 0.f;
        for (int m = lane; m < NTOK; m += 32) {
            float e = expf(S[n * NTOK + m] - mx);
            S[n * NTOK + m] = e;
            sum += e;
        }
        #pragma unroll
        for (int o = 16; o; o >>= 1) sum += __shfl_xor_sync(0xffffffffu, sum, o);
        float inv = 1.0f / sum;
        for (int m = lane; m < NTOK; m += 32) S[n * NTOK + m] *= inv;
    }
    __syncthreads();

    // out = S @ v ; write into (row, head*HD + d) of CDIM-wide layout
    for (int i = tid; i < NTOK * HD; i += 256) {
        int n = i / HD, d = i % HD;
        float acc = 0.f;
        #pragma unroll
        for (int m = 0; m < NTOK; m++) acc += S[n * NTOK + m] * vs[m * HD + d];
        out[((long)wg * NTOK + n) * CDIM + head * HD + d] = acc;
    }
}

// ---------------- launch ----------------
extern "C" void kernel_launch(void* const* d_in, const int* in_sizes, int n_in,
                              void* d_out, int out_size) {
    const float* x      = (const float*)d_in[0];
    const float* qkv_w  = (const float*)d_in[1];
    const float* qkv_b  = (const float*)d_in[2];
    const float* proj_w = (const float*)d_in[3];
    const float* proj_b = (const float*)d_in[4];
    const float* rpb    = (const float*)d_in[5];
    const float* n1g    = (const float*)d_in[6];
    const float* n1b    = (const float*)d_in[7];
    const float* n2g    = (const float*)d_in[8];
    const float* n2b    = (const float*)d_in[9];
    const float* fc1_w  = (const float*)d_in[10];
    const float* fc1_b  = (const float*)d_in[11];
    const float* fc2_w  = (const float*)d_in[12];
    const float* fc2_b  = (const float*)d_in[13];
    float* out = (float*)d_out;

    float *xw, *qkvb, *att, *hid;
    cudaGetSymbolAddress((void**)&xw,  g_xw);
    cudaGetSymbolAddress((void**)&qkvb, g_qkv);
    cudaGetSymbolAddress((void**)&att, g_att);
    cudaGetSymbolAddress((void**)&hid, g_hid);

    // 1. LN1 + roll + partition
    ln1_partition<<<MROWS, 128>>>(x, n1g, n1b, xw);
    // 2. QKV GEMM
    gemm64<384, 128, 0><<<dim3(MROWS / 64, 6), 256>>>(xw, qkv_w, qkv_b, qkvb, nullptr);
    // 3. attention
    attn_kernel<<<dim3(BIMG * NWIN, NHEAD), 256>>>(qkvb, rpb, att);
    // 4. proj GEMM + window reverse + roll + residual -> y in d_out
    gemm64<128, 128, 1><<<dim3(MROWS / 64, 2), 256>>>(att, proj_w, proj_b, out, x);
    // 5. LN2 -> xw
    ln_plain<<<MROWS, 128>>>(out, n2g, n2b, xw);
    // 6. fc1 + GELU
    gemm64<512, 128, 2><<<dim3(MROWS / 64, 8), 256>>>(xw, fc1_w, fc1_b, hid, nullptr);
    // 7. fc2 + residual -> d_out
    gemm64<128, 512, 3><<<dim3(MROWS / 64, 2), 256>>>(hid, fc2_w, fc2_b, out, out);
}

// round 4
// speedup vs baseline: 1.7669x; 1.7669x over previous
#include <cuda_runtime.h>
#include <math.h>

#define HH 56
#define WW 56
#define WS 7
#define SH 3
#define NHEAD 4
#define HD 32
#define CDIM 128
#define NTOK 49
#define NWIN 64
#define BIMG 64
#define MROWS (BIMG * NWIN * NTOK)   // 200704
#define LSEQ (HH * WW)
#define EPS 1e-5f

// ---------------- scratch ----------------
__device__ float g_xw[(size_t)MROWS * CDIM];
__device__ float g_qkv[(size_t)MROWS * 3 * CDIM];
__device__ float g_att[(size_t)MROWS * CDIM];
__device__ float g_hid[(size_t)MROWS * 512];

// ---------------- helpers ----------------
__device__ __forceinline__ float to_tf32(float x) {
    unsigned u;
    asm("cvt.rna.tf32.f32 %0, %1;" : "=r"(u) : "f"(x));
    return __uint_as_float(u);
}

__device__ __forceinline__ void mma_tf32(float* d, const float* a, const float* b) {
    asm volatile(
        "mma.sync.aligned.m16n8k8.row.col.f32.tf32.tf32.f32 "
        "{%0,%1,%2,%3}, {%4,%5,%6,%7}, {%8,%9}, {%0,%1,%2,%3};\n"
        : "+f"(d[0]), "+f"(d[1]), "+f"(d[2]), "+f"(d[3])
        : "r"(__float_as_uint(a[0])), "r"(__float_as_uint(a[1])),
          "r"(__float_as_uint(a[2])), "r"(__float_as_uint(a[3])),
          "r"(__float_as_uint(b[0])), "r"(__float_as_uint(b[1])));
}

__device__ __forceinline__ float block128_sum(float v, float* red, int tid) {
    float s = v;
    #pragma unroll
    for (int o = 16; o; o >>= 1) s += __shfl_xor_sync(0xffffffffu, s, o);
    int wid = tid >> 5, lane = tid & 31;
    if (lane == 0) red[wid] = s;
    __syncthreads();
    return red[0] + red[1] + red[2] + red[3];
}

// ---------------- LN kernels ----------------
__global__ void ln1_partition(const float* __restrict__ x,
                              const float* __restrict__ g,
                              const float* __restrict__ b,
                              float* __restrict__ out) {
    __shared__ float red1[4];
    __shared__ float red2[4];
    int r = blockIdx.x;
    int tid = threadIdx.x;

    int bi  = r / (NWIN * NTOK);
    int t   = r % (NWIN * NTOK);
    int win = t / NTOK;
    int n   = t % NTOK;
    int hh = (win / 8) * WS + n / WS;
    int ww = (win % 8) * WS + n % WS;
    int hs = (hh + SH) % HH;
    int ws = (ww + SH) % WW;
    long src = ((long)bi * LSEQ + hs * WW + ws) * CDIM;

    float v = x[src + tid];
    float tot = block128_sum(v, red1, tid);
    float mu = tot * (1.f / CDIM);
    float d = v - mu;
    float tot2 = block128_sum(d * d, red2, tid);
    float inv = rsqrtf(tot2 * (1.f / CDIM) + EPS);
    out[(long)r * CDIM + tid] = d * inv * g[tid] + b[tid];
}

__global__ void ln_plain(const float* __restrict__ x,
                         const float* __restrict__ g,
                         const float* __restrict__ b,
                         float* __restrict__ out) {
    __shared__ float red1[4];
    __shared__ float red2[4];
    int r = blockIdx.x;
    int tid = threadIdx.x;
    float v = x[(long)r * CDIM + tid];
    float tot = block128_sum(v, red1, tid);
    float mu = tot * (1.f / CDIM);
    float d = v - mu;
    float tot2 = block128_sum(d * d, red2, tid);
    float inv = rsqrtf(tot2 * (1.f / CDIM) + EPS);
    out[(long)r * CDIM + tid] = d * inv * g[tid] + b[tid];
}

// ---------------- tensor-core GEMM: C(MROWS x N) = A(MROWS x K) @ B(K x N) + bias ----------------
// BM=128, BN=128, BK=16; 256 threads = 8 warps; warp tile 64x32 (4 m x 4 n of m16n8k8).
// EPI: 0 plain, 1 proj(scatter+residual), 2 gelu, 3 residual
template<int N, int K, int EPI>
__global__ void __launch_bounds__(256, 2)
gemm_tc(const float* __restrict__ A, const float* __restrict__ B,
        const float* __restrict__ bias, float* __restrict__ C,
        const float* __restrict__ res) {
    __shared__ float As[128][20];   // [m][k], stride 20 => conflict-free frag loads
    __shared__ float BsT[128][20];  // [n][k]

    const int tid = threadIdx.x;
    const int lane = tid & 31, wid = tid >> 5;
    const int wm = (wid & 1) * 64;
    const int wn = (wid >> 1) * 32;
    const int m0 = blockIdx.x * 128;
    const int n0 = blockIdx.y * 128;
    const int g = lane >> 2, tg = lane & 3;

    float acc[4][4][4];
    #pragma unroll
    for (int i = 0; i < 4; i++)
        #pragma unroll
        for (int j = 0; j < 4; j++)
            #pragma unroll
            for (int r = 0; r < 4; r++) acc[i][j][r] = 0.f;

    for (int k0 = 0; k0 < K; k0 += 16) {
        #pragma unroll
        for (int i = 0; i < 2; i++) {
            int idx = tid + i * 256;
            int r = idx >> 2, cv = (idx & 3) * 4;
            float4 v = *(const float4*)&A[(long)(m0 + r) * K + k0 + cv];
            v.x = to_tf32(v.x); v.y = to_tf32(v.y); v.z = to_tf32(v.z); v.w = to_tf32(v.w);
            *(float4*)&As[r][cv] = v;
        }
        #pragma unroll
        for (int i = 0; i < 2; i++) {
            int idx = tid + i * 256;
            int kk = idx >> 5, nv = (idx & 31) * 4;
            float4 v = *(const float4*)&B[(long)(k0 + kk) * N + n0 + nv];
            BsT[nv + 0][kk] = to_tf32(v.x);
            BsT[nv + 1][kk] = to_tf32(v.y);
            BsT[nv + 2][kk] = to_tf32(v.z);
            BsT[nv + 3][kk] = to_tf32(v.w);
        }
        __syncthreads();
        #pragma unroll
        for (int ks = 0; ks < 2; ks++) {
            const int kb = ks * 8;
            float af[4][4], bf[4][2];
            #pragma unroll
            for (int mi = 0; mi < 4; mi++) {
                int r = wm + mi * 16 + g;
                af[mi][0] = As[r][kb + tg];
                af[mi][1] = As[r + 8][kb + tg];
                af[mi][2] = As[r][kb + tg + 4];
                af[mi][3] = As[r + 8][kb + tg + 4];
            }
            #pragma unroll
            for (int ni = 0; ni < 4; ni++) {
                int c = wn + ni * 8 + g;
                bf[ni][0] = BsT[c][kb + tg];
                bf[ni][1] = BsT[c][kb + tg + 4];
            }
            #pragma unroll
            for (int mi = 0; mi < 4; mi++)
                #pragma unroll
                for (int ni = 0; ni < 4; ni++)
                    mma_tf32(acc[mi][ni], af[mi], bf[ni]);
        }
        __syncthreads();
    }

    #pragma unroll
    for (int mi = 0; mi < 4; mi++) {
        #pragma unroll
        for (int half = 0; half < 2; half++) {
            int row = m0 + wm + mi * 16 + g + half * 8;
            long drow = row;
            if (EPI == 1) {
                int bi  = row / (NWIN * NTOK);
                int t   = row % (NWIN * NTOK);
                int win = t / NTOK;
                int n   = t % NTOK;
                int hh2 = (win / 8) * WS + n / WS;
                int ww2 = (win % 8) * WS + n % WS;
                drow = (long)bi * LSEQ + ((hh2 + SH) % HH) * WW + (ww2 + SH) % WW;
            }
            #pragma unroll
            for (int ni = 0; ni < 4; ni++) {
                int col = n0 + wn + ni * 8 + 2 * tg;
                float v0 = acc[mi][ni][half * 2 + 0] + bias[col];
                float v1 = acc[mi][ni][half * 2 + 1] + bias[col + 1];
                if (EPI == 0) {
                    *(float2*)&C[(long)row * N + col] = make_float2(v0, v1);
                } else if (EPI == 1) {
                    float2 r2 = *(const float2*)&res[drow * N + col];
                    *(float2*)&C[drow * N + col] = make_float2(r2.x + v0, r2.y + v1);
                } else if (EPI == 2) {
                    v0 = 0.5f * v0 * (1.0f + erff(v0 * 0.70710678118654752f));
                    v1 = 0.5f * v1 * (1.0f + erff(v1 * 0.70710678118654752f));
                    *(float2*)&C[(long)row * N + col] = make_float2(v0, v1);
                } else {
                    float2 r2 = *(const float2*)&res[(long)row * N + col];
                    *(float2*)&C[(long)row * N + col] = make_float2(r2.x + v0, r2.y + v1);
                }
            }
        }
    }
}

// ---------------- attention: one block per (window, head) ----------------
__global__ void __launch_bounds__(256, 2)
attn_kernel(const float* __restrict__ qkv,
            const float* __restrict__ rpb,
            float* __restrict__ out) {
    const int wg = blockIdx.x;
    const int head = blockIdx.y;
    const int tid = threadIdx.x;
    const int lane = tid & 31, wid = tid >> 5;
    const float scale = rsqrtf((float)HD);

    __shared__ float qs[NTOK * HD];
    __shared__ float ks_s[NTOK * 33];
    __shared__ float vs[NTOK * 33];
    __shared__ float S[NTOK * NTOK];
    __shared__ int lab[NTOK];

    if (tid < NTOK) {
        int wi = wg & (NWIN - 1);
        int h = (wi / 8) * WS + tid / WS;
        int w = (wi % 8) * WS + tid % WS;
        int rh = (h < HH - WS) ? 0 : ((h < HH - SH) ? 1 : 2);
        int rw = (w < WW - WS) ? 0 : ((w < WW - SH) ? 1 : 2);
        lab[tid] = rh * 3 + rw;
    }

    for (int i = tid; i < NTOK * HD; i += 256) {
        int n = i >> 5, d = i & 31;
        long base = ((long)wg * NTOK + n) * (3 * CDIM) + head * HD + d;
        qs[n * 32 + d] = qkv[base] * scale;
        ks_s[n * 33 + d] = qkv[base + CDIM];
        vs[n * 33 + d] = qkv[base + 2 * CDIM];
    }
    __syncthreads();

    #pragma unroll
    for (int p = 0; p < 2; p++) {
        int m = p * 32 + lane;
        bool valid = (m < NTOK);
        int mm = valid ? m : 0;
        float kreg[HD];
        #pragma unroll
        for (int d = 0; d < HD; d++) kreg[d] = ks_s[mm * 33 + d];
        int rm = mm / WS, cm = mm % WS, lm = lab[mm];
        for (int n = wid; n < NTOK; n += 8) {
            float a = 0.f;
            #pragma unroll
            for (int d4 = 0; d4 < 8; d4++) {
                float4 qv = *(const float4*)&qs[n * 32 + d4 * 4];
                a += qv.x * kreg[d4 * 4] + qv.y * kreg[d4 * 4 + 1]
                   + qv.z * kreg[d4 * 4 + 2] + qv.w * kreg[d4 * 4 + 3];
            }
            if (valid) {
                int rn = n / WS, cn = n % WS;
                int ridx = (rn - rm + WS - 1) * (2 * WS - 1) + (cn - cm + WS - 1);
                a += rpb[ridx * NHEAD + head];
                if (lab[n] != lm) a -= 100.0f;
                S[n * NTOK + m] = a;
            }
        }
    }
    __syncthreads();

    for (int n = wid; n < NTOK; n += 8) {
        float mx = -1e30f;
        for (int m = lane; m < NTOK; m += 32) mx = fmaxf(mx, S[n * NTOK + m]);
        #pragma unroll
        for (int o = 16; o; o >>= 1) mx = fmaxf(mx, __shfl_xor_sync(0xffffffffu, mx, o));
        float sum = 0.f;
        for (int m = lane; m < NTOK; m += 32) {
            float e = expf(S[n * NTOK + m] - mx);
            S[n * NTOK + m] = e;
            sum += e;
        }
        #pragma unroll
        for (int o = 16; o; o >>= 1) sum += __shfl_xor_sync(0xffffffffu, sum, o);
        float inv = 1.0f / sum;
        for (int m = lane; m < NTOK; m += 32) S[n * NTOK + m] *= inv;
    }
    __syncthreads();

    {
        float oacc[7];
        #pragma unroll
        for (int j = 0; j < 7; j++) oacc[j] = 0.f;
        for (int m = 0; m < NTOK; m++) {
            float vv = vs[m * 33 + lane];
            #pragma unroll
            for (int j = 0; j < 7; j++) {
                int n = wid + 8 * j;
                if (n < NTOK) oacc[j] += S[n * NTOK + m] * vv;
            }
        }
        #pragma unroll
        for (int j = 0; j < 7; j++) {
            int n = wid + 8 * j;
            if (n < NTOK)
                out[((long)wg * NTOK + n) * CDIM + head * HD + lane] = oacc[j];
        }
    }
}

// ---------------- launch ----------------
extern "C" void kernel_launch(void* const* d_in, const int* in_sizes, int n_in,
                              void* d_out, int out_size) {
    const float* x      = (const float*)d_in[0];
    const float* qkv_w  = (const float*)d_in[1];
    const float* qkv_b  = (const float*)d_in[2];
    const float* proj_w = (const float*)d_in[3];
    const float* proj_b = (const float*)d_in[4];
    const float* rpb    = (const float*)d_in[5];
    const float* n1g    = (const float*)d_in[6];
    const float* n1b    = (const float*)d_in[7];
    const float* n2g    = (const float*)d_in[8];
    const float* n2b    = (const float*)d_in[9];
    const float* fc1_w  = (const float*)d_in[10];
    const float* fc1_b  = (const float*)d_in[11];
    const float* fc2_w  = (const float*)d_in[12];
    const float* fc2_b  = (const float*)d_in[13];
    float* out = (float*)d_out;

    float *xw, *qkvb, *att, *hid;
    cudaGetSymbolAddress((void**)&xw,  g_xw);
    cudaGetSymbolAddress((void**)&qkvb, g_qkv);
    cudaGetSymbolAddress((void**)&att, g_att);
    cudaGetSymbolAddress((void**)&hid, g_hid);

    ln1_partition<<<MROWS, 128>>>(x, n1g, n1b, xw);
    gemm_tc<384, 128, 0><<<dim3(MROWS / 128, 3), 256>>>(xw, qkv_w, qkv_b, qkvb, nullptr);
    attn_kernel<<<dim3(BIMG * NWIN, NHEAD), 256>>>(qkvb, rpb, att);
    gemm_tc<128, 128, 1><<<dim3(MROWS / 128, 1), 256>>>(att, proj_w, proj_b, out, x);
    ln_plain<<<MROWS, 128>>>(out, n2g, n2b, xw);
    gemm_tc<512, 128, 2><<<dim3(MROWS / 128, 4), 256>>>(xw, fc1_w, fc1_b, hid, nullptr);
    gemm_tc<128, 512, 3><<<dim3(MROWS / 128, 1), 256>>>(hid, fc2_w, fc2_b, out, out);
}

// round 6
// speedup vs baseline: 2.8849x; 1.6327x over previous
#include <cuda_runtime.h>
#include <cuda_fp16.h>
#include <cstdint>
#include <math.h>

#define HH 56
#define WW 56
#define WS 7
#define SH 3
#define NHEAD 4
#define HD 32
#define CDIM 128
#define NTOK 49
#define NWIN 64
#define BIMG 64
#define MROWS (BIMG * NWIN * NTOK)   // 200704
#define LSEQ (HH * WW)
#define EPS 1e-5f

// ---------------- scratch ----------------
__device__ __half g_xwh[(size_t)MROWS * CDIM];
__device__ __half g_qkvh[(size_t)MROWS * 3 * CDIM];
__device__ __half g_atth[(size_t)MROWS * CDIM];
__device__ __half g_hidh[(size_t)MROWS * 512];
__device__ __half g_wqkv[384 * 128];
__device__ __half g_wproj[128 * 128];
__device__ __half g_wfc1[512 * 128];
__device__ __half g_wfc2[128 * 512];

// ---------------- ptx helpers ----------------
__device__ __forceinline__ unsigned smem_u32(const void* p) {
    return (unsigned)__cvta_generic_to_shared(p);
}
__device__ __forceinline__ void cp16(unsigned dst, const void* src) {
    asm volatile("cp.async.cg.shared.global [%0], [%1], 16;" :: "r"(dst), "l"(src));
}
__device__ __forceinline__ void cp_commit() { asm volatile("cp.async.commit_group;"); }
__device__ __forceinline__ void cp_wait1() { asm volatile("cp.async.wait_group 1;"); }

__device__ __forceinline__ void ldsm4(unsigned* r, unsigned addr) {
    asm volatile("ldmatrix.sync.aligned.m8n8.x4.shared.b16 {%0,%1,%2,%3}, [%4];"
                 : "=r"(r[0]), "=r"(r[1]), "=r"(r[2]), "=r"(r[3]) : "r"(addr));
}
__device__ __forceinline__ void mma_fp16(float* d, const unsigned* a, const unsigned* b) {
    asm volatile(
        "mma.sync.aligned.m16n8k16.row.col.f32.f16.f16.f32 "
        "{%0,%1,%2,%3}, {%4,%5,%6,%7}, {%8,%9}, {%0,%1,%2,%3};\n"
        : "+f"(d[0]), "+f"(d[1]), "+f"(d[2]), "+f"(d[3])
        : "r"(a[0]), "r"(a[1]), "r"(a[2]), "r"(a[3]), "r"(b[0]), "r"(b[1]));
}

__device__ __forceinline__ float block128_sum(float v, float* red, int tid) {
    float s = v;
    #pragma unroll
    for (int o = 16; o; o >>= 1) s += __shfl_xor_sync(0xffffffffu, s, o);
    int wid = tid >> 5, lane = tid & 31;
    if (lane == 0) red[wid] = s;
    __syncthreads();
    return red[0] + red[1] + red[2] + red[3];
}

// ---------------- weight convert + transpose: Wt[n][k] = (half)W[k][n] ----------------
__global__ void convert_w(const float* __restrict__ W, __half* __restrict__ Wt, int K, int N) {
    int i = blockIdx.x * 256 + threadIdx.x;
    if (i < K * N) {
        int k = i / N, n = i % N;
        Wt[n * K + k] = __float2half(W[i]);
    }
}

// ---------------- LN kernels (half output) ----------------
__global__ void ln1_partition(const float* __restrict__ x,
                              const float* __restrict__ g,
                              const float* __restrict__ b,
                              __half* __restrict__ out) {
    __shared__ float red1[4];
    __shared__ float red2[4];
    int r = blockIdx.x;
    int tid = threadIdx.x;

    int bi  = r / (NWIN * NTOK);
    int t   = r % (NWIN * NTOK);
    int win = t / NTOK;
    int n   = t % NTOK;
    int hh = (win / 8) * WS + n / WS;
    int ww = (win % 8) * WS + n % WS;
    int hs = (hh + SH) % HH;
    int ws = (ww + SH) % WW;
    long src = ((long)bi * LSEQ + hs * WW + ws) * CDIM;

    float v = x[src + tid];
    float tot = block128_sum(v, red1, tid);
    float mu = tot * (1.f / CDIM);
    float d = v - mu;
    float tot2 = block128_sum(d * d, red2, tid);
    float inv = rsqrtf(tot2 * (1.f / CDIM) + EPS);
    out[(long)r * CDIM + tid] = __float2half(d * inv * g[tid] + b[tid]);
}

__global__ void ln_plain(const float* __restrict__ x,
                         const float* __restrict__ g,
                         const float* __restrict__ b,
                         __half* __restrict__ out) {
    __shared__ float red1[4];
    __shared__ float red2[4];
    int r = blockIdx.x;
    int tid = threadIdx.x;
    float v = x[(long)r * CDIM + tid];
    float tot = block128_sum(v, red1, tid);
    float mu = tot * (1.f / CDIM);
    float d = v - mu;
    float tot2 = block128_sum(d * d, red2, tid);
    float inv = rsqrtf(tot2 * (1.f / CDIM) + EPS);
    out[(long)r * CDIM + tid] = __float2half(d * inv * g[tid] + b[tid]);
}

// ---------------- fp16 tensor-core GEMM with cp.async 3-stage pipeline ----------------
// C(MROWS x N) = A(MROWS x K)[half] @ Bt(N x K)[half]^T + bias
// BM=128 BN=128 BK=16, 8 warps, warp tile 64x32.
// EPI: 0 half plain, 1 f32 scatter+residual (proj), 2 half gelu, 3 f32 residual
template<int N, int K, int EPI>
__global__ void __launch_bounds__(256, 2)
gemm_h(const __half* __restrict__ A, const __half* __restrict__ Bt,
       const float* __restrict__ bias, void* __restrict__ Cv,
       const float* __restrict__ res) {
    __shared__ __half As[3][128][24];
    __shared__ __half Bs[3][128][24];

    const int tid = threadIdx.x;
    const int lane = tid & 31, wid = tid >> 5;
    const int wm = (wid & 1) * 64;
    const int wn = (wid >> 1) * 32;
    const int m0 = blockIdx.x * 128;
    const int n0 = blockIdx.y * 128;
    const int g = lane >> 2, tg = lane & 3;

    const int fr = tid >> 1;            // row 0..127
    const int fc = (tid & 1) * 8;       // k chunk 0 or 8

    float acc[4][4][4];
    #pragma unroll
    for (int i = 0; i < 4; i++)
        #pragma unroll
        for (int j = 0; j < 4; j++)
            #pragma unroll
            for (int r = 0; r < 4; r++) acc[i][j][r] = 0.f;

    const int NIT = K / 16;

    const int a_row = (lane & 7) + ((lane >> 3) & 1) * 8;
    const int a_kc  = ((lane >> 4) & 1) * 8;
    const int b_row = (lane & 7) + ((lane >> 4) & 1) * 8;
    const int b_kc  = ((lane >> 3) & 1) * 8;

    #pragma unroll
    for (int s = 0; s < 2; s++) {
        if (s < NIT) {
            cp16(smem_u32(&As[s][fr][fc]), &A[(long)(m0 + fr) * K + s * 16 + fc]);
            cp16(smem_u32(&Bs[s][fr][fc]), &Bt[(long)(n0 + fr) * K + s * 16 + fc]);
        }
        cp_commit();
    }

    for (int it = 0; it < NIT; it++) {
        cp_wait1();
        __syncthreads();
        {
            int s = it + 2;
            if (s < NIT) {
                int bufn = s % 3;
                cp16(smem_u32(&As[bufn][fr][fc]), &A[(long)(m0 + fr) * K + s * 16 + fc]);
                cp16(smem_u32(&Bs[bufn][fr][fc]), &Bt[(long)(n0 + fr) * K + s * 16 + fc]);
            }
            cp_commit();
        }
        const int buf = it % 3;

        unsigned a_frag[4][4];
        unsigned b_frag[4][2];
        #pragma unroll
        for (int mi = 0; mi < 4; mi++)
            ldsm4(a_frag[mi], smem_u32(&As[buf][wm + mi * 16 + a_row][a_kc]));
        #pragma unroll
        for (int n2 = 0; n2 < 2; n2++) {
            unsigned r4[4];
            ldsm4(r4, smem_u32(&Bs[buf][wn + n2 * 16 + b_row][b_kc]));
            b_frag[2 * n2][0] = r4[0]; b_frag[2 * n2][1] = r4[1];
            b_frag[2 * n2 + 1][0] = r4[2]; b_frag[2 * n2 + 1][1] = r4[3];
        }
        #pragma unroll
        for (int mi = 0; mi < 4; mi++)
            #pragma unroll
            for (int ni = 0; ni < 4; ni++)
                mma_fp16(acc[mi][ni], a_frag[mi], b_frag[ni]);
    }

    // epilogue
    #pragma unroll
    for (int mi = 0; mi < 4; mi++) {
        #pragma unroll
        for (int hf = 0; hf < 2; hf++) {
            int row = m0 + wm + mi * 16 + g + hf * 8;
            long drow = row;
            if (EPI == 1) {
                int bi  = row / (NWIN * NTOK);
                int t   = row % (NWIN * NTOK);
                int win = t / NTOK;
                int n   = t % NTOK;
                int hh2 = (win / 8) * WS + n / WS;
                int ww2 = (win % 8) * WS + n % WS;
                drow = (long)bi * LSEQ + ((hh2 + SH) % HH) * WW + (ww2 + SH) % WW;
            }
            #pragma unroll
            for (int ni = 0; ni < 4; ni++) {
                int col = n0 + wn + ni * 8 + 2 * tg;
                float v0 = acc[mi][ni][hf * 2 + 0] + bias[col];
                float v1 = acc[mi][ni][hf * 2 + 1] + bias[col + 1];
                if (EPI == 0) {
                    __half* C = (__half*)Cv;
                    *(__half2*)&C[(long)row * N + col] = __floats2half2_rn(v0, v1);
                } else if (EPI == 1) {
                    float* C = (float*)Cv;
                    float2 r2 = *(const float2*)&res[drow * N + col];
                    *(float2*)&C[drow * N + col] = make_float2(r2.x + v0, r2.y + v1);
                } else if (EPI == 2) {
                    v0 = 0.5f * v0 * (1.0f + erff(v0 * 0.70710678118654752f));
                    v1 = 0.5f * v1 * (1.0f + erff(v1 * 0.70710678118654752f));
                    __half* C = (__half*)Cv;
                    *(__half2*)&C[(long)row * N + col] = __floats2half2_rn(v0, v1);
                } else {
                    float* C = (float*)Cv;
                    float2 r2 = *(const float2*)&res[(long)row * N + col];
                    *(float2*)&C[(long)row * N + col] = make_float2(r2.x + v0, r2.y + v1);
                }
            }
        }
    }
}

// ---------------- attention: one block per (window, head); half in/out ----------------
__global__ void __launch_bounds__(256, 2)
attn_kernel(const __half* __restrict__ qkv,
            const float* __restrict__ rpb,
            __half* __restrict__ out) {
    const int wg = blockIdx.x;
    const int head = blockIdx.y;
    const int tid = threadIdx.x;
    const int lane = tid & 31, wid = tid >> 5;
    const float scale = rsqrtf((float)HD);

    __shared__ float qs[NTOK * HD];
    __shared__ float ks_s[NTOK * 33];
    __shared__ float vs[NTOK * 33];
    __shared__ float S[NTOK * NTOK];
    __shared__ int lab[NTOK];

    if (tid < NTOK) {
        int wi = wg & (NWIN - 1);
        int h = (wi / 8) * WS + tid / WS;
        int w = (wi % 8) * WS + tid % WS;
        int rh = (h < HH - WS) ? 0 : ((h < HH - SH) ? 1 : 2);
        int rw = (w < WW - WS) ? 0 : ((w < WW - SH) ? 1 : 2);
        lab[tid] = rh * 3 + rw;
    }

    for (int i = tid; i < NTOK * HD; i += 256) {
        int n = i >> 5, d = i & 31;
        long base = ((long)wg * NTOK + n) * (3 * CDIM) + head * HD + d;
        qs[n * 32 + d] = __half2float(qkv[base]) * scale;
        ks_s[n * 33 + d] = __half2float(qkv[base + CDIM]);
        vs[n * 33 + d] = __half2float(qkv[base + 2 * CDIM]);
    }
    __syncthreads();

    #pragma unroll
    for (int p = 0; p < 2; p++) {
        int m = p * 32 + lane;
        bool valid = (m < NTOK);
        int mm = valid ? m : 0;
        float kreg[HD];
        #pragma unroll
        for (int d = 0; d < HD; d++) kreg[d] = ks_s[mm * 33 + d];
        int rm = mm / WS, cm = mm % WS, lm = lab[mm];
        for (int n = wid; n < NTOK; n += 8) {
            float a = 0.f;
            #pragma unroll
            for (int d4 = 0; d4 < 8; d4++) {
                float4 qv = *(const float4*)&qs[n * 32 + d4 * 4];
                a += qv.x * kreg[d4 * 4] + qv.y * kreg[d4 * 4 + 1]
                   + qv.z * kreg[d4 * 4 + 2] + qv.w * kreg[d4 * 4 + 3];
            }
            if (valid) {
                int rn = n / WS, cn = n % WS;
                int ridx = (rn - rm + WS - 1) * (2 * WS - 1) + (cn - cm + WS - 1);
                a += rpb[ridx * NHEAD + head];
                if (lab[n] != lm) a -= 100.0f;
                S[n * NTOK + m] = a;
            }
        }
    }
    __syncthreads();

    for (int n = wid; n < NTOK; n += 8) {
        float mx = -1e30f;
        for (int m = lane; m < NTOK; m += 32) mx = fmaxf(mx, S[n * NTOK + m]);
        #pragma unroll
        for (int o = 16; o; o >>= 1) mx = fmaxf(mx, __shfl_xor_sync(0xffffffffu, mx, o));
        float sum = 0.f;
        for (int m = lane; m < NTOK; m += 32) {
            float e = expf(S[n * NTOK + m] - mx);
            S[n * NTOK + m] = e;
            sum += e;
        }
        #pragma unroll
        for (int o = 16; o; o >>= 1) sum += __shfl_xor_sync(0xffffffffu, sum, o);
        float inv = 1.0f / sum;
        for (int m = lane; m < NTOK; m += 32) S[n * NTOK + m] *= inv;
    }
    __syncthreads();

    {
        float oacc[7];
        #pragma unroll
        for (int j = 0; j < 7; j++) oacc[j] = 0.f;
        for (int m = 0; m < NTOK; m++) {
            float vv = vs[m * 33 + lane];
            #pragma unroll
            for (int j = 0; j < 7; j++) {
                int n = wid + 8 * j;
                if (n < NTOK) oacc[j] += S[n * NTOK + m] * vv;
            }
        }
        #pragma unroll
        for (int j = 0; j < 7; j++) {
            int n = wid + 8 * j;
            if (n < NTOK)
                out[((long)wg * NTOK + n) * CDIM + head * HD + lane] = __float2half(oacc[j]);
        }
    }
}

// ---------------- launch ----------------
extern "C" void kernel_launch(void* const* d_in, const int* in_sizes, int n_in,
                              void* d_out, int out_size) {
    const float* x      = (const float*)d_in[0];
    const float* qkv_w  = (const float*)d_in[1];
    const float* qkv_b  = (const float*)d_in[2];
    const float* proj_w = (const float*)d_in[3];
    const float* proj_b = (const float*)d_in[4];
    const float* rpb    = (const float*)d_in[5];
    const float* n1g    = (const float*)d_in[6];
    const float* n1b    = (const float*)d_in[7];
    const float* n2g    = (const float*)d_in[8];
    const float* n2b    = (const float*)d_in[9];
    const float* fc1_w  = (const float*)d_in[10];
    const float* fc1_b  = (const float*)d_in[11];
    const float* fc2_w  = (const float*)d_in[12];
    const float* fc2_b  = (const float*)d_in[13];
    float* out = (float*)d_out;

    __half *xwh, *qkvh, *atth, *hidh, *wqkv, *wproj, *wfc1, *wfc2;
    cudaGetSymbolAddress((void**)&xwh,  g_xwh);
    cudaGetSymbolAddress((void**)&qkvh, g_qkvh);
    cudaGetSymbolAddress((void**)&atth, g_atth);
    cudaGetSymbolAddress((void**)&hidh, g_hidh);
    cudaGetSymbolAddress((void**)&wqkv, g_wqkv);
    cudaGetSymbolAddress((void**)&wproj, g_wproj);
    cudaGetSymbolAddress((void**)&wfc1, g_wfc1);
    cudaGetSymbolAddress((void**)&wfc2, g_wfc2);

    convert_w<<<(128 * 384 + 255) / 256, 256>>>(qkv_w, wqkv, 128, 384);
    convert_w<<<(128 * 128 + 255) / 256, 256>>>(proj_w, wproj, 128, 128);
    convert_w<<<(128 * 512 + 255) / 256, 256>>>(fc1_w, wfc1, 128, 512);
    convert_w<<<(512 * 128 + 255) / 256, 256>>>(fc2_w, wfc2, 512, 128);

    ln1_partition<<<MROWS, 128>>>(x, n1g, n1b, xwh);
    gemm_h<384, 128, 0><<<dim3(MROWS / 128, 3), 256>>>(xwh, wqkv, qkv_b, qkvh, nullptr);
    attn_kernel<<<dim3(BIMG * NWIN, NHEAD), 256>>>(qkvh, rpb, atth);
    gemm_h<128, 128, 1><<<dim3(MROWS / 128, 1), 256>>>(atth, wproj, proj_b, out, x);
    ln_plain<<<MROWS, 128>>>(out, n2g, n2b, xwh);
    gemm_h<512, 128, 2><<<dim3(MROWS / 128, 4), 256>>>(xwh, wfc1, fc1_b, hidh, nullptr);
    gemm_h<128, 512, 3><<<dim3(MROWS / 128, 1), 256>>>(hidh, wfc2, fc2_b, out, out);
}

// round 7
// speedup vs baseline: 3.1572x; 1.0944x over previous
#include <cuda_runtime.h>
#include <cuda_fp16.h>
#include <cstdint>
#include <math.h>

#define HH 56
#define WW 56
#define WS 7
#define SH 3
#define NHEAD 4
#define HD 32
#define CDIM 128
#define NTOK 49
#define NWIN 64
#define BIMG 64
#define MROWS (BIMG * NWIN * NTOK)   // 200704
#define LSEQ (HH * WW)
#define EPS 1e-5f

// ---------------- scratch ----------------
__device__ __half g_qkvh[(size_t)MROWS * 3 * CDIM];
__device__ __half g_atth[(size_t)MROWS * CDIM];
__device__ __half g_hidh[(size_t)MROWS * 512];
__device__ __half g_wqkv[384 * 128];
__device__ __half g_wproj[128 * 128];
__device__ __half g_wfc1[512 * 128];
__device__ __half g_wfc2[128 * 512];

// ---------------- ptx helpers ----------------
__device__ __forceinline__ unsigned smem_u32(const void* p) {
    return (unsigned)__cvta_generic_to_shared(p);
}
__device__ __forceinline__ void cp16(unsigned dst, const void* src) {
    asm volatile("cp.async.cg.shared.global [%0], [%1], 16;" :: "r"(dst), "l"(src));
}
__device__ __forceinline__ void cp_commit() { asm volatile("cp.async.commit_group;"); }
__device__ __forceinline__ void cp_wait1() { asm volatile("cp.async.wait_group 1;"); }
__device__ __forceinline__ void cp_wait0() { asm volatile("cp.async.wait_group 0;"); }

__device__ __forceinline__ void ldsm4(unsigned* r, unsigned addr) {
    asm volatile("ldmatrix.sync.aligned.m8n8.x4.shared.b16 {%0,%1,%2,%3}, [%4];"
                 : "=r"(r[0]), "=r"(r[1]), "=r"(r[2]), "=r"(r[3]) : "r"(addr));
}
__device__ __forceinline__ void mma_fp16(float* d, const unsigned* a, const unsigned* b) {
    asm volatile(
        "mma.sync.aligned.m16n8k16.row.col.f32.f16.f16.f32 "
        "{%0,%1,%2,%3}, {%4,%5,%6,%7}, {%8,%9}, {%0,%1,%2,%3};\n"
        : "+f"(d[0]), "+f"(d[1]), "+f"(d[2]), "+f"(d[3])
        : "r"(a[0]), "r"(a[1]), "r"(a[2]), "r"(a[3]), "r"(b[0]), "r"(b[1]));
}

// ---------------- weight convert + transpose: Wt[n][k] = (half)W[k][n] ----------------
__global__ void convert_w(const float* __restrict__ W, __half* __restrict__ Wt, int K, int N) {
    int i = blockIdx.x * 256 + threadIdx.x;
    if (i < K * N) {
        int k = i / N, n = i % N;
        Wt[n * K + k] = __float2half(W[i]);
    }
}

// ============ fused LN + GEMM (K=128), A kept resident across N-chunks ============
// C(128 rows x NCHUNKS*128) = LN(X rows) @ Bt^T + bias  [+ GELU]
// GATHER: apply roll+window-partition row mapping when reading X.
#define DSMEM_LNGEMM (34816 * 2 + 16384)
template<int NCHUNKS, bool GATHER, bool DOGELU>
__global__ void __launch_bounds__(256)
ln_gemm(const float* __restrict__ X, const __half* __restrict__ Bt,
        const float* __restrict__ bias, const float* __restrict__ lng,
        const float* __restrict__ lnb, __half* __restrict__ C) {
    extern __shared__ char dyn[];
    __half (*As)[136] = (__half(*)[136])dyn;                 // 128 x 136 half = 34816 B
    __half (*Bs)[136] = (__half(*)[136])(dyn + 34816);       // 128 x 136 half = 34816 B
    float (*stage)[128] = (float(*)[128])(dyn + 69632);      // 32 x 128 f32  = 16384 B

    const int tid = threadIdx.x;
    const int lane = tid & 31, wid = tid >> 5;
    const int m0 = blockIdx.x * 128;
    const int NT = NCHUNKS * 128;

    // ---- LN phase: 4 stages of 32 rows ----
    for (int rs = 0; rs < 128; rs += 32) {
        #pragma unroll
        for (int t = 0; t < 4; t++) {
            int i = tid + t * 256;
            int row = i >> 5;
            int c4 = (i & 31) * 4;
            int R = m0 + rs + row;
            long srow;
            if (GATHER) {
                int bi = R / (NWIN * NTOK);
                int tt = R % (NWIN * NTOK);
                int win = tt / NTOK, n = tt % NTOK;
                int hh = (win / 8) * WS + n / WS;
                int ww = (win % 8) * WS + n % WS;
                srow = (long)bi * LSEQ + ((hh + SH) % HH) * WW + (ww + SH) % WW;
            } else {
                srow = R;
            }
            *(float4*)&stage[row][c4] = *(const float4*)&X[srow * CDIM + c4];
        }
        __syncthreads();
        #pragma unroll
        for (int rr = 0; rr < 4; rr++) {
            int row = wid * 4 + rr;
            float v[4];
            #pragma unroll
            for (int t = 0; t < 4; t++) v[t] = stage[row][lane + t * 32];
            float s = v[0] + v[1] + v[2] + v[3];
            float s2 = v[0] * v[0] + v[1] * v[1] + v[2] * v[2] + v[3] * v[3];
            #pragma unroll
            for (int o = 16; o; o >>= 1) {
                s += __shfl_xor_sync(0xffffffffu, s, o);
                s2 += __shfl_xor_sync(0xffffffffu, s2, o);
            }
            float mu = s * (1.f / 128.f);
            float inv = rsqrtf(s2 * (1.f / 128.f) - mu * mu + EPS);
            #pragma unroll
            for (int t = 0; t < 4; t++) {
                int c = lane + t * 32;
                As[rs + row][c] = __float2half((v[t] - mu) * inv * lng[c] + lnb[c]);
            }
        }
        __syncthreads();
    }

    // ---- GEMM phase ----
    const int a_row = (lane & 7) + ((lane >> 3) & 1) * 8;
    const int a_kc  = ((lane >> 4) & 1) * 8;
    const int b_row = (lane & 7) + ((lane >> 4) & 1) * 8;
    const int b_kc  = ((lane >> 3) & 1) * 8;
    const int wm = (wid & 1) * 64;
    const int wn = (wid >> 1) * 32;
    const int g = lane >> 2, tg = lane & 3;

    for (int c = 0; c < NCHUNKS; c++) {
        #pragma unroll
        for (int t = 0; t < 8; t++) {
            int i = tid + t * 256;
            int row = i >> 4;
            int col = (i & 15) * 8;
            cp16(smem_u32(&Bs[row][col]), &Bt[(long)(c * 128 + row) * CDIM + col]);
        }
        cp_commit();
        cp_wait0();
        __syncthreads();

        float acc[4][4][4];
        #pragma unroll
        for (int i = 0; i < 4; i++)
            #pragma unroll
            for (int j = 0; j < 4; j++)
                #pragma unroll
                for (int r = 0; r < 4; r++) acc[i][j][r] = 0.f;

        #pragma unroll
        for (int it = 0; it < 8; it++) {
            const int k0 = it * 16;
            unsigned a_frag[4][4], b_frag[4][2];
            #pragma unroll
            for (int mi = 0; mi < 4; mi++)
                ldsm4(a_frag[mi], smem_u32(&As[wm + mi * 16 + a_row][k0 + a_kc]));
            #pragma unroll
            for (int n2 = 0; n2 < 2; n2++) {
                unsigned r4[4];
                ldsm4(r4, smem_u32(&Bs[wn + n2 * 16 + b_row][k0 + b_kc]));
                b_frag[2 * n2][0] = r4[0]; b_frag[2 * n2][1] = r4[1];
                b_frag[2 * n2 + 1][0] = r4[2]; b_frag[2 * n2 + 1][1] = r4[3];
            }
            #pragma unroll
            for (int mi = 0; mi < 4; mi++)
                #pragma unroll
                for (int ni = 0; ni < 4; ni++)
                    mma_fp16(acc[mi][ni], a_frag[mi], b_frag[ni]);
        }
        __syncthreads();

        #pragma unroll
        for (int mi = 0; mi < 4; mi++) {
            #pragma unroll
            for (int hf = 0; hf < 2; hf++) {
                int row = m0 + wm + mi * 16 + g + hf * 8;
                #pragma unroll
                for (int ni = 0; ni < 4; ni++) {
                    int col = c * 128 + wn + ni * 8 + 2 * tg;
                    float v0 = acc[mi][ni][hf * 2 + 0] + bias[col];
                    float v1 = acc[mi][ni][hf * 2 + 1] + bias[col + 1];
                    if (DOGELU) {
                        v0 = 0.5f * v0 * (1.0f + erff(v0 * 0.70710678118654752f));
                        v1 = 0.5f * v1 * (1.0f + erff(v1 * 0.70710678118654752f));
                    }
                    *(__half2*)&C[(long)row * NT + col] = __floats2half2_rn(v0, v1);
                }
            }
        }
    }
}

// ---------------- fp16 GEMM with cp.async pipeline (proj / fc2) ----------------
// EPI: 1 f32 scatter+residual (proj), 3 f32 residual (fc2)
template<int N, int K, int EPI>
__global__ void __launch_bounds__(256, 2)
gemm_h(const __half* __restrict__ A, const __half* __restrict__ Bt,
       const float* __restrict__ bias, float* __restrict__ C,
       const float* __restrict__ res) {
    __shared__ __half As[3][128][24];
    __shared__ __half Bs[3][128][24];

    const int tid = threadIdx.x;
    const int lane = tid & 31, wid = tid >> 5;
    const int wm = (wid & 1) * 64;
    const int wn = (wid >> 1) * 32;
    const int m0 = blockIdx.x * 128;
    const int n0 = blockIdx.y * 128;
    const int g = lane >> 2, tg = lane & 3;

    const int fr = tid >> 1;
    const int fc = (tid & 1) * 8;

    float acc[4][4][4];
    #pragma unroll
    for (int i = 0; i < 4; i++)
        #pragma unroll
        for (int j = 0; j < 4; j++)
            #pragma unroll
            for (int r = 0; r < 4; r++) acc[i][j][r] = 0.f;

    const int NIT = K / 16;

    const int a_row = (lane & 7) + ((lane >> 3) & 1) * 8;
    const int a_kc  = ((lane >> 4) & 1) * 8;
    const int b_row = (lane & 7) + ((lane >> 4) & 1) * 8;
    const int b_kc  = ((lane >> 3) & 1) * 8;

    #pragma unroll
    for (int s = 0; s < 2; s++) {
        if (s < NIT) {
            cp16(smem_u32(&As[s][fr][fc]), &A[(long)(m0 + fr) * K + s * 16 + fc]);
            cp16(smem_u32(&Bs[s][fr][fc]), &Bt[(long)(n0 + fr) * K + s * 16 + fc]);
        }
        cp_commit();
    }

    for (int it = 0; it < NIT; it++) {
        cp_wait1();
        __syncthreads();
        {
            int s = it + 2;
            if (s < NIT) {
                int bufn = s % 3;
                cp16(smem_u32(&As[bufn][fr][fc]), &A[(long)(m0 + fr) * K + s * 16 + fc]);
                cp16(smem_u32(&Bs[bufn][fr][fc]), &Bt[(long)(n0 + fr) * K + s * 16 + fc]);
            }
            cp_commit();
        }
        const int buf = it % 3;

        unsigned a_frag[4][4];
        unsigned b_frag[4][2];
        #pragma unroll
        for (int mi = 0; mi < 4; mi++)
            ldsm4(a_frag[mi], smem_u32(&As[buf][wm + mi * 16 + a_row][a_kc]));
        #pragma unroll
        for (int n2 = 0; n2 < 2; n2++) {
            unsigned r4[4];
            ldsm4(r4, smem_u32(&Bs[buf][wn + n2 * 16 + b_row][b_kc]));
            b_frag[2 * n2][0] = r4[0]; b_frag[2 * n2][1] = r4[1];
            b_frag[2 * n2 + 1][0] = r4[2]; b_frag[2 * n2 + 1][1] = r4[3];
        }
        #pragma unroll
        for (int mi = 0; mi < 4; mi++)
            #pragma unroll
            for (int ni = 0; ni < 4; ni++)
                mma_fp16(acc[mi][ni], a_frag[mi], b_frag[ni]);
    }

    #pragma unroll
    for (int mi = 0; mi < 4; mi++) {
        #pragma unroll
        for (int hf = 0; hf < 2; hf++) {
            int row = m0 + wm + mi * 16 + g + hf * 8;
            long drow = row;
            if (EPI == 1) {
                int bi  = row / (NWIN * NTOK);
                int t   = row % (NWIN * NTOK);
                int win = t / NTOK;
                int n   = t % NTOK;
                int hh2 = (win / 8) * WS + n / WS;
                int ww2 = (win % 8) * WS + n % WS;
                drow = (long)bi * LSEQ + ((hh2 + SH) % HH) * WW + (ww2 + SH) % WW;
            }
            #pragma unroll
            for (int ni = 0; ni < 4; ni++) {
                int col = n0 + wn + ni * 8 + 2 * tg;
                float v0 = acc[mi][ni][hf * 2 + 0] + bias[col];
                float v1 = acc[mi][ni][hf * 2 + 1] + bias[col + 1];
                if (EPI == 1) {
                    float2 r2 = *(const float2*)&res[drow * N + col];
                    *(float2*)&C[drow * N + col] = make_float2(r2.x + v0, r2.y + v1);
                } else {
                    float2 r2 = *(const float2*)&res[(long)row * N + col];
                    *(float2*)&C[(long)row * N + col] = make_float2(r2.x + v0, r2.y + v1);
                }
            }
        }
    }
}

// ---------------- attention: one block per (window, head); half in/out ----------------
__global__ void __launch_bounds__(256, 2)
attn_kernel(const __half* __restrict__ qkv,
            const float* __restrict__ rpb,
            __half* __restrict__ out) {
    const int wg = blockIdx.x;
    const int head = blockIdx.y;
    const int tid = threadIdx.x;
    const int lane = tid & 31, wid = tid >> 5;
    const float scale = rsqrtf((float)HD);

    __shared__ float qs[NTOK * HD];
    __shared__ float ks_s[NTOK * 33];
    __shared__ float vs[NTOK * 33];
    __shared__ float S[NTOK * NTOK];
    __shared__ int lab[NTOK];

    if (tid < NTOK) {
        int wi = wg & (NWIN - 1);
        int h = (wi / 8) * WS + tid / WS;
        int w = (wi % 8) * WS + tid % WS;
        int rh = (h < HH - WS) ? 0 : ((h < HH - SH) ? 1 : 2);
        int rw = (w < WW - WS) ? 0 : ((w < WW - SH) ? 1 : 2);
        lab[tid] = rh * 3 + rw;
    }

    for (int i = tid; i < NTOK * HD; i += 256) {
        int n = i >> 5, d = i & 31;
        long base = ((long)wg * NTOK + n) * (3 * CDIM) + head * HD + d;
        qs[n * 32 + d] = __half2float(qkv[base]) * scale;
        ks_s[n * 33 + d] = __half2float(qkv[base + CDIM]);
        vs[n * 33 + d] = __half2float(qkv[base + 2 * CDIM]);
    }
    __syncthreads();

    #pragma unroll
    for (int p = 0; p < 2; p++) {
        int m = p * 32 + lane;
        bool valid = (m < NTOK);
        int mm = valid ? m : 0;
        float kreg[HD];
        #pragma unroll
        for (int d = 0; d < HD; d++) kreg[d] = ks_s[mm * 33 + d];
        int rm = mm / WS, cm = mm % WS, lm = lab[mm];
        for (int n = wid; n < NTOK; n += 8) {
            float a = 0.f;
            #pragma unroll
            for (int d4 = 0; d4 < 8; d4++) {
                float4 qv = *(const float4*)&qs[n * 32 + d4 * 4];
                a += qv.x * kreg[d4 * 4] + qv.y * kreg[d4 * 4 + 1]
                   + qv.z * kreg[d4 * 4 + 2] + qv.w * kreg[d4 * 4 + 3];
            }
            if (valid) {
                int rn = n / WS, cn = n % WS;
                int ridx = (rn - rm + WS - 1) * (2 * WS - 1) + (cn - cm + WS - 1);
                a += rpb[ridx * NHEAD + head];
                if (lab[n] != lm) a -= 100.0f;
                S[n * NTOK + m] = a;
            }
        }
    }
    __syncthreads();

    for (int n = wid; n < NTOK; n += 8) {
        float mx = -1e30f;
        for (int m = lane; m < NTOK; m += 32) mx = fmaxf(mx, S[n * NTOK + m]);
        #pragma unroll
        for (int o = 16; o; o >>= 1) mx = fmaxf(mx, __shfl_xor_sync(0xffffffffu, mx, o));
        float sum = 0.f;
        for (int m = lane; m < NTOK; m += 32) {
            float e = expf(S[n * NTOK + m] - mx);
            S[n * NTOK + m] = e;
            sum += e;
        }
        #pragma unroll
        for (int o = 16; o; o >>= 1) sum += __shfl_xor_sync(0xffffffffu, sum, o);
        float inv = 1.0f / sum;
        for (int m = lane; m < NTOK; m += 32) S[n * NTOK + m] *= inv;
    }
    __syncthreads();

    {
        float oacc[7];
        #pragma unroll
        for (int j = 0; j < 7; j++) oacc[j] = 0.f;
        for (int m = 0; m < NTOK; m++) {
            float vv = vs[m * 33 + lane];
            #pragma unroll
            for (int j = 0; j < 7; j++) {
                int n = wid + 8 * j;
                if (n < NTOK) oacc[j] += S[n * NTOK + m] * vv;
            }
        }
        #pragma unroll
        for (int j = 0; j < 7; j++) {
            int n = wid + 8 * j;
            if (n < NTOK)
                out[((long)wg * NTOK + n) * CDIM + head * HD + lane] = __float2half(oacc[j]);
        }
    }
}

// ---------------- launch ----------------
extern "C" void kernel_launch(void* const* d_in, const int* in_sizes, int n_in,
                              void* d_out, int out_size) {
    const float* x      = (const float*)d_in[0];
    const float* qkv_w  = (const float*)d_in[1];
    const float* qkv_b  = (const float*)d_in[2];
    const float* proj_w = (const float*)d_in[3];
    const float* proj_b = (const float*)d_in[4];
    const float* rpb    = (const float*)d_in[5];
    const float* n1g    = (const float*)d_in[6];
    const float* n1b    = (const float*)d_in[7];
    const float* n2g    = (const float*)d_in[8];
    const float* n2b    = (const float*)d_in[9];
    const float* fc1_w  = (const float*)d_in[10];
    const float* fc1_b  = (const float*)d_in[11];
    const float* fc2_w  = (const float*)d_in[12];
    const float* fc2_b  = (const float*)d_in[13];
    float* out = (float*)d_out;

    __half *qkvh, *atth, *hidh, *wqkv, *wproj, *wfc1, *wfc2;
    cudaGetSymbolAddress((void**)&qkvh, g_qkvh);
    cudaGetSymbolAddress((void**)&atth, g_atth);
    cudaGetSymbolAddress((void**)&hidh, g_hidh);
    cudaGetSymbolAddress((void**)&wqkv, g_wqkv);
    cudaGetSymbolAddress((void**)&wproj, g_wproj);
    cudaGetSymbolAddress((void**)&wfc1, g_wfc1);
    cudaGetSymbolAddress((void**)&wfc2, g_wfc2);

    static bool attr_set = false;
    if (!attr_set) {
        cudaFuncSetAttribute(ln_gemm<3, true, false>,
                             cudaFuncAttributeMaxDynamicSharedMemorySize, DSMEM_LNGEMM);
        cudaFuncSetAttribute(ln_gemm<4, false, true>,
                             cudaFuncAttributeMaxDynamicSharedMemorySize, DSMEM_LNGEMM);
        attr_set = true;
    }

    convert_w<<<(128 * 384 + 255) / 256, 256>>>(qkv_w, wqkv, 128, 384);
    convert_w<<<(128 * 128 + 255) / 256, 256>>>(proj_w, wproj, 128, 128);
    convert_w<<<(128 * 512 + 255) / 256, 256>>>(fc1_w, wfc1, 128, 512);
    convert_w<<<(512 * 128 + 255) / 256, 256>>>(fc2_w, wfc2, 512, 128);

    // 1. LN1 + roll + partition + QKV GEMM (fused)
    ln_gemm<3, true, false><<<MROWS / 128, 256, DSMEM_LNGEMM>>>(
        x, wqkv, qkv_b, n1g, n1b, qkvh);
    // 2. attention
    attn_kernel<<<dim3(BIMG * NWIN, NHEAD), 256>>>(qkvh, rpb, atth);
    // 3. proj + window-reverse + roll + residual -> d_out (f32)
    gemm_h<128, 128, 1><<<dim3(MROWS / 128, 1), 256>>>(atth, wproj, proj_b, out, x);
    // 4. LN2 + fc1 + GELU (fused)
    ln_gemm<4, false, true><<<MROWS / 128, 256, DSMEM_LNGEMM>>>(
        out, wfc1, fc1_b, n2g, n2b, hidh);
    // 5. fc2 + residual -> d_out
    gemm_h<128, 512, 3><<<dim3(MROWS / 128, 1), 256>>>(hidh, wfc2, fc2_b, out, out);
}

// round 9
// speedup vs baseline: 5.3950x; 1.7088x over previous
#include <cuda_runtime.h>
#include <cuda_fp16.h>
#include <cstdint>
#include <math.h>

#define HH 56
#define WW 56
#define WS 7
#define SH 3
#define NHEAD 4
#define HD 32
#define CDIM 128
#define NTOK 49
#define NWIN 64
#define BIMG 64
#define MROWS (BIMG * NWIN * NTOK)   // 200704
#define LSEQ (HH * WW)
#define EPS 1e-5f

// ---------------- scratch ----------------
__device__ __half g_qkvh[(size_t)MROWS * 3 * CDIM];
__device__ __half g_atth[(size_t)MROWS * CDIM];
__device__ __half g_hidh[(size_t)MROWS * 512];
__device__ __half g_wqkv[384 * 128];
__device__ __half g_wproj[128 * 128];
__device__ __half g_wfc1[512 * 128];
__device__ __half g_wfc2[128 * 512];
__device__ float  g_biasM[NHEAD * NTOK * NTOK];

// ---------------- ptx helpers ----------------
__device__ __forceinline__ unsigned smem_u32(const void* p) {
    return (unsigned)__cvta_generic_to_shared(p);
}
__device__ __forceinline__ unsigned h2_as_u32(__half2 h) {
    return *(unsigned*)&h;
}
__device__ __forceinline__ void cp16(unsigned dst, const void* src) {
    asm volatile("cp.async.cg.shared.global [%0], [%1], 16;" :: "r"(dst), "l"(src));
}
__device__ __forceinline__ void cp_commit() { asm volatile("cp.async.commit_group;"); }
__device__ __forceinline__ void cp_wait1() { asm volatile("cp.async.wait_group 1;"); }
__device__ __forceinline__ void cp_wait0() { asm volatile("cp.async.wait_group 0;"); }

__device__ __forceinline__ void ldsm4(unsigned* r, unsigned addr) {
    asm volatile("ldmatrix.sync.aligned.m8n8.x4.shared.b16 {%0,%1,%2,%3}, [%4];"
                 : "=r"(r[0]), "=r"(r[1]), "=r"(r[2]), "=r"(r[3]) : "r"(addr));
}
__device__ __forceinline__ void mma_fp16(float* d, const unsigned* a, const unsigned* b) {
    asm volatile(
        "mma.sync.aligned.m16n8k16.row.col.f32.f16.f16.f32 "
        "{%0,%1,%2,%3}, {%4,%5,%6,%7}, {%8,%9}, {%0,%1,%2,%3};\n"
        : "+f"(d[0]), "+f"(d[1]), "+f"(d[2]), "+f"(d[3])
        : "r"(a[0]), "r"(a[1]), "r"(a[2]), "r"(a[3]), "r"(b[0]), "r"(b[1]));
}

// ---------------- fused weight convert + transpose (4 matrices, 1 launch) ----------------
__global__ void convert_all(const float* __restrict__ qkv_w, const float* __restrict__ proj_w,
                            const float* __restrict__ fc1_w, const float* __restrict__ fc2_w,
                            __half* __restrict__ wqkv, __half* __restrict__ wproj,
                            __half* __restrict__ wfc1, __half* __restrict__ wfc2) {
    int i = blockIdx.x * 256 + threadIdx.x;
    if (i < 49152) {                       // qkv: K=128, N=384
        int k = i / 384, n = i % 384;
        wqkv[n * 128 + k] = __float2half(qkv_w[i]);
    } else if (i < 65536) {                // proj: 128x128
        int j = i - 49152;
        int k = j / 128, n = j % 128;
        wproj[n * 128 + k] = __float2half(proj_w[j]);
    } else if (i < 131072) {               // fc1: K=128, N=512
        int j = i - 65536;
        int k = j / 512, n = j % 512;
        wfc1[n * 128 + k] = __float2half(fc1_w[j]);
    } else if (i < 196608) {               // fc2: K=512, N=128
        int j = i - 131072;
        int k = j / 128, n = j % 128;
        wfc2[n * 512 + k] = __float2half(fc2_w[j]);
    }
}

// ---------------- relative-position bias precompute: biasM[h][n][m] ----------------
__global__ void bias_pre(const float* __restrict__ rpb, float* __restrict__ biasM) {
    int i = blockIdx.x * 256 + threadIdx.x;
    if (i < NHEAD * NTOK * NTOK) {
        int h = i / (NTOK * NTOK);
        int r = i % (NTOK * NTOK);
        int n = r / NTOK, m = r % NTOK;
        int ridx = (n / WS - m / WS + WS - 1) * (2 * WS - 1) + (n % WS - m % WS + WS - 1);
        biasM[i] = rpb[ridx * NHEAD + h];
    }
}

// ============ fused LN + GEMM (K=128), A kept resident across N-chunks ============
#define DSMEM_LNGEMM (34816 * 2 + 16384)
template<int NCHUNKS, bool GATHER, bool DOGELU>
__global__ void __launch_bounds__(256)
ln_gemm(const float* __restrict__ X, const __half* __restrict__ Bt,
        const float* __restrict__ bias, const float* __restrict__ lng,
        const float* __restrict__ lnb, __half* __restrict__ C) {
    extern __shared__ char dyn[];
    __half (*As)[136] = (__half(*)[136])dyn;
    __half (*Bs)[136] = (__half(*)[136])(dyn + 34816);
    float (*stage)[128] = (float(*)[128])(dyn + 69632);

    const int tid = threadIdx.x;
    const int lane = tid & 31, wid = tid >> 5;
    const int m0 = blockIdx.x * 128;
    const int NT = NCHUNKS * 128;

    for (int rs = 0; rs < 128; rs += 32) {
        #pragma unroll
        for (int t = 0; t < 4; t++) {
            int i = tid + t * 256;
            int row = i >> 5;
            int c4 = (i & 31) * 4;
            int R = m0 + rs + row;
            long srow;
            if (GATHER) {
                int bi = R / (NWIN * NTOK);
                int tt = R % (NWIN * NTOK);
                int win = tt / NTOK, n = tt % NTOK;
                int hh = (win / 8) * WS + n / WS;
                int ww = (win % 8) * WS + n % WS;
                srow = (long)bi * LSEQ + ((hh + SH) % HH) * WW + (ww + SH) % WW;
            } else {
                srow = R;
            }
            *(float4*)&stage[row][c4] = *(const float4*)&X[srow * CDIM + c4];
        }
        __syncthreads();
        #pragma unroll
        for (int rr = 0; rr < 4; rr++) {
            int row = wid * 4 + rr;
            float v[4];
            #pragma unroll
            for (int t = 0; t < 4; t++) v[t] = stage[row][lane + t * 32];
            float s = v[0] + v[1] + v[2] + v[3];
            float s2 = v[0] * v[0] + v[1] * v[1] + v[2] * v[2] + v[3] * v[3];
            #pragma unroll
            for (int o = 16; o; o >>= 1) {
                s += __shfl_xor_sync(0xffffffffu, s, o);
                s2 += __shfl_xor_sync(0xffffffffu, s2, o);
            }
            float mu = s * (1.f / 128.f);
            float inv = rsqrtf(s2 * (1.f / 128.f) - mu * mu + EPS);
            #pragma unroll
            for (int t = 0; t < 4; t++) {
                int c = lane + t * 32;
                As[rs + row][c] = __float2half((v[t] - mu) * inv * lng[c] + lnb[c]);
            }
        }
        __syncthreads();
    }

    const int a_row = (lane & 7) + ((lane >> 3) & 1) * 8;
    const int a_kc  = ((lane >> 4) & 1) * 8;
    const int b_row = (lane & 7) + ((lane >> 4) & 1) * 8;
    const int b_kc  = ((lane >> 3) & 1) * 8;
    const int wm = (wid & 1) * 64;
    const int wn = (wid >> 1) * 32;
    const int g = lane >> 2, tg = lane & 3;

    for (int c = 0; c < NCHUNKS; c++) {
        #pragma unroll
        for (int t = 0; t < 8; t++) {
            int i = tid + t * 256;
            int row = i >> 4;
            int col = (i & 15) * 8;
            cp16(smem_u32(&Bs[row][col]), &Bt[(long)(c * 128 + row) * CDIM + col]);
        }
        cp_commit();
        cp_wait0();
        __syncthreads();

        float acc[4][4][4];
        #pragma unroll
        for (int i = 0; i < 4; i++)
            #pragma unroll
            for (int j = 0; j < 4; j++)
                #pragma unroll
                for (int r = 0; r < 4; r++) acc[i][j][r] = 0.f;

        #pragma unroll
        for (int it = 0; it < 8; it++) {
            const int k0 = it * 16;
            unsigned a_frag[4][4], b_frag[4][2];
            #pragma unroll
            for (int mi = 0; mi < 4; mi++)
                ldsm4(a_frag[mi], smem_u32(&As[wm + mi * 16 + a_row][k0 + a_kc]));
            #pragma unroll
            for (int n2 = 0; n2 < 2; n2++) {
                unsigned r4[4];
                ldsm4(r4, smem_u32(&Bs[wn + n2 * 16 + b_row][k0 + b_kc]));
                b_frag[2 * n2][0] = r4[0]; b_frag[2 * n2][1] = r4[1];
                b_frag[2 * n2 + 1][0] = r4[2]; b_frag[2 * n2 + 1][1] = r4[3];
            }
            #pragma unroll
            for (int mi = 0; mi < 4; mi++)
                #pragma unroll
                for (int ni = 0; ni < 4; ni++)
                    mma_fp16(acc[mi][ni], a_frag[mi], b_frag[ni]);
        }
        __syncthreads();

        #pragma unroll
        for (int mi = 0; mi < 4; mi++) {
            #pragma unroll
            for (int hf = 0; hf < 2; hf++) {
                int row = m0 + wm + mi * 16 + g + hf * 8;
                #pragma unroll
                for (int ni = 0; ni < 4; ni++) {
                    int col = c * 128 + wn + ni * 8 + 2 * tg;
                    float v0 = acc[mi][ni][hf * 2 + 0] + bias[col];
                    float v1 = acc[mi][ni][hf * 2 + 1] + bias[col + 1];
                    if (DOGELU) {
                        v0 = 0.5f * v0 * (1.0f + erff(v0 * 0.70710678118654752f));
                        v1 = 0.5f * v1 * (1.0f + erff(v1 * 0.70710678118654752f));
                    }
                    *(__half2*)&C[(long)row * NT + col] = __floats2half2_rn(v0, v1);
                }
            }
        }
    }
}

// ---------------- fp16 GEMM with cp.async pipeline (proj / fc2) ----------------
template<int N, int K, int EPI>
__global__ void __launch_bounds__(256, 2)
gemm_h(const __half* __restrict__ A, const __half* __restrict__ Bt,
       const float* __restrict__ bias, float* __restrict__ C,
       const float* __restrict__ res) {
    __shared__ __half As[3][128][24];
    __shared__ __half Bs[3][128][24];

    const int tid = threadIdx.x;
    const int lane = tid & 31, wid = tid >> 5;
    const int wm = (wid & 1) * 64;
    const int wn = (wid >> 1) * 32;
    const int m0 = blockIdx.x * 128;
    const int n0 = blockIdx.y * 128;
    const int g = lane >> 2, tg = lane & 3;

    const int fr = tid >> 1;
    const int fc = (tid & 1) * 8;

    float acc[4][4][4];
    #pragma unroll
    for (int i = 0; i < 4; i++)
        #pragma unroll
        for (int j = 0; j < 4; j++)
            #pragma unroll
            for (int r = 0; r < 4; r++) acc[i][j][r] = 0.f;

    const int NIT = K / 16;

    const int a_row = (lane & 7) + ((lane >> 3) & 1) * 8;
    const int a_kc  = ((lane >> 4) & 1) * 8;
    const int b_row = (lane & 7) + ((lane >> 4) & 1) * 8;
    const int b_kc  = ((lane >> 3) & 1) * 8;

    #pragma unroll
    for (int s = 0; s < 2; s++) {
        if (s < NIT) {
            cp16(smem_u32(&As[s][fr][fc]), &A[(long)(m0 + fr) * K + s * 16 + fc]);
            cp16(smem_u32(&Bs[s][fr][fc]), &Bt[(long)(n0 + fr) * K + s * 16 + fc]);
        }
        cp_commit();
    }

    for (int it = 0; it < NIT; it++) {
        cp_wait1();
        __syncthreads();
        {
            int s = it + 2;
            if (s < NIT) {
                int bufn = s % 3;
                cp16(smem_u32(&As[bufn][fr][fc]), &A[(long)(m0 + fr) * K + s * 16 + fc]);
                cp16(smem_u32(&Bs[bufn][fr][fc]), &Bt[(long)(n0 + fr) * K + s * 16 + fc]);
            }
            cp_commit();
        }
        const int buf = it % 3;

        unsigned a_frag[4][4];
        unsigned b_frag[4][2];
        #pragma unroll
        for (int mi = 0; mi < 4; mi++)
            ldsm4(a_frag[mi], smem_u32(&As[buf][wm + mi * 16 + a_row][a_kc]));
        #pragma unroll
        for (int n2 = 0; n2 < 2; n2++) {
            unsigned r4[4];
            ldsm4(r4, smem_u32(&Bs[buf][wn + n2 * 16 + b_row][b_kc]));
            b_frag[2 * n2][0] = r4[0]; b_frag[2 * n2][1] = r4[1];
            b_frag[2 * n2 + 1][0] = r4[2]; b_frag[2 * n2 + 1][1] = r4[3];
        }
        #pragma unroll
        for (int mi = 0; mi < 4; mi++)
            #pragma unroll
            for (int ni = 0; ni < 4; ni++)
                mma_fp16(acc[mi][ni], a_frag[mi], b_frag[ni]);
    }

    #pragma unroll
    for (int mi = 0; mi < 4; mi++) {
        #pragma unroll
        for (int hf = 0; hf < 2; hf++) {
            int row = m0 + wm + mi * 16 + g + hf * 8;
            long drow = row;
            if (EPI == 1) {
                int bi  = row / (NWIN * NTOK);
                int t   = row % (NWIN * NTOK);
                int win = t / NTOK;
                int n   = t % NTOK;
                int hh2 = (win / 8) * WS + n / WS;
                int ww2 = (win % 8) * WS + n % WS;
                drow = (long)bi * LSEQ + ((hh2 + SH) % HH) * WW + (ww2 + SH) % WW;
            }
            #pragma unroll
            for (int ni = 0; ni < 4; ni++) {
                int col = n0 + wn + ni * 8 + 2 * tg;
                float v0 = acc[mi][ni][hf * 2 + 0] + bias[col];
                float v1 = acc[mi][ni][hf * 2 + 1] + bias[col + 1];
                if (EPI == 1) {
                    float2 r2 = *(const float2*)&res[drow * N + col];
                    *(float2*)&C[drow * N + col] = make_float2(r2.x + v0, r2.y + v1);
                } else {
                    float2 r2 = *(const float2*)&res[(long)row * N + col];
                    *(float2*)&C[(long)row * N + col] = make_float2(r2.x + v0, r2.y + v1);
                }
            }
        }
    }
}

// ============ tensor-core window attention: one block per (window, head), 4 warps ============
__global__ void __launch_bounds__(128)
attn_mma(const __half* __restrict__ qkv,
         const float* __restrict__ biasM,
         __half* __restrict__ out) {
    const int wg = blockIdx.x;      // [0, 4096)
    const int head = blockIdx.y;    // [0, 4)
    const int tid = threadIdx.x;    // 128
    const int lane = tid & 31, wid = tid >> 5;
    const int g = lane >> 2, tg = lane & 3;

    __shared__ __half Qs[64][40];
    __shared__ __half Ks[64][40];
    __shared__ __half Vt[32][72];
    __shared__ float bias_s[NTOK][NTOK];
    __shared__ int lab[64];

    // zero pads
    for (int i = tid; i < 15 * 40; i += 128) {
        int r = 49 + i / 40, c = i % 40;
        Qs[r][c] = __float2half(0.f);
        Ks[r][c] = __float2half(0.f);
    }
    for (int i = tid; i < 32 * 72; i += 128) ((__half*)Vt)[i] = __float2half(0.f);

    // labels
    if (tid < 64) {
        int t = tid < NTOK ? tid : 0;
        int wi = wg & (NWIN - 1);
        int h = (wi / 8) * WS + t / WS;
        int w = (wi % 8) * WS + t % WS;
        int rh = (h < HH - WS) ? 0 : ((h < HH - SH) ? 1 : 2);
        int rw = (w < WW - WS) ? 0 : ((w < WW - SH) ? 1 : 2);
        lab[tid] = rh * 3 + rw;
    }

    // bias matrix for this head
    for (int i = tid; i < NTOK * NTOK; i += 128)
        ((float*)bias_s)[i] = biasM[head * NTOK * NTOK + i];

    // load Q (scaled), K, V (transposed)
    const float scale = rsqrtf((float)HD);
    const __half2 scale2 = __float2half2_rn(scale);
    for (int i = tid; i < NTOK * 4; i += 128) {
        int r = i >> 2, c8 = (i & 3) * 8;
        long base = ((long)wg * NTOK + r) * 384 + c8 + head * 32;
        uint4 qv = *(const uint4*)&qkv[base];
        __half2* qh = (__half2*)&qv;
        #pragma unroll
        for (int j = 0; j < 4; j++) qh[j] = __hmul2(qh[j], scale2);
        *(uint4*)&Qs[r][c8] = qv;
        *(uint4*)&Ks[r][c8] = *(const uint4*)&qkv[base + 128];
        uint4 vv = *(const uint4*)&qkv[base + 256];
        __half* vh = (__half*)&vv;
        #pragma unroll
        for (int j = 0; j < 8; j++) Vt[c8 + j][r] = vh[j];
    }
    __syncthreads();

    const int a_row = (lane & 7) + ((lane >> 3) & 1) * 8;
    const int a_kc  = ((lane >> 4) & 1) * 8;
    const int b_row = (lane & 7) + ((lane >> 4) & 1) * 8;
    const int b_kc  = ((lane >> 3) & 1) * 8;
    const int w16 = wid * 16;

    // ---- S = Q K^T : warp computes 16x64 ----
    float sa[8][4];
    #pragma unroll
    for (int i = 0; i < 8; i++)
        #pragma unroll
        for (int r = 0; r < 4; r++) sa[i][r] = 0.f;

    #pragma unroll
    for (int kc = 0; kc < 2; kc++) {
        unsigned aq[4];
        ldsm4(aq, smem_u32(&Qs[w16 + a_row][kc * 16 + a_kc]));
        #pragma unroll
        for (int nt = 0; nt < 4; nt++) {
            unsigned r4[4];
            ldsm4(r4, smem_u32(&Ks[nt * 16 + b_row][kc * 16 + b_kc]));
            unsigned b0[2] = {r4[0], r4[1]};
            unsigned b1[2] = {r4[2], r4[3]};
            mma_fp16(sa[2 * nt], aq, b0);
            mma_fp16(sa[2 * nt + 1], aq, b1);
        }
    }

    // ---- bias + mask ----
    const int rowA = w16 + g;
    const int rowB = w16 + g + 8;
    const int rA = rowA < NTOK ? rowA : 0;
    const int rB = rowB < NTOK ? rowB : 0;
    const int labA = lab[rA], labB = lab[rB];
    #pragma unroll
    for (int ni = 0; ni < 8; ni++) {
        #pragma unroll
        for (int cc = 0; cc < 2; cc++) {
            int m = 8 * ni + 2 * tg + cc;
            if (m < NTOK) {
                int lm = lab[m];
                sa[ni][cc]     += bias_s[rA][m] + (labA != lm ? -100.f : 0.f);
                sa[ni][cc + 2] += bias_s[rB][m] + (labB != lm ? -100.f : 0.f);
            } else {
                sa[ni][cc] = -1e30f;
                sa[ni][cc + 2] = -1e30f;
            }
        }
    }

    // ---- softmax over each row (A: regs 0,1; B: regs 2,3) across 4 tg lanes ----
    float mxA = -1e30f, mxB = -1e30f;
    #pragma unroll
    for (int ni = 0; ni < 8; ni++) {
        mxA = fmaxf(mxA, fmaxf(sa[ni][0], sa[ni][1]));
        mxB = fmaxf(mxB, fmaxf(sa[ni][2], sa[ni][3]));
    }
    #pragma unroll
    for (int o = 1; o <= 2; o <<= 1) {
        mxA = fmaxf(mxA, __shfl_xor_sync(0xffffffffu, mxA, o));
        mxB = fmaxf(mxB, __shfl_xor_sync(0xffffffffu, mxB, o));
    }
    float smA = 0.f, smB = 0.f;
    #pragma unroll
    for (int ni = 0; ni < 8; ni++) {
        sa[ni][0] = expf(sa[ni][0] - mxA); smA += sa[ni][0];
        sa[ni][1] = expf(sa[ni][1] - mxA); smA += sa[ni][1];
        sa[ni][2] = expf(sa[ni][2] - mxB); smB += sa[ni][2];
        sa[ni][3] = expf(sa[ni][3] - mxB); smB += sa[ni][3];
    }
    #pragma unroll
    for (int o = 1; o <= 2; o <<= 1) {
        smA += __shfl_xor_sync(0xffffffffu, smA, o);
        smB += __shfl_xor_sync(0xffffffffu, smB, o);
    }
    const float ivA = 1.0f / smA, ivB = 1.0f / smB;

    // ---- pack P to A-fragments (4 k-chunks over k=64) ----
    unsigned ap[4][4];
    #pragma unroll
    for (int kc = 0; kc < 4; kc++) {
        ap[kc][0] = h2_as_u32(__floats2half2_rn(sa[2 * kc][0] * ivA, sa[2 * kc][1] * ivA));
        ap[kc][1] = h2_as_u32(__floats2half2_rn(sa[2 * kc][2] * ivB, sa[2 * kc][3] * ivB));
        ap[kc][2] = h2_as_u32(__floats2half2_rn(sa[2 * kc + 1][0] * ivA, sa[2 * kc + 1][1] * ivA));
        ap[kc][3] = h2_as_u32(__floats2half2_rn(sa[2 * kc + 1][2] * ivB, sa[2 * kc + 1][3] * ivB));
    }

    // ---- O = P V : warp computes 16x32 ----
    float oa[4][4];
    #pragma unroll
    for (int i = 0; i < 4; i++)
        #pragma unroll
        for (int r = 0; r < 4; r++) oa[i][r] = 0.f;

    #pragma unroll
    for (int kc = 0; kc < 4; kc++) {
        #pragma unroll
        for (int nt = 0; nt < 2; nt++) {
            unsigned r4[4];
            ldsm4(r4, smem_u32(&Vt[nt * 16 + b_row][kc * 16 + b_kc]));
            unsigned b0[2] = {r4[0], r4[1]};
            unsigned b1[2] = {r4[2], r4[3]};
            mma_fp16(oa[2 * nt], ap[kc], b0);
            mma_fp16(oa[2 * nt + 1], ap[kc], b1);
        }
    }

    // ---- store ----
    #pragma unroll
    for (int ni = 0; ni < 4; ni++) {
        int d0 = 8 * ni + 2 * tg;
        if (rowA < NTOK)
            *(__half2*)&out[((long)wg * NTOK + rowA) * CDIM + head * 32 + d0] =
                __floats2half2_rn(oa[ni][0], oa[ni][1]);
        if (rowB < NTOK)
            *(__half2*)&out[((long)wg * NTOK + rowB) * CDIM + head * 32 + d0] =
                __floats2half2_rn(oa[ni][2], oa[ni][3]);
    }
}

// ---------------- launch ----------------
extern "C" void kernel_launch(void* const* d_in, const int* in_sizes, int n_in,
                              void* d_out, int out_size) {
    const float* x      = (const float*)d_in[0];
    const float* qkv_w  = (const float*)d_in[1];
    const float* qkv_b  = (const float*)d_in[2];
    const float* proj_w = (const float*)d_in[3];
    const float* proj_b = (const float*)d_in[4];
    const float* rpb    = (const float*)d_in[5];
    const float* n1g    = (const float*)d_in[6];
    const float* n1b    = (const float*)d_in[7];
    const float* n2g    = (const float*)d_in[8];
    const float* n2b    = (const float*)d_in[9];
    const float* fc1_w  = (const float*)d_in[10];
    const float* fc1_b  = (const float*)d_in[11];
    const float* fc2_w  = (const float*)d_in[12];
    const float* fc2_b  = (const float*)d_in[13];
    float* out = (float*)d_out;

    __half *qkvh, *atth, *hidh, *wqkv, *wproj, *wfc1, *wfc2;
    float* biasM;
    cudaGetSymbolAddress((void**)&qkvh, g_qkvh);
    cudaGetSymbolAddress((void**)&atth, g_atth);
    cudaGetSymbolAddress((void**)&hidh, g_hidh);
    cudaGetSymbolAddress((void**)&wqkv, g_wqkv);
    cudaGetSymbolAddress((void**)&wproj, g_wproj);
    cudaGetSymbolAddress((void**)&wfc1, g_wfc1);
    cudaGetSymbolAddress((void**)&wfc2, g_wfc2);
    cudaGetSymbolAddress((void**)&biasM, g_biasM);

    static bool attr_set = false;
    if (!attr_set) {
        cudaFuncSetAttribute(ln_gemm<3, true, false>,
                             cudaFuncAttributeMaxDynamicSharedMemorySize, DSMEM_LNGEMM);
        cudaFuncSetAttribute(ln_gemm<4, false, true>,
                             cudaFuncAttributeMaxDynamicSharedMemorySize, DSMEM_LNGEMM);
        attr_set = true;
    }

    convert_all<<<768, 256>>>(qkv_w, proj_w, fc1_w, fc2_w, wqkv, wproj, wfc1, wfc2);
    bias_pre<<<(NHEAD * NTOK * NTOK + 255) / 256, 256>>>(rpb, biasM);

    // 1. LN1 + roll + partition + QKV GEMM (fused)
    ln_gemm<3, true, false><<<MROWS / 128, 256, DSMEM_LNGEMM>>>(
        x, wqkv, qkv_b, n1g, n1b, qkvh);
    // 2. attention (tensor cores)
    attn_mma<<<dim3(BIMG * NWIN, NHEAD), 128>>>(qkvh, biasM, atth);
    // 3. proj + window-reverse + roll + residual -> d_out (f32)
    gemm_h<128, 128, 1><<<dim3(MROWS / 128, 1), 256>>>(atth, wproj, proj_b, out, x);
    // 4. LN2 + fc1 + GELU (fused)
    ln_gemm<4, false, true><<<MROWS / 128, 256, DSMEM_LNGEMM>>>(
        out, wfc1, fc1_b, n2g, n2b, hidh);
    // 5. fc2 + residual -> d_out
    gemm_h<128, 512, 3><<<dim3(MROWS / 128, 1), 256>>>(hidh, wfc2, fc2_b, out, out);
}

// round 10
// speedup vs baseline: 5.7544x; 1.0666x over previous
#include <cuda_runtime.h>
#include <cuda_fp16.h>
#include <cstdint>
#include <math.h>

#define HH 56
#define WW 56
#define WS 7
#define SH 3
#define NHEAD 4
#define HD 32
#define CDIM 128
#define NTOK 49
#define NWIN 64
#define BIMG 64
#define MROWS (BIMG * NWIN * NTOK)   // 200704
#define LSEQ (HH * WW)
#define EPS 1e-5f

// ---------------- scratch ----------------
__device__ __half g_qkvh[(size_t)MROWS * 3 * CDIM];
__device__ __half g_atth[(size_t)MROWS * CDIM];
__device__ __half g_hidh[(size_t)MROWS * 512];
__device__ __half g_wqkv[384 * 128];
__device__ __half g_wproj[128 * 128];
__device__ __half g_wfc1[512 * 128];
__device__ __half g_wfc2[128 * 512];
__device__ __half g_biasMh[NHEAD * NTOK * NTOK];

// ---------------- ptx helpers ----------------
__device__ __forceinline__ unsigned smem_u32(const void* p) {
    return (unsigned)__cvta_generic_to_shared(p);
}
__device__ __forceinline__ unsigned h2_as_u32(__half2 h) {
    return *(unsigned*)&h;
}
__device__ __forceinline__ void cp16(unsigned dst, const void* src) {
    asm volatile("cp.async.cg.shared.global [%0], [%1], 16;" :: "r"(dst), "l"(src));
}
__device__ __forceinline__ void cp_commit() { asm volatile("cp.async.commit_group;"); }
__device__ __forceinline__ void cp_wait1() { asm volatile("cp.async.wait_group 1;"); }
__device__ __forceinline__ void cp_wait0() { asm volatile("cp.async.wait_group 0;"); }

__device__ __forceinline__ void ldsm4(unsigned* r, unsigned addr) {
    asm volatile("ldmatrix.sync.aligned.m8n8.x4.shared.b16 {%0,%1,%2,%3}, [%4];"
                 : "=r"(r[0]), "=r"(r[1]), "=r"(r[2]), "=r"(r[3]) : "r"(addr));
}
__device__ __forceinline__ void ldsm4t(unsigned* r, unsigned addr) {
    asm volatile("ldmatrix.sync.aligned.m8n8.x4.trans.shared.b16 {%0,%1,%2,%3}, [%4];"
                 : "=r"(r[0]), "=r"(r[1]), "=r"(r[2]), "=r"(r[3]) : "r"(addr));
}
__device__ __forceinline__ void mma_fp16(float* d, const unsigned* a, const unsigned* b) {
    asm volatile(
        "mma.sync.aligned.m16n8k16.row.col.f32.f16.f16.f32 "
        "{%0,%1,%2,%3}, {%4,%5,%6,%7}, {%8,%9}, {%0,%1,%2,%3};\n"
        : "+f"(d[0]), "+f"(d[1]), "+f"(d[2]), "+f"(d[3])
        : "r"(a[0]), "r"(a[1]), "r"(a[2]), "r"(a[3]), "r"(b[0]), "r"(b[1]));
}

// ---------------- fused weight convert + transpose (4 matrices, 1 launch) ----------------
__global__ void convert_all(const float* __restrict__ qkv_w, const float* __restrict__ proj_w,
                            const float* __restrict__ fc1_w, const float* __restrict__ fc2_w,
                            __half* __restrict__ wqkv, __half* __restrict__ wproj,
                            __half* __restrict__ wfc1, __half* __restrict__ wfc2) {
    int i = blockIdx.x * 256 + threadIdx.x;
    if (i < 49152) {
        int k = i / 384, n = i % 384;
        wqkv[n * 128 + k] = __float2half(qkv_w[i]);
    } else if (i < 65536) {
        int j = i - 49152;
        int k = j / 128, n = j % 128;
        wproj[n * 128 + k] = __float2half(proj_w[j]);
    } else if (i < 131072) {
        int j = i - 65536;
        int k = j / 512, n = j % 512;
        wfc1[n * 128 + k] = __float2half(fc1_w[j]);
    } else if (i < 196608) {
        int j = i - 131072;
        int k = j / 128, n = j % 128;
        wfc2[n * 512 + k] = __float2half(fc2_w[j]);
    }
}

// ---------------- relative-position bias precompute (half): biasMh[h][n][m] ----------------
__global__ void bias_pre(const float* __restrict__ rpb, __half* __restrict__ biasMh) {
    int i = blockIdx.x * 256 + threadIdx.x;
    if (i < NHEAD * NTOK * NTOK) {
        int h = i / (NTOK * NTOK);
        int r = i % (NTOK * NTOK);
        int n = r / NTOK, m = r % NTOK;
        int ridx = (n / WS - m / WS + WS - 1) * (2 * WS - 1) + (n % WS - m % WS + WS - 1);
        biasMh[i] = __float2half(rpb[ridx * NHEAD + h]);
    }
}

// ============ fused LN + GEMM (K=128), A kept resident across N-chunks ============
#define DSMEM_LNGEMM (34816 * 2 + 16384)
template<int NCHUNKS, bool GATHER, bool DOGELU>
__global__ void __launch_bounds__(256)
ln_gemm(const float* __restrict__ X, const __half* __restrict__ Bt,
        const float* __restrict__ bias, const float* __restrict__ lng,
        const float* __restrict__ lnb, __half* __restrict__ C) {
    extern __shared__ char dyn[];
    __half (*As)[136] = (__half(*)[136])dyn;
    __half (*Bs)[136] = (__half(*)[136])(dyn + 34816);
    float (*stage)[128] = (float(*)[128])(dyn + 69632);

    const int tid = threadIdx.x;
    const int lane = tid & 31, wid = tid >> 5;
    const int m0 = blockIdx.x * 128;
    const int NT = NCHUNKS * 128;

    for (int rs = 0; rs < 128; rs += 32) {
        #pragma unroll
        for (int t = 0; t < 4; t++) {
            int i = tid + t * 256;
            int row = i >> 5;
            int c4 = (i & 31) * 4;
            int R = m0 + rs + row;
            long srow;
            if (GATHER) {
                int bi = R / (NWIN * NTOK);
                int tt = R % (NWIN * NTOK);
                int win = tt / NTOK, n = tt % NTOK;
                int hh = (win / 8) * WS + n / WS;
                int ww = (win % 8) * WS + n % WS;
                srow = (long)bi * LSEQ + ((hh + SH) % HH) * WW + (ww + SH) % WW;
            } else {
                srow = R;
            }
            *(float4*)&stage[row][c4] = *(const float4*)&X[srow * CDIM + c4];
        }
        __syncthreads();
        #pragma unroll
        for (int rr = 0; rr < 4; rr++) {
            int row = wid * 4 + rr;
            float v[4];
            #pragma unroll
            for (int t = 0; t < 4; t++) v[t] = stage[row][lane + t * 32];
            float s = v[0] + v[1] + v[2] + v[3];
            float s2 = v[0] * v[0] + v[1] * v[1] + v[2] * v[2] + v[3] * v[3];
            #pragma unroll
            for (int o = 16; o; o >>= 1) {
                s += __shfl_xor_sync(0xffffffffu, s, o);
                s2 += __shfl_xor_sync(0xffffffffu, s2, o);
            }
            float mu = s * (1.f / 128.f);
            float inv = rsqrtf(s2 * (1.f / 128.f) - mu * mu + EPS);
            #pragma unroll
            for (int t = 0; t < 4; t++) {
                int c = lane + t * 32;
                As[rs + row][c] = __float2half((v[t] - mu) * inv * lng[c] + lnb[c]);
            }
        }
        __syncthreads();
    }

    const int a_row = (lane & 7) + ((lane >> 3) & 1) * 8;
    const int a_kc  = ((lane >> 4) & 1) * 8;
    const int b_row = (lane & 7) + ((lane >> 4) & 1) * 8;
    const int b_kc  = ((lane >> 3) & 1) * 8;
    const int wm = (wid & 1) * 64;
    const int wn = (wid >> 1) * 32;
    const int g = lane >> 2, tg = lane & 3;

    for (int c = 0; c < NCHUNKS; c++) {
        #pragma unroll
        for (int t = 0; t < 8; t++) {
            int i = tid + t * 256;
            int row = i >> 4;
            int col = (i & 15) * 8;
            cp16(smem_u32(&Bs[row][col]), &Bt[(long)(c * 128 + row) * CDIM + col]);
        }
        cp_commit();
        cp_wait0();
        __syncthreads();

        float acc[4][4][4];
        #pragma unroll
        for (int i = 0; i < 4; i++)
            #pragma unroll
            for (int j = 0; j < 4; j++)
                #pragma unroll
                for (int r = 0; r < 4; r++) acc[i][j][r] = 0.f;

        #pragma unroll
        for (int it = 0; it < 8; it++) {
            const int k0 = it * 16;
            unsigned a_frag[4][4], b_frag[4][2];
            #pragma unroll
            for (int mi = 0; mi < 4; mi++)
                ldsm4(a_frag[mi], smem_u32(&As[wm + mi * 16 + a_row][k0 + a_kc]));
            #pragma unroll
            for (int n2 = 0; n2 < 2; n2++) {
                unsigned r4[4];
                ldsm4(r4, smem_u32(&Bs[wn + n2 * 16 + b_row][k0 + b_kc]));
                b_frag[2 * n2][0] = r4[0]; b_frag[2 * n2][1] = r4[1];
                b_frag[2 * n2 + 1][0] = r4[2]; b_frag[2 * n2 + 1][1] = r4[3];
            }
            #pragma unroll
            for (int mi = 0; mi < 4; mi++)
                #pragma unroll
                for (int ni = 0; ni < 4; ni++)
                    mma_fp16(acc[mi][ni], a_frag[mi], b_frag[ni]);
        }
        __syncthreads();

        #pragma unroll
        for (int mi = 0; mi < 4; mi++) {
            #pragma unroll
            for (int hf = 0; hf < 2; hf++) {
                int row = m0 + wm + mi * 16 + g + hf * 8;
                #pragma unroll
                for (int ni = 0; ni < 4; ni++) {
                    int col = c * 128 + wn + ni * 8 + 2 * tg;
                    float v0 = acc[mi][ni][hf * 2 + 0] + bias[col];
                    float v1 = acc[mi][ni][hf * 2 + 1] + bias[col + 1];
                    if (DOGELU) {
                        v0 = 0.5f * v0 * (1.0f + erff(v0 * 0.70710678118654752f));
                        v1 = 0.5f * v1 * (1.0f + erff(v1 * 0.70710678118654752f));
                    }
                    *(__half2*)&C[(long)row * NT + col] = __floats2half2_rn(v0, v1);
                }
            }
        }
    }
}

// ---------------- fp16 GEMM with cp.async pipeline (proj / fc2) ----------------
template<int N, int K, int EPI>
__global__ void __launch_bounds__(256, 2)
gemm_h(const __half* __restrict__ A, const __half* __restrict__ Bt,
       const float* __restrict__ bias, float* __restrict__ C,
       const float* __restrict__ res) {
    __shared__ __half As[3][128][24];
    __shared__ __half Bs[3][128][24];

    const int tid = threadIdx.x;
    const int lane = tid & 31, wid = tid >> 5;
    const int wm = (wid & 1) * 64;
    const int wn = (wid >> 1) * 32;
    const int m0 = blockIdx.x * 128;
    const int n0 = blockIdx.y * 128;
    const int g = lane >> 2, tg = lane & 3;

    const int fr = tid >> 1;
    const int fc = (tid & 1) * 8;

    float acc[4][4][4];
    #pragma unroll
    for (int i = 0; i < 4; i++)
        #pragma unroll
        for (int j = 0; j < 4; j++)
            #pragma unroll
            for (int r = 0; r < 4; r++) acc[i][j][r] = 0.f;

    const int NIT = K / 16;

    const int a_row = (lane & 7) + ((lane >> 3) & 1) * 8;
    const int a_kc  = ((lane >> 4) & 1) * 8;
    const int b_row = (lane & 7) + ((lane >> 4) & 1) * 8;
    const int b_kc  = ((lane >> 3) & 1) * 8;

    #pragma unroll
    for (int s = 0; s < 2; s++) {
        if (s < NIT) {
            cp16(smem_u32(&As[s][fr][fc]), &A[(long)(m0 + fr) * K + s * 16 + fc]);
            cp16(smem_u32(&Bs[s][fr][fc]), &Bt[(long)(n0 + fr) * K + s * 16 + fc]);
        }
        cp_commit();
    }

    for (int it = 0; it < NIT; it++) {
        cp_wait1();
        __syncthreads();
        {
            int s = it + 2;
            if (s < NIT) {
                int bufn = s % 3;
                cp16(smem_u32(&As[bufn][fr][fc]), &A[(long)(m0 + fr) * K + s * 16 + fc]);
                cp16(smem_u32(&Bs[bufn][fr][fc]), &Bt[(long)(n0 + fr) * K + s * 16 + fc]);
            }
            cp_commit();
        }
        const int buf = it % 3;

        unsigned a_frag[4][4];
        unsigned b_frag[4][2];
        #pragma unroll
        for (int mi = 0; mi < 4; mi++)
            ldsm4(a_frag[mi], smem_u32(&As[buf][wm + mi * 16 + a_row][a_kc]));
        #pragma unroll
        for (int n2 = 0; n2 < 2; n2++) {
            unsigned r4[4];
            ldsm4(r4, smem_u32(&Bs[buf][wn + n2 * 16 + b_row][b_kc]));
            b_frag[2 * n2][0] = r4[0]; b_frag[2 * n2][1] = r4[1];
            b_frag[2 * n2 + 1][0] = r4[2]; b_frag[2 * n2 + 1][1] = r4[3];
        }
        #pragma unroll
        for (int mi = 0; mi < 4; mi++)
            #pragma unroll
            for (int ni = 0; ni < 4; ni++)
                mma_fp16(acc[mi][ni], a_frag[mi], b_frag[ni]);
    }

    #pragma unroll
    for (int mi = 0; mi < 4; mi++) {
        #pragma unroll
        for (int hf = 0; hf < 2; hf++) {
            int row = m0 + wm + mi * 16 + g + hf * 8;
            long drow = row;
            if (EPI == 1) {
                int bi  = row / (NWIN * NTOK);
                int t   = row % (NWIN * NTOK);
                int win = t / NTOK;
                int n   = t % NTOK;
                int hh2 = (win / 8) * WS + n / WS;
                int ww2 = (win % 8) * WS + n % WS;
                drow = (long)bi * LSEQ + ((hh2 + SH) % HH) * WW + (ww2 + SH) % WW;
            }
            #pragma unroll
            for (int ni = 0; ni < 4; ni++) {
                int col = n0 + wn + ni * 8 + 2 * tg;
                float v0 = acc[mi][ni][hf * 2 + 0] + bias[col];
                float v1 = acc[mi][ni][hf * 2 + 1] + bias[col + 1];
                if (EPI == 1) {
                    float2 r2 = *(const float2*)&res[drow * N + col];
                    *(float2*)&C[drow * N + col] = make_float2(r2.x + v0, r2.y + v1);
                } else {
                    float2 r2 = *(const float2*)&res[(long)row * N + col];
                    *(float2*)&C[(long)row * N + col] = make_float2(r2.x + v0, r2.y + v1);
                }
            }
        }
    }
}

// ============ tensor-core window attention v2 ============
__global__ void __launch_bounds__(128)
attn_mma(const __half* __restrict__ qkv,
         const __half* __restrict__ biasMh,
         __half* __restrict__ out) {
    const int wg = blockIdx.x;
    const int head = blockIdx.y;
    const int tid = threadIdx.x;
    const int lane = tid & 31, wid = tid >> 5;
    const int g = lane >> 2, tg = lane & 3;

    __shared__ __half Qs[64][40];
    __shared__ __half Ks[64][40];
    __shared__ __half Vs[64][40];
    __shared__ __half bias_s[NTOK][NTOK + 1];
    __shared__ int lab[64];

    // zero ONLY Vs pad rows (P is exactly 0 for pad m, but must multiply finite values)
    for (int i = tid; i < 15 * 40; i += 128) {
        Vs[49 + i / 40][i % 40] = __float2half(0.f);
    }

    if (tid < 64) {
        int t = tid < NTOK ? tid : 0;
        int wi = wg & (NWIN - 1);
        int h = (wi / 8) * WS + t / WS;
        int w = (wi % 8) * WS + t % WS;
        int rh = (h < HH - WS) ? 0 : ((h < HH - SH) ? 1 : 2);
        int rw = (w < WW - WS) ? 0 : ((w < WW - SH) ? 1 : 2);
        lab[tid] = rh * 3 + rw;
    }

    // bias table (half)
    for (int i = tid; i < NTOK * NTOK; i += 128) {
        int n = i / NTOK, m = i % NTOK;
        bias_s[n][m] = biasMh[head * NTOK * NTOK + i];
    }

    // load Q (scaled), K, V — all plain vectorized row stores
    const __half2 scale2 = __float2half2_rn(0.1767766952966369f);  // 1/sqrt(32)
    for (int i = tid; i < NTOK * 4; i += 128) {
        int r = i >> 2, c8 = (i & 3) * 8;
        long base = ((long)wg * NTOK + r) * 384 + c8 + head * 32;
        uint4 qv = *(const uint4*)&qkv[base];
        __half2* qh = (__half2*)&qv;
        #pragma unroll
        for (int j = 0; j < 4; j++) qh[j] = __hmul2(qh[j], scale2);
        *(uint4*)&Qs[r][c8] = qv;
        *(uint4*)&Ks[r][c8] = *(const uint4*)&qkv[base + 128];
        *(uint4*)&Vs[r][c8] = *(const uint4*)&qkv[base + 256];
    }
    __syncthreads();

    const int a_row = (lane & 7) + ((lane >> 3) & 1) * 8;
    const int a_kc  = ((lane >> 4) & 1) * 8;
    const int b_row = (lane & 7) + ((lane >> 4) & 1) * 8;
    const int b_kc  = ((lane >> 3) & 1) * 8;
    // trans-ldmatrix lane address pattern (V as B via .trans)
    const int t_row = (lane & 7) + ((lane >> 3) & 1) * 8;
    const int t_col = (lane >> 4) * 8;
    const int w16 = wid * 16;

    // ---- S = Q K^T : warp computes 16x64 ----
    float sa[8][4];
    #pragma unroll
    for (int i = 0; i < 8; i++)
        #pragma unroll
        for (int r = 0; r < 4; r++) sa[i][r] = 0.f;

    #pragma unroll
    for (int kc = 0; kc < 2; kc++) {
        unsigned aq[4];
        ldsm4(aq, smem_u32(&Qs[w16 + a_row][kc * 16 + a_kc]));
        #pragma unroll
        for (int nt = 0; nt < 4; nt++) {
            unsigned r4[4];
            ldsm4(r4, smem_u32(&Ks[nt * 16 + b_row][kc * 16 + b_kc]));
            unsigned b0[2] = {r4[0], r4[1]};
            unsigned b1[2] = {r4[2], r4[3]};
            mma_fp16(sa[2 * nt], aq, b0);
            mma_fp16(sa[2 * nt + 1], aq, b1);
        }
    }

    // ---- bias + mask ----
    const int rowA = w16 + g;
    const int rowB = w16 + g + 8;
    const int rA = rowA < NTOK ? rowA : 0;
    const int rB = rowB < NTOK ? rowB : 0;
    const int labA = lab[rA], labB = lab[rB];
    #pragma unroll
    for (int ni = 0; ni < 8; ni++) {
        #pragma unroll
        for (int cc = 0; cc < 2; cc++) {
            int m = 8 * ni + 2 * tg + cc;
            if (m < NTOK) {
                int lm = lab[m];
                sa[ni][cc]     += __half2float(bias_s[rA][m]) + (labA != lm ? -100.f : 0.f);
                sa[ni][cc + 2] += __half2float(bias_s[rB][m]) + (labB != lm ? -100.f : 0.f);
            } else {
                sa[ni][cc] = -1e30f;
                sa[ni][cc + 2] = -1e30f;
            }
        }
    }

    // ---- softmax (fast exp) ----
    float mxA = -1e30f, mxB = -1e30f;
    #pragma unroll
    for (int ni = 0; ni < 8; ni++) {
        mxA = fmaxf(mxA, fmaxf(sa[ni][0], sa[ni][1]));
        mxB = fmaxf(mxB, fmaxf(sa[ni][2], sa[ni][3]));
    }
    #pragma unroll
    for (int o = 1; o <= 2; o <<= 1) {
        mxA = fmaxf(mxA, __shfl_xor_sync(0xffffffffu, mxA, o));
        mxB = fmaxf(mxB, __shfl_xor_sync(0xffffffffu, mxB, o));
    }
    float smA = 0.f, smB = 0.f;
    #pragma unroll
    for (int ni = 0; ni < 8; ni++) {
        sa[ni][0] = __expf(sa[ni][0] - mxA); smA += sa[ni][0];
        sa[ni][1] = __expf(sa[ni][1] - mxA); smA += sa[ni][1];
        sa[ni][2] = __expf(sa[ni][2] - mxB); smB += sa[ni][2];
        sa[ni][3] = __expf(sa[ni][3] - mxB); smB += sa[ni][3];
    }
    #pragma unroll
    for (int o = 1; o <= 2; o <<= 1) {
        smA += __shfl_xor_sync(0xffffffffu, smA, o);
        smB += __shfl_xor_sync(0xffffffffu, smB, o);
    }
    const float ivA = 1.0f / smA, ivB = 1.0f / smB;

    // ---- pack P to A-fragments ----
    unsigned ap[4][4];
    #pragma unroll
    for (int kc = 0; kc < 4; kc++) {
        ap[kc][0] = h2_as_u32(__floats2half2_rn(sa[2 * kc][0] * ivA, sa[2 * kc][1] * ivA));
        ap[kc][1] = h2_as_u32(__floats2half2_rn(sa[2 * kc][2] * ivB, sa[2 * kc][3] * ivB));
        ap[kc][2] = h2_as_u32(__floats2half2_rn(sa[2 * kc + 1][0] * ivA, sa[2 * kc + 1][1] * ivA));
        ap[kc][3] = h2_as_u32(__floats2half2_rn(sa[2 * kc + 1][2] * ivB, sa[2 * kc + 1][3] * ivB));
    }

    // ---- O = P V via trans-ldmatrix (V stored row-major [m][d]) ----
    float oa[4][4];
    #pragma unroll
    for (int i = 0; i < 4; i++)
        #pragma unroll
        for (int r = 0; r < 4; r++) oa[i][r] = 0.f;

    #pragma unroll
    for (int kc = 0; kc < 4; kc++) {
        #pragma unroll
        for (int nt = 0; nt < 2; nt++) {
            unsigned r4[4];
            ldsm4t(r4, smem_u32(&Vs[kc * 16 + t_row][nt * 16 + t_col]));
            unsigned b0[2] = {r4[0], r4[1]};
            unsigned b1[2] = {r4[2], r4[3]};
            mma_fp16(oa[2 * nt], ap[kc], b0);
            mma_fp16(oa[2 * nt + 1], ap[kc], b1);
        }
    }

    // ---- store ----
    #pragma unroll
    for (int ni = 0; ni < 4; ni++) {
        int d0 = 8 * ni + 2 * tg;
        if (rowA < NTOK)
            *(__half2*)&out[((long)wg * NTOK + rowA) * CDIM + head * 32 + d0] =
                __floats2half2_rn(oa[ni][0], oa[ni][1]);
        if (rowB < NTOK)
            *(__half2*)&out[((long)wg * NTOK + rowB) * CDIM + head * 32 + d0] =
                __floats2half2_rn(oa[ni][2], oa[ni][3]);
    }
}

// ---------------- launch ----------------
extern "C" void kernel_launch(void* const* d_in, const int* in_sizes, int n_in,
                              void* d_out, int out_size) {
    const float* x      = (const float*)d_in[0];
    const float* qkv_w  = (const float*)d_in[1];
    const float* qkv_b  = (const float*)d_in[2];
    const float* proj_w = (const float*)d_in[3];
    const float* proj_b = (const float*)d_in[4];
    const float* rpb    = (const float*)d_in[5];
    const float* n1g    = (const float*)d_in[6];
    const float* n1b    = (const float*)d_in[7];
    const float* n2g    = (const float*)d_in[8];
    const float* n2b    = (const float*)d_in[9];
    const float* fc1_w  = (const float*)d_in[10];
    const float* fc1_b  = (const float*)d_in[11];
    const float* fc2_w  = (const float*)d_in[12];
    const float* fc2_b  = (const float*)d_in[13];
    float* out = (float*)d_out;

    __half *qkvh, *atth, *hidh, *wqkv, *wproj, *wfc1, *wfc2, *biasMh;
    cudaGetSymbolAddress((void**)&qkvh, g_qkvh);
    cudaGetSymbolAddress((void**)&atth, g_atth);
    cudaGetSymbolAddress((void**)&hidh, g_hidh);
    cudaGetSymbolAddress((void**)&wqkv, g_wqkv);
    cudaGetSymbolAddress((void**)&wproj, g_wproj);
    cudaGetSymbolAddress((void**)&wfc1, g_wfc1);
    cudaGetSymbolAddress((void**)&wfc2, g_wfc2);
    cudaGetSymbolAddress((void**)&biasMh, g_biasMh);

    static bool attr_set = false;
    if (!attr_set) {
        cudaFuncSetAttribute(ln_gemm<3, true, false>,
                             cudaFuncAttributeMaxDynamicSharedMemorySize, DSMEM_LNGEMM);
        cudaFuncSetAttribute(ln_gemm<4, false, true>,
                             cudaFuncAttributeMaxDynamicSharedMemorySize, DSMEM_LNGEMM);
        attr_set = true;
    }

    convert_all<<<768, 256>>>(qkv_w, proj_w, fc1_w, fc2_w, wqkv, wproj, wfc1, wfc2);
    bias_pre<<<(NHEAD * NTOK * NTOK + 255) / 256, 256>>>(rpb, biasMh);

    ln_gemm<3, true, false><<<MROWS / 128, 256, DSMEM_LNGEMM>>>(
        x, wqkv, qkv_b, n1g, n1b, qkvh);
    attn_mma<<<dim3(BIMG * NWIN, NHEAD), 128>>>(qkvh, biasMh, atth);
    gemm_h<128, 128, 1><<<dim3(MROWS / 128, 1), 256>>>(atth, wproj, proj_b, out, x);
    ln_gemm<4, false, true><<<MROWS / 128, 256, DSMEM_LNGEMM>>>(
        out, wfc1, fc1_b, n2g, n2b, hidh);
    gemm_h<128, 512, 3><<<dim3(MROWS / 128, 1), 256>>>(hidh, wfc2, fc2_b, out, out);
}

// round 11
// speedup vs baseline: 6.0896x; 1.0582x over previous
#include <cuda_runtime.h>
#include <cuda_fp16.h>
#include <cstdint>
#include <math.h>

#define HH 56
#define WW 56
#define WS 7
#define SH 3
#define NHEAD 4
#define HD 32
#define CDIM 128
#define NTOK 49
#define NWIN 64
#define BIMG 64
#define MROWS (BIMG * NWIN * NTOK)   // 200704
#define LSEQ (HH * WW)
#define EPS 1e-5f

// ---------------- scratch ----------------
__device__ __half g_qkvh[(size_t)MROWS * 3 * CDIM];
__device__ __half g_atth[(size_t)MROWS * CDIM];
__device__ __half g_hidh[(size_t)MROWS * 512];
__device__ __half g_wqkv[384 * 128];
__device__ __half g_wproj[128 * 128];
__device__ __half g_wfc1[512 * 128];
__device__ __half g_wfc2[128 * 512];
__device__ __half g_biasMh[NHEAD * NTOK * NTOK];

// ---------------- ptx helpers ----------------
__device__ __forceinline__ unsigned smem_u32(const void* p) {
    return (unsigned)__cvta_generic_to_shared(p);
}
__device__ __forceinline__ unsigned h2_as_u32(__half2 h) {
    return *(unsigned*)&h;
}
__device__ __forceinline__ void cp16(unsigned dst, const void* src) {
    asm volatile("cp.async.cg.shared.global [%0], [%1], 16;" :: "r"(dst), "l"(src));
}
__device__ __forceinline__ void cp_commit() { asm volatile("cp.async.commit_group;"); }
__device__ __forceinline__ void cp_wait1() { asm volatile("cp.async.wait_group 1;"); }
__device__ __forceinline__ void cp_wait0() { asm volatile("cp.async.wait_group 0;"); }

__device__ __forceinline__ void ldsm4(unsigned* r, unsigned addr) {
    asm volatile("ldmatrix.sync.aligned.m8n8.x4.shared.b16 {%0,%1,%2,%3}, [%4];"
                 : "=r"(r[0]), "=r"(r[1]), "=r"(r[2]), "=r"(r[3]) : "r"(addr));
}
__device__ __forceinline__ void ldsm4t(unsigned* r, unsigned addr) {
    asm volatile("ldmatrix.sync.aligned.m8n8.x4.trans.shared.b16 {%0,%1,%2,%3}, [%4];"
                 : "=r"(r[0]), "=r"(r[1]), "=r"(r[2]), "=r"(r[3]) : "r"(addr));
}
__device__ __forceinline__ void mma_fp16(float* d, const unsigned* a, const unsigned* b) {
    asm volatile(
        "mma.sync.aligned.m16n8k16.row.col.f32.f16.f16.f32 "
        "{%0,%1,%2,%3}, {%4,%5,%6,%7}, {%8,%9}, {%0,%1,%2,%3};\n"
        : "+f"(d[0]), "+f"(d[1]), "+f"(d[2]), "+f"(d[3])
        : "r"(a[0]), "r"(a[1]), "r"(a[2]), "r"(a[3]), "r"(b[0]), "r"(b[1]));
}

// ---------------- fused weight convert + transpose ----------------
__global__ void convert_all(const float* __restrict__ qkv_w, const float* __restrict__ proj_w,
                            const float* __restrict__ fc1_w, const float* __restrict__ fc2_w,
                            __half* __restrict__ wqkv, __half* __restrict__ wproj,
                            __half* __restrict__ wfc1, __half* __restrict__ wfc2) {
    int i = blockIdx.x * 256 + threadIdx.x;
    if (i < 49152) {
        int k = i / 384, n = i % 384;
        wqkv[n * 128 + k] = __float2half(qkv_w[i]);
    } else if (i < 65536) {
        int j = i - 49152;
        int k = j / 128, n = j % 128;
        wproj[n * 128 + k] = __float2half(proj_w[j]);
    } else if (i < 131072) {
        int j = i - 65536;
        int k = j / 512, n = j % 512;
        wfc1[n * 128 + k] = __float2half(fc1_w[j]);
    } else if (i < 196608) {
        int j = i - 131072;
        int k = j / 128, n = j % 128;
        wfc2[n * 512 + k] = __float2half(fc2_w[j]);
    }
}

// ---------------- relative-position bias precompute (half) ----------------
__global__ void bias_pre(const float* __restrict__ rpb, __half* __restrict__ biasMh) {
    int i = blockIdx.x * 256 + threadIdx.x;
    if (i < NHEAD * NTOK * NTOK) {
        int h = i / (NTOK * NTOK);
        int r = i % (NTOK * NTOK);
        int n = r / NTOK, m = r % NTOK;
        int ridx = (n / WS - m / WS + WS - 1) * (2 * WS - 1) + (n % WS - m % WS + WS - 1);
        biasMh[i] = __float2half(rpb[ridx * NHEAD + h]);
    }
}

// ============ fused LN + GEMM (K=128); LN stage aliased into Bs region ============
#define DSMEM_LNGEMM (34816 * 2)
template<int NCHUNKS, bool GATHER, bool DOGELU>
__global__ void __launch_bounds__(256, 2)
ln_gemm(const float* __restrict__ X, const __half* __restrict__ Bt,
        const float* __restrict__ bias, const float* __restrict__ lng,
        const float* __restrict__ lnb, __half* __restrict__ C) {
    extern __shared__ char dyn[];
    __half (*As)[136] = (__half(*)[136])dyn;
    __half (*Bs)[136] = (__half(*)[136])(dyn + 34816);
    float (*stage)[128] = (float(*)[128])(dyn + 34816);   // aliases Bs (dead before GEMM)

    const int tid = threadIdx.x;
    const int lane = tid & 31, wid = tid >> 5;
    const int m0 = blockIdx.x * 128;
    const int NT = NCHUNKS * 128;

    for (int rs = 0; rs < 128; rs += 32) {
        #pragma unroll
        for (int t = 0; t < 4; t++) {
            int i = tid + t * 256;
            int row = i >> 5;
            int c4 = (i & 31) * 4;
            int R = m0 + rs + row;
            long srow;
            if (GATHER) {
                int bi = R / (NWIN * NTOK);
                int tt = R % (NWIN * NTOK);
                int win = tt / NTOK, n = tt % NTOK;
                int hh = (win / 8) * WS + n / WS;
                int ww = (win % 8) * WS + n % WS;
                srow = (long)bi * LSEQ + ((hh + SH) % HH) * WW + (ww + SH) % WW;
            } else {
                srow = R;
            }
            *(float4*)&stage[row][c4] = *(const float4*)&X[srow * CDIM + c4];
        }
        __syncthreads();
        #pragma unroll
        for (int rr = 0; rr < 4; rr++) {
            int row = wid * 4 + rr;
            float v[4];
            #pragma unroll
            for (int t = 0; t < 4; t++) v[t] = stage[row][lane + t * 32];
            float s = v[0] + v[1] + v[2] + v[3];
            float s2 = v[0] * v[0] + v[1] * v[1] + v[2] * v[2] + v[3] * v[3];
            #pragma unroll
            for (int o = 16; o; o >>= 1) {
                s += __shfl_xor_sync(0xffffffffu, s, o);
                s2 += __shfl_xor_sync(0xffffffffu, s2, o);
            }
            float mu = s * (1.f / 128.f);
            float inv = rsqrtf(s2 * (1.f / 128.f) - mu * mu + EPS);
            #pragma unroll
            for (int t = 0; t < 4; t++) {
                int c = lane + t * 32;
                As[rs + row][c] = __float2half((v[t] - mu) * inv * lng[c] + lnb[c]);
            }
        }
        __syncthreads();
    }

    const int a_row = (lane & 7) + ((lane >> 3) & 1) * 8;
    const int a_kc  = ((lane >> 4) & 1) * 8;
    const int b_row = (lane & 7) + ((lane >> 4) & 1) * 8;
    const int b_kc  = ((lane >> 3) & 1) * 8;
    const int wm = (wid & 1) * 64;
    const int wn = (wid >> 1) * 32;
    const int g = lane >> 2, tg = lane & 3;

    for (int c = 0; c < NCHUNKS; c++) {
        #pragma unroll
        for (int t = 0; t < 8; t++) {
            int i = tid + t * 256;
            int row = i >> 4;
            int col = (i & 15) * 8;
            cp16(smem_u32(&Bs[row][col]), &Bt[(long)(c * 128 + row) * CDIM + col]);
        }
        cp_commit();
        cp_wait0();
        __syncthreads();

        float acc[4][4][4];
        #pragma unroll
        for (int i = 0; i < 4; i++)
            #pragma unroll
            for (int j = 0; j < 4; j++)
                #pragma unroll
                for (int r = 0; r < 4; r++) acc[i][j][r] = 0.f;

        #pragma unroll
        for (int it = 0; it < 8; it++) {
            const int k0 = it * 16;
            unsigned a_frag[4][4], b_frag[4][2];
            #pragma unroll
            for (int mi = 0; mi < 4; mi++)
                ldsm4(a_frag[mi], smem_u32(&As[wm + mi * 16 + a_row][k0 + a_kc]));
            #pragma unroll
            for (int n2 = 0; n2 < 2; n2++) {
                unsigned r4[4];
                ldsm4(r4, smem_u32(&Bs[wn + n2 * 16 + b_row][k0 + b_kc]));
                b_frag[2 * n2][0] = r4[0]; b_frag[2 * n2][1] = r4[1];
                b_frag[2 * n2 + 1][0] = r4[2]; b_frag[2 * n2 + 1][1] = r4[3];
            }
            #pragma unroll
            for (int mi = 0; mi < 4; mi++)
                #pragma unroll
                for (int ni = 0; ni < 4; ni++)
                    mma_fp16(acc[mi][ni], a_frag[mi], b_frag[ni]);
        }
        __syncthreads();

        #pragma unroll
        for (int mi = 0; mi < 4; mi++) {
            #pragma unroll
            for (int hf = 0; hf < 2; hf++) {
                int row = m0 + wm + mi * 16 + g + hf * 8;
                #pragma unroll
                for (int ni = 0; ni < 4; ni++) {
                    int col = c * 128 + wn + ni * 8 + 2 * tg;
                    float v0 = acc[mi][ni][hf * 2 + 0] + bias[col];
                    float v1 = acc[mi][ni][hf * 2 + 1] + bias[col + 1];
                    if (DOGELU) {
                        v0 = 0.5f * v0 * (1.0f + erff(v0 * 0.70710678118654752f));
                        v1 = 0.5f * v1 * (1.0f + erff(v1 * 0.70710678118654752f));
                    }
                    *(__half2*)&C[(long)row * NT + col] = __floats2half2_rn(v0, v1);
                }
            }
        }
    }
}

// ---------------- fp16 GEMM with cp.async pipeline (proj / fc2) ----------------
template<int N, int K, int EPI>
__global__ void __launch_bounds__(256, 2)
gemm_h(const __half* __restrict__ A, const __half* __restrict__ Bt,
       const float* __restrict__ bias, float* __restrict__ C,
       const float* __restrict__ res) {
    __shared__ __half As[3][128][24];
    __shared__ __half Bs[3][128][24];

    const int tid = threadIdx.x;
    const int lane = tid & 31, wid = tid >> 5;
    const int wm = (wid & 1) * 64;
    const int wn = (wid >> 1) * 32;
    const int m0 = blockIdx.x * 128;
    const int n0 = blockIdx.y * 128;
    const int g = lane >> 2, tg = lane & 3;

    const int fr = tid >> 1;
    const int fc = (tid & 1) * 8;

    float acc[4][4][4];
    #pragma unroll
    for (int i = 0; i < 4; i++)
        #pragma unroll
        for (int j = 0; j < 4; j++)
            #pragma unroll
            for (int r = 0; r < 4; r++) acc[i][j][r] = 0.f;

    const int NIT = K / 16;

    const int a_row = (lane & 7) + ((lane >> 3) & 1) * 8;
    const int a_kc  = ((lane >> 4) & 1) * 8;
    const int b_row = (lane & 7) + ((lane >> 4) & 1) * 8;
    const int b_kc  = ((lane >> 3) & 1) * 8;

    #pragma unroll
    for (int s = 0; s < 2; s++) {
        if (s < NIT) {
            cp16(smem_u32(&As[s][fr][fc]), &A[(long)(m0 + fr) * K + s * 16 + fc]);
            cp16(smem_u32(&Bs[s][fr][fc]), &Bt[(long)(n0 + fr) * K + s * 16 + fc]);
        }
        cp_commit();
    }

    for (int it = 0; it < NIT; it++) {
        cp_wait1();
        __syncthreads();
        {
            int s = it + 2;
            if (s < NIT) {
                int bufn = s % 3;
                cp16(smem_u32(&As[bufn][fr][fc]), &A[(long)(m0 + fr) * K + s * 16 + fc]);
                cp16(smem_u32(&Bs[bufn][fr][fc]), &Bt[(long)(n0 + fr) * K + s * 16 + fc]);
            }
            cp_commit();
        }
        const int buf = it % 3;

        unsigned a_frag[4][4];
        unsigned b_frag[4][2];
        #pragma unroll
        for (int mi = 0; mi < 4; mi++)
            ldsm4(a_frag[mi], smem_u32(&As[buf][wm + mi * 16 + a_row][a_kc]));
        #pragma unroll
        for (int n2 = 0; n2 < 2; n2++) {
            unsigned r4[4];
            ldsm4(r4, smem_u32(&Bs[buf][wn + n2 * 16 + b_row][b_kc]));
            b_frag[2 * n2][0] = r4[0]; b_frag[2 * n2][1] = r4[1];
            b_frag[2 * n2 + 1][0] = r4[2]; b_frag[2 * n2 + 1][1] = r4[3];
        }
        #pragma unroll
        for (int mi = 0; mi < 4; mi++)
            #pragma unroll
            for (int ni = 0; ni < 4; ni++)
                mma_fp16(acc[mi][ni], a_frag[mi], b_frag[ni]);
    }

    #pragma unroll
    for (int mi = 0; mi < 4; mi++) {
        #pragma unroll
        for (int hf = 0; hf < 2; hf++) {
            int row = m0 + wm + mi * 16 + g + hf * 8;
            long drow = row;
            if (EPI == 1) {
                int bi  = row / (NWIN * NTOK);
                int t   = row % (NWIN * NTOK);
                int win = t / NTOK;
                int n   = t % NTOK;
                int hh2 = (win / 8) * WS + n / WS;
                int ww2 = (win % 8) * WS + n % WS;
                drow = (long)bi * LSEQ + ((hh2 + SH) % HH) * WW + (ww2 + SH) % WW;
            }
            #pragma unroll
            for (int ni = 0; ni < 4; ni++) {
                int col = n0 + wn + ni * 8 + 2 * tg;
                float v0 = acc[mi][ni][hf * 2 + 0] + bias[col];
                float v1 = acc[mi][ni][hf * 2 + 1] + bias[col + 1];
                if (EPI == 1) {
                    float2 r2 = *(const float2*)&res[drow * N + col];
                    *(float2*)&C[drow * N + col] = make_float2(r2.x + v0, r2.y + v1);
                } else {
                    float2 r2 = *(const float2*)&res[(long)row * N + col];
                    *(float2*)&C[(long)row * N + col] = make_float2(r2.x + v0, r2.y + v1);
                }
            }
        }
    }
}

// ============ tensor-core window attention v3: 4 windows/block, 512 threads ============
// dyn smem layout: Qs[4][64][40] | Ks[4][64][40] | Vs[4][64][40] | bias[49][50] | lab[4][64]
#define ATT_TILE (64 * 40)                    // halfs per tile
#define ATT_SM_Q 0
#define ATT_SM_K (4 * ATT_TILE * 2)
#define ATT_SM_V (8 * ATT_TILE * 2)
#define ATT_SM_B (12 * ATT_TILE * 2)          // 61440
#define ATT_SM_L (ATT_SM_B + 49 * 50 * 2 + 28)  // 66368 (16B aligned)
#define DSMEM_ATT (ATT_SM_L + 4 * 64 * 4)     // 67392
__global__ void __launch_bounds__(512)
attn_mma(const __half* __restrict__ qkv,
         const __half* __restrict__ biasMh,
         __half* __restrict__ out) {
    extern __shared__ char dynA[];
    __half (*Qs)[64][40] = (__half(*)[64][40])(dynA + ATT_SM_Q);
    __half (*Ks)[64][40] = (__half(*)[64][40])(dynA + ATT_SM_K);
    __half (*Vs)[64][40] = (__half(*)[64][40])(dynA + ATT_SM_V);
    __half (*bias_s)[50] = (__half(*)[50])(dynA + ATT_SM_B);
    int (*lab)[64] = (int(*)[64])(dynA + ATT_SM_L);

    const int head = blockIdx.y;
    const int tid = threadIdx.x;
    const int gtid = tid & 127;               // tid within warp-group
    const int grp = tid >> 7;                 // window group 0..3
    const int wg = blockIdx.x * 4 + grp;      // global window
    const int lane = tid & 31;
    const int lwid = (tid >> 5) & 3;          // warp within group
    const int g = lane >> 2, tg = lane & 3;

    // zero Vs pad rows (per group)
    for (int i = gtid; i < 15 * 40; i += 128)
        Vs[grp][49 + i / 40][i % 40] = __float2half(0.f);

    // labels (per group)
    if (gtid < 64) {
        int t = gtid < NTOK ? gtid : 0;
        int wi = wg & (NWIN - 1);
        int h = (wi / 8) * WS + t / WS;
        int w = (wi % 8) * WS + t % WS;
        int rh = (h < HH - WS) ? 0 : ((h < HH - SH) ? 1 : 2);
        int rw = (w < WW - WS) ? 0 : ((w < WW - SH) ? 1 : 2);
        lab[grp][gtid] = rh * 3 + rw;
    }

    // bias table once per block (all 512 threads)
    for (int i = tid; i < NTOK * NTOK; i += 512) {
        int n = i / NTOK, m = i % NTOK;
        bias_s[n][m] = biasMh[head * NTOK * NTOK + i];
    }

    // load Q (scaled), K, V for this group's window
    const __half2 scale2 = __float2half2_rn(0.1767766952966369f);
    for (int i = gtid; i < NTOK * 4; i += 128) {
        int r = i >> 2, c8 = (i & 3) * 8;
        long base = ((long)wg * NTOK + r) * 384 + c8 + head * 32;
        uint4 qv = *(const uint4*)&qkv[base];
        __half2* qh = (__half2*)&qv;
        #pragma unroll
        for (int j = 0; j < 4; j++) qh[j] = __hmul2(qh[j], scale2);
        *(uint4*)&Qs[grp][r][c8] = qv;
        *(uint4*)&Ks[grp][r][c8] = *(const uint4*)&qkv[base + 128];
        *(uint4*)&Vs[grp][r][c8] = *(const uint4*)&qkv[base + 256];
    }
    __syncthreads();

    const int a_row = (lane & 7) + ((lane >> 3) & 1) * 8;
    const int a_kc  = ((lane >> 4) & 1) * 8;
    const int b_row = (lane & 7) + ((lane >> 4) & 1) * 8;
    const int b_kc  = ((lane >> 3) & 1) * 8;
    const int t_row = (lane & 7) + ((lane >> 3) & 1) * 8;
    const int t_col = (lane >> 4) * 8;
    const int w16 = lwid * 16;

    // ---- S = Q K^T ----
    float sa[8][4];
    #pragma unroll
    for (int i = 0; i < 8; i++)
        #pragma unroll
        for (int r = 0; r < 4; r++) sa[i][r] = 0.f;

    #pragma unroll
    for (int kc = 0; kc < 2; kc++) {
        unsigned aq[4];
        ldsm4(aq, smem_u32(&Qs[grp][w16 + a_row][kc * 16 + a_kc]));
        #pragma unroll
        for (int nt = 0; nt < 4; nt++) {
            unsigned r4[4];
            ldsm4(r4, smem_u32(&Ks[grp][nt * 16 + b_row][kc * 16 + b_kc]));
            unsigned b0[2] = {r4[0], r4[1]};
            unsigned b1[2] = {r4[2], r4[3]};
            mma_fp16(sa[2 * nt], aq, b0);
            mma_fp16(sa[2 * nt + 1], aq, b1);
        }
    }

    // ---- bias + mask ----
    const int rowA = w16 + g;
    const int rowB = w16 + g + 8;
    const int rA = rowA < NTOK ? rowA : 0;
    const int rB = rowB < NTOK ? rowB : 0;
    const int labA = lab[grp][rA], labB = lab[grp][rB];
    #pragma unroll
    for (int ni = 0; ni < 8; ni++) {
        #pragma unroll
        for (int cc = 0; cc < 2; cc++) {
            int m = 8 * ni + 2 * tg + cc;
            if (m < NTOK) {
                int lm = lab[grp][m];
                sa[ni][cc]     += __half2float(bias_s[rA][m]) + (labA != lm ? -100.f : 0.f);
                sa[ni][cc + 2] += __half2float(bias_s[rB][m]) + (labB != lm ? -100.f : 0.f);
            } else {
                sa[ni][cc] = -1e30f;
                sa[ni][cc + 2] = -1e30f;
            }
        }
    }

    // ---- softmax ----
    float mxA = -1e30f, mxB = -1e30f;
    #pragma unroll
    for (int ni = 0; ni < 8; ni++) {
        mxA = fmaxf(mxA, fmaxf(sa[ni][0], sa[ni][1]));
        mxB = fmaxf(mxB, fmaxf(sa[ni][2], sa[ni][3]));
    }
    #pragma unroll
    for (int o = 1; o <= 2; o <<= 1) {
        mxA = fmaxf(mxA, __shfl_xor_sync(0xffffffffu, mxA, o));
        mxB = fmaxf(mxB, __shfl_xor_sync(0xffffffffu, mxB, o));
    }
    float smA = 0.f, smB = 0.f;
    #pragma unroll
    for (int ni = 0; ni < 8; ni++) {
        sa[ni][0] = __expf(sa[ni][0] - mxA); smA += sa[ni][0];
        sa[ni][1] = __expf(sa[ni][1] - mxA); smA += sa[ni][1];
        sa[ni][2] = __expf(sa[ni][2] - mxB); smB += sa[ni][2];
        sa[ni][3] = __expf(sa[ni][3] - mxB); smB += sa[ni][3];
    }
    #pragma unroll
    for (int o = 1; o <= 2; o <<= 1) {
        smA += __shfl_xor_sync(0xffffffffu, smA, o);
        smB += __shfl_xor_sync(0xffffffffu, smB, o);
    }
    const float ivA = 1.0f / smA, ivB = 1.0f / smB;

    // ---- pack P ----
    unsigned ap[4][4];
    #pragma unroll
    for (int kc = 0; kc < 4; kc++) {
        ap[kc][0] = h2_as_u32(__floats2half2_rn(sa[2 * kc][0] * ivA, sa[2 * kc][1] * ivA));
        ap[kc][1] = h2_as_u32(__floats2half2_rn(sa[2 * kc][2] * ivB, sa[2 * kc][3] * ivB));
        ap[kc][2] = h2_as_u32(__floats2half2_rn(sa[2 * kc + 1][0] * ivA, sa[2 * kc + 1][1] * ivA));
        ap[kc][3] = h2_as_u32(__floats2half2_rn(sa[2 * kc + 1][2] * ivB, sa[2 * kc + 1][3] * ivB));
    }

    // ---- O = P V ----
    float oa[4][4];
    #pragma unroll
    for (int i = 0; i < 4; i++)
        #pragma unroll
        for (int r = 0; r < 4; r++) oa[i][r] = 0.f;

    #pragma unroll
    for (int kc = 0; kc < 4; kc++) {
        #pragma unroll
        for (int nt = 0; nt < 2; nt++) {
            unsigned r4[4];
            ldsm4t(r4, smem_u32(&Vs[grp][kc * 16 + t_row][nt * 16 + t_col]));
            unsigned b0[2] = {r4[0], r4[1]};
            unsigned b1[2] = {r4[2], r4[3]};
            mma_fp16(oa[2 * nt], ap[kc], b0);
            mma_fp16(oa[2 * nt + 1], ap[kc], b1);
        }
    }

    // ---- store ----
    #pragma unroll
    for (int ni = 0; ni < 4; ni++) {
        int d0 = 8 * ni + 2 * tg;
        if (rowA < NTOK)
            *(__half2*)&out[((long)wg * NTOK + rowA) * CDIM + head * 32 + d0] =
                __floats2half2_rn(oa[ni][0], oa[ni][1]);
        if (rowB < NTOK)
            *(__half2*)&out[((long)wg * NTOK + rowB) * CDIM + head * 32 + d0] =
                __floats2half2_rn(oa[ni][2], oa[ni][3]);
    }
}

// ---------------- launch ----------------
extern "C" void kernel_launch(void* const* d_in, const int* in_sizes, int n_in,
                              void* d_out, int out_size) {
    const float* x      = (const float*)d_in[0];
    const float* qkv_w  = (const float*)d_in[1];
    const float* qkv_b  = (const float*)d_in[2];
    const float* proj_w = (const float*)d_in[3];
    const float* proj_b = (const float*)d_in[4];
    const float* rpb    = (const float*)d_in[5];
    const float* n1g    = (const float*)d_in[6];
    const float* n1b    = (const float*)d_in[7];
    const float* n2g    = (const float*)d_in[8];
    const float* n2b    = (const float*)d_in[9];
    const float* fc1_w  = (const float*)d_in[10];
    const float* fc1_b  = (const float*)d_in[11];
    const float* fc2_w  = (const float*)d_in[12];
    const float* fc2_b  = (const float*)d_in[13];
    float* out = (float*)d_out;

    __half *qkvh, *atth, *hidh, *wqkv, *wproj, *wfc1, *wfc2, *biasMh;
    cudaGetSymbolAddress((void**)&qkvh, g_qkvh);
    cudaGetSymbolAddress((void**)&atth, g_atth);
    cudaGetSymbolAddress((void**)&hidh, g_hidh);
    cudaGetSymbolAddress((void**)&wqkv, g_wqkv);
    cudaGetSymbolAddress((void**)&wproj, g_wproj);
    cudaGetSymbolAddress((void**)&wfc1, g_wfc1);
    cudaGetSymbolAddress((void**)&wfc2, g_wfc2);
    cudaGetSymbolAddress((void**)&biasMh, g_biasMh);

    static bool attr_set = false;
    if (!attr_set) {
        cudaFuncSetAttribute(ln_gemm<3, true, false>,
                             cudaFuncAttributeMaxDynamicSharedMemorySize, DSMEM_LNGEMM);
        cudaFuncSetAttribute(ln_gemm<4, false, true>,
                             cudaFuncAttributeMaxDynamicSharedMemorySize, DSMEM_LNGEMM);
        cudaFuncSetAttribute(attn_mma,
                             cudaFuncAttributeMaxDynamicSharedMemorySize, DSMEM_ATT);
        attr_set = true;
    }

    convert_all<<<768, 256>>>(qkv_w, proj_w, fc1_w, fc2_w, wqkv, wproj, wfc1, wfc2);
    bias_pre<<<(NHEAD * NTOK * NTOK + 255) / 256, 256>>>(rpb, biasMh);

    ln_gemm<3, true, false><<<MROWS / 128, 256, DSMEM_LNGEMM>>>(
        x, wqkv, qkv_b, n1g, n1b, qkvh);
    attn_mma<<<dim3(BIMG * NWIN / 4, NHEAD), 512, DSMEM_ATT>>>(qkvh, biasMh, atth);
    gemm_h<128, 128, 1><<<dim3(MROWS / 128, 1), 256>>>(atth, wproj, proj_b, out, x);
    ln_gemm<4, false, true><<<MROWS / 128, 256, DSMEM_LNGEMM>>>(
        out, wfc1, fc1_b, n2g, n2b, hidh);
    gemm_h<128, 512, 3><<<dim3(MROWS / 128, 1), 256>>>(hidh, wfc2, fc2_b, out, out);
}

// round 12
// speedup vs baseline: 6.2912x; 1.0331x over previous
#include <cuda_runtime.h>
#include <cuda_fp16.h>
#include <cstdint>
#include <math.h>

#define HH 56
#define WW 56
#define WS 7
#define SH 3
#define NHEAD 4
#define HD 32
#define CDIM 128
#define NTOK 49
#define NWIN 64
#define BIMG 64
#define MROWS (BIMG * NWIN * NTOK)   // 200704
#define LSEQ (HH * WW)
#define EPS 1e-5f

// ---------------- scratch ----------------
__device__ __half g_qkvh[(size_t)MROWS * 3 * CDIM];  // reused as f32 ywin after attn
__device__ __half g_atth[(size_t)MROWS * CDIM];
__device__ __half g_hidh[(size_t)MROWS * 512];
__device__ __half g_wqkv[384 * 128];
__device__ __half g_wproj[128 * 128];
__device__ __half g_wfc1[512 * 128];
__device__ __half g_wfc2[128 * 512];
__device__ __half g_biasMh[NHEAD * NTOK * NTOK];

// ---------------- ptx helpers ----------------
__device__ __forceinline__ unsigned smem_u32(const void* p) {
    return (unsigned)__cvta_generic_to_shared(p);
}
__device__ __forceinline__ unsigned h2_as_u32(__half2 h) {
    return *(unsigned*)&h;
}
__device__ __forceinline__ void cp16(unsigned dst, const void* src) {
    asm volatile("cp.async.cg.shared.global [%0], [%1], 16;" :: "r"(dst), "l"(src));
}
__device__ __forceinline__ void cp_commit() { asm volatile("cp.async.commit_group;"); }
__device__ __forceinline__ void cp_wait1() { asm volatile("cp.async.wait_group 1;"); }
__device__ __forceinline__ void cp_wait0() { asm volatile("cp.async.wait_group 0;"); }

__device__ __forceinline__ void ldsm4(unsigned* r, unsigned addr) {
    asm volatile("ldmatrix.sync.aligned.m8n8.x4.shared.b16 {%0,%1,%2,%3}, [%4];"
                 : "=r"(r[0]), "=r"(r[1]), "=r"(r[2]), "=r"(r[3]) : "r"(addr));
}
__device__ __forceinline__ void ldsm4t(unsigned* r, unsigned addr) {
    asm volatile("ldmatrix.sync.aligned.m8n8.x4.trans.shared.b16 {%0,%1,%2,%3}, [%4];"
                 : "=r"(r[0]), "=r"(r[1]), "=r"(r[2]), "=r"(r[3]) : "r"(addr));
}
__device__ __forceinline__ void mma_fp16(float* d, const unsigned* a, const unsigned* b) {
    asm volatile(
        "mma.sync.aligned.m16n8k16.row.col.f32.f16.f16.f32 "
        "{%0,%1,%2,%3}, {%4,%5,%6,%7}, {%8,%9}, {%0,%1,%2,%3};\n"
        : "+f"(d[0]), "+f"(d[1]), "+f"(d[2]), "+f"(d[3])
        : "r"(a[0]), "r"(a[1]), "r"(a[2]), "r"(a[3]), "r"(b[0]), "r"(b[1]));
}

// ---------------- fused weight convert + transpose ----------------
__global__ void convert_all(const float* __restrict__ qkv_w, const float* __restrict__ proj_w,
                            const float* __restrict__ fc1_w, const float* __restrict__ fc2_w,
                            __half* __restrict__ wqkv, __half* __restrict__ wproj,
                            __half* __restrict__ wfc1, __half* __restrict__ wfc2) {
    int i = blockIdx.x * 256 + threadIdx.x;
    if (i < 49152) {
        int k = i / 384, n = i % 384;
        wqkv[n * 128 + k] = __float2half(qkv_w[i]);
    } else if (i < 65536) {
        int j = i - 49152;
        int k = j / 128, n = j % 128;
        wproj[n * 128 + k] = __float2half(proj_w[j]);
    } else if (i < 131072) {
        int j = i - 65536;
        int k = j / 512, n = j % 512;
        wfc1[n * 128 + k] = __float2half(fc1_w[j]);
    } else if (i < 196608) {
        int j = i - 131072;
        int k = j / 128, n = j % 128;
        wfc2[n * 512 + k] = __float2half(fc2_w[j]);
    }
}

// ---------------- relative-position bias precompute (half) ----------------
__global__ void bias_pre(const float* __restrict__ rpb, __half* __restrict__ biasMh) {
    int i = blockIdx.x * 256 + threadIdx.x;
    if (i < NHEAD * NTOK * NTOK) {
        int h = i / (NTOK * NTOK);
        int r = i % (NTOK * NTOK);
        int n = r / NTOK, m = r % NTOK;
        int ridx = (n / WS - m / WS + WS - 1) * (2 * WS - 1) + (n % WS - m % WS + WS - 1);
        biasMh[i] = __float2half(rpb[ridx * NHEAD + h]);
    }
}

// ============ fused LN + GEMM (qkv path) ============
#define DSMEM_LNGEMM (34816 * 2)
template<int NCHUNKS, bool GATHER, bool DOGELU>
__global__ void __launch_bounds__(256, 2)
ln_gemm(const float* __restrict__ X, const __half* __restrict__ Bt,
        const float* __restrict__ bias, const float* __restrict__ lng,
        const float* __restrict__ lnb, __half* __restrict__ C) {
    extern __shared__ char dyn[];
    __half (*As)[136] = (__half(*)[136])dyn;
    __half (*Bs)[136] = (__half(*)[136])(dyn + 34816);
    float (*stage)[128] = (float(*)[128])(dyn + 34816);

    const int tid = threadIdx.x;
    const int lane = tid & 31, wid = tid >> 5;
    const int m0 = blockIdx.x * 128;
    const int NT = NCHUNKS * 128;

    for (int rs = 0; rs < 128; rs += 32) {
        #pragma unroll
        for (int t = 0; t < 4; t++) {
            int i = tid + t * 256;
            int row = i >> 5;
            int c4 = (i & 31) * 4;
            int R = m0 + rs + row;
            long srow;
            if (GATHER) {
                int bi = R / (NWIN * NTOK);
                int tt = R % (NWIN * NTOK);
                int win = tt / NTOK, n = tt % NTOK;
                int hh = (win / 8) * WS + n / WS;
                int ww = (win % 8) * WS + n % WS;
                srow = (long)bi * LSEQ + ((hh + SH) % HH) * WW + (ww + SH) % WW;
            } else {
                srow = R;
            }
            *(float4*)&stage[row][c4] = *(const float4*)&X[srow * CDIM + c4];
        }
        __syncthreads();
        #pragma unroll
        for (int rr = 0; rr < 4; rr++) {
            int row = wid * 4 + rr;
            float v[4];
            #pragma unroll
            for (int t = 0; t < 4; t++) v[t] = stage[row][lane + t * 32];
            float s = v[0] + v[1] + v[2] + v[3];
            float s2 = v[0] * v[0] + v[1] * v[1] + v[2] * v[2] + v[3] * v[3];
            #pragma unroll
            for (int o = 16; o; o >>= 1) {
                s += __shfl_xor_sync(0xffffffffu, s, o);
                s2 += __shfl_xor_sync(0xffffffffu, s2, o);
            }
            float mu = s * (1.f / 128.f);
            float inv = rsqrtf(s2 * (1.f / 128.f) - mu * mu + EPS);
            #pragma unroll
            for (int t = 0; t < 4; t++) {
                int c = lane + t * 32;
                As[rs + row][c] = __float2half((v[t] - mu) * inv * lng[c] + lnb[c]);
            }
        }
        __syncthreads();
    }

    const int a_row = (lane & 7) + ((lane >> 3) & 1) * 8;
    const int a_kc  = ((lane >> 4) & 1) * 8;
    const int b_row = (lane & 7) + ((lane >> 4) & 1) * 8;
    const int b_kc  = ((lane >> 3) & 1) * 8;
    const int wm = (wid & 1) * 64;
    const int wn = (wid >> 1) * 32;
    const int g = lane >> 2, tg = lane & 3;

    for (int c = 0; c < NCHUNKS; c++) {
        #pragma unroll
        for (int t = 0; t < 8; t++) {
            int i = tid + t * 256;
            int row = i >> 4;
            int col = (i & 15) * 8;
            cp16(smem_u32(&Bs[row][col]), &Bt[(long)(c * 128 + row) * CDIM + col]);
        }
        cp_commit();
        cp_wait0();
        __syncthreads();

        float acc[4][4][4];
        #pragma unroll
        for (int i = 0; i < 4; i++)
            #pragma unroll
            for (int j = 0; j < 4; j++)
                #pragma unroll
                for (int r = 0; r < 4; r++) acc[i][j][r] = 0.f;

        #pragma unroll
        for (int it = 0; it < 8; it++) {
            const int k0 = it * 16;
            unsigned a_frag[4][4], b_frag[4][2];
            #pragma unroll
            for (int mi = 0; mi < 4; mi++)
                ldsm4(a_frag[mi], smem_u32(&As[wm + mi * 16 + a_row][k0 + a_kc]));
            #pragma unroll
            for (int n2 = 0; n2 < 2; n2++) {
                unsigned r4[4];
                ldsm4(r4, smem_u32(&Bs[wn + n2 * 16 + b_row][k0 + b_kc]));
                b_frag[2 * n2][0] = r4[0]; b_frag[2 * n2][1] = r4[1];
                b_frag[2 * n2 + 1][0] = r4[2]; b_frag[2 * n2 + 1][1] = r4[3];
            }
            #pragma unroll
            for (int mi = 0; mi < 4; mi++)
                #pragma unroll
                for (int ni = 0; ni < 4; ni++)
                    mma_fp16(acc[mi][ni], a_frag[mi], b_frag[ni]);
        }
        __syncthreads();

        #pragma unroll
        for (int mi = 0; mi < 4; mi++) {
            #pragma unroll
            for (int hf = 0; hf < 2; hf++) {
                int row = m0 + wm + mi * 16 + g + hf * 8;
                #pragma unroll
                for (int ni = 0; ni < 4; ni++) {
                    int col = c * 128 + wn + ni * 8 + 2 * tg;
                    float v0 = acc[mi][ni][hf * 2 + 0] + bias[col];
                    float v1 = acc[mi][ni][hf * 2 + 1] + bias[col + 1];
                    if (DOGELU) {
                        v0 = 0.5f * v0 * (1.0f + erff(v0 * 0.70710678118654752f));
                        v1 = 0.5f * v1 * (1.0f + erff(v1 * 0.70710678118654752f));
                    }
                    *(__half2*)&C[(long)row * NT + col] = __floats2half2_rn(v0, v1);
                }
            }
        }
    }
}

// ============ fused proj + residual + LN2 + fc1(+GELU) ============
// One block = 128 window-order rows. ywin (f32, window order) + hidh (half) out.
#define DSMEM_PLF (34816 * 2 + 4096)
__global__ void __launch_bounds__(256, 2)
proj_ln_fc1(const __half* __restrict__ atth, const __half* __restrict__ wproj,
            const float* __restrict__ pbias, const float* __restrict__ x,
            const float* __restrict__ lng, const float* __restrict__ lnb,
            const __half* __restrict__ wfc1, const float* __restrict__ fbias,
            float* __restrict__ ywin, __half* __restrict__ hidh) {
    extern __shared__ char dyn[];
    __half (*As)[136] = (__half(*)[136])dyn;
    __half (*Bs)[136] = (__half(*)[136])(dyn + 34816);
    float (*redS)[128] = (float(*)[128])(dyn + 69632);
    float (*redQ)[128] = (float(*)[128])(dyn + 69632 + 2048);

    const int tid = threadIdx.x;
    const int lane = tid & 31, wid = tid >> 5;
    const int m0 = blockIdx.x * 128;

    const int a_row = (lane & 7) + ((lane >> 3) & 1) * 8;
    const int a_kc  = ((lane >> 4) & 1) * 8;
    const int b_row = (lane & 7) + ((lane >> 4) & 1) * 8;
    const int b_kc  = ((lane >> 3) & 1) * 8;
    const int wm = (wid & 1) * 64;
    const int wn = (wid >> 1) * 32;
    const int g = lane >> 2, tg = lane & 3;

    // load atth tile (As) + proj weights (Bs)
    #pragma unroll
    for (int t = 0; t < 8; t++) {
        int i = tid + t * 256;
        int row = i >> 4;
        int col = (i & 15) * 8;
        cp16(smem_u32(&As[row][col]), &atth[(long)(m0 + row) * CDIM + col]);
        cp16(smem_u32(&Bs[row][col]), &wproj[row * CDIM + col]);
    }
    cp_commit();
    cp_wait0();
    __syncthreads();

    // proj GEMM (K=128)
    float acc[4][4][4];
    #pragma unroll
    for (int i = 0; i < 4; i++)
        #pragma unroll
        for (int j = 0; j < 4; j++)
            #pragma unroll
            for (int r = 0; r < 4; r++) acc[i][j][r] = 0.f;

    #pragma unroll
    for (int it = 0; it < 8; it++) {
        const int k0 = it * 16;
        unsigned a_frag[4][4], b_frag[4][2];
        #pragma unroll
        for (int mi = 0; mi < 4; mi++)
            ldsm4(a_frag[mi], smem_u32(&As[wm + mi * 16 + a_row][k0 + a_kc]));
        #pragma unroll
        for (int n2 = 0; n2 < 2; n2++) {
            unsigned r4[4];
            ldsm4(r4, smem_u32(&Bs[wn + n2 * 16 + b_row][k0 + b_kc]));
            b_frag[2 * n2][0] = r4[0]; b_frag[2 * n2][1] = r4[1];
            b_frag[2 * n2 + 1][0] = r4[2]; b_frag[2 * n2 + 1][1] = r4[3];
        }
        #pragma unroll
        for (int mi = 0; mi < 4; mi++)
            #pragma unroll
            for (int ni = 0; ni < 4; ni++)
                mma_fp16(acc[mi][ni], a_frag[mi], b_frag[ni]);
    }
    __syncthreads();   // all smem reads done; As/Bs now reusable

    // epilogue: y = acc + pbias + x[gather]; write ywin; LN partial sums
    #pragma unroll
    for (int mi = 0; mi < 4; mi++) {
        #pragma unroll
        for (int hf = 0; hf < 2; hf++) {
            int lrow = wm + mi * 16 + g + hf * 8;
            int R = m0 + lrow;
            int bi = R / (NWIN * NTOK);
            int tt = R % (NWIN * NTOK);
            int win = tt / NTOK, n = tt % NTOK;
            int hh = (win / 8) * WS + n / WS;
            int ww = (win % 8) * WS + n % WS;
            long srow = (long)bi * LSEQ + ((hh + SH) % HH) * WW + (ww + SH) % WW;

            float s = 0.f, s2 = 0.f;
            #pragma unroll
            for (int ni = 0; ni < 4; ni++) {
                int col = wn + ni * 8 + 2 * tg;
                float2 xr = *(const float2*)&x[srow * CDIM + col];
                float v0 = acc[mi][ni][hf * 2 + 0] + pbias[col] + xr.x;
                float v1 = acc[mi][ni][hf * 2 + 1] + pbias[col + 1] + xr.y;
                acc[mi][ni][hf * 2 + 0] = v0;
                acc[mi][ni][hf * 2 + 1] = v1;
                *(float2*)&ywin[(long)R * CDIM + col] = make_float2(v0, v1);
                s += v0 + v1;
                s2 += v0 * v0 + v1 * v1;
            }
            // reduce over tg quad (lanes xor 1,2 share g)
            s += __shfl_xor_sync(0xffffffffu, s, 1);
            s += __shfl_xor_sync(0xffffffffu, s, 2);
            s2 += __shfl_xor_sync(0xffffffffu, s2, 1);
            s2 += __shfl_xor_sync(0xffffffffu, s2, 2);
            if (tg == 0) {
                redS[wid >> 1][lrow] = s;
                redQ[wid >> 1][lrow] = s2;
            }
        }
    }
    __syncthreads();

    // normalize -> As (half)
    #pragma unroll
    for (int mi = 0; mi < 4; mi++) {
        #pragma unroll
        for (int hf = 0; hf < 2; hf++) {
            int lrow = wm + mi * 16 + g + hf * 8;
            float s = redS[0][lrow] + redS[1][lrow] + redS[2][lrow] + redS[3][lrow];
            float s2 = redQ[0][lrow] + redQ[1][lrow] + redQ[2][lrow] + redQ[3][lrow];
            float mu = s * (1.f / 128.f);
            float inv = rsqrtf(s2 * (1.f / 128.f) - mu * mu + EPS);
            #pragma unroll
            for (int ni = 0; ni < 4; ni++) {
                int col = wn + ni * 8 + 2 * tg;
                float v0 = (acc[mi][ni][hf * 2 + 0] - mu) * inv * lng[col] + lnb[col];
                float v1 = (acc[mi][ni][hf * 2 + 1] - mu) * inv * lng[col + 1] + lnb[col + 1];
                *(__half2*)&As[lrow][col] = __floats2half2_rn(v0, v1);
            }
        }
    }
    __syncthreads();

    // fc1: 4 chunks of 128 cols, GELU, write hidh (window order)
    for (int c = 0; c < 4; c++) {
        #pragma unroll
        for (int t = 0; t < 8; t++) {
            int i = tid + t * 256;
            int row = i >> 4;
            int col = (i & 15) * 8;
            cp16(smem_u32(&Bs[row][col]), &wfc1[(long)(c * 128 + row) * CDIM + col]);
        }
        cp_commit();
        cp_wait0();
        __syncthreads();

        float fa[4][4][4];
        #pragma unroll
        for (int i = 0; i < 4; i++)
            #pragma unroll
            for (int j = 0; j < 4; j++)
                #pragma unroll
                for (int r = 0; r < 4; r++) fa[i][j][r] = 0.f;

        #pragma unroll
        for (int it = 0; it < 8; it++) {
            const int k0 = it * 16;
            unsigned a_frag[4][4], b_frag[4][2];
            #pragma unroll
            for (int mi = 0; mi < 4; mi++)
                ldsm4(a_frag[mi], smem_u32(&As[wm + mi * 16 + a_row][k0 + a_kc]));
            #pragma unroll
            for (int n2 = 0; n2 < 2; n2++) {
                unsigned r4[4];
                ldsm4(r4, smem_u32(&Bs[wn + n2 * 16 + b_row][k0 + b_kc]));
                b_frag[2 * n2][0] = r4[0]; b_frag[2 * n2][1] = r4[1];
                b_frag[2 * n2 + 1][0] = r4[2]; b_frag[2 * n2 + 1][1] = r4[3];
            }
            #pragma unroll
            for (int mi = 0; mi < 4; mi++)
                #pragma unroll
                for (int ni = 0; ni < 4; ni++)
                    mma_fp16(fa[mi][ni], a_frag[mi], b_frag[ni]);
        }
        __syncthreads();

        #pragma unroll
        for (int mi = 0; mi < 4; mi++) {
            #pragma unroll
            for (int hf = 0; hf < 2; hf++) {
                int row = m0 + wm + mi * 16 + g + hf * 8;
                #pragma unroll
                for (int ni = 0; ni < 4; ni++) {
                    int col = c * 128 + wn + ni * 8 + 2 * tg;
                    float v0 = fa[mi][ni][hf * 2 + 0] + fbias[col];
                    float v1 = fa[mi][ni][hf * 2 + 1] + fbias[col + 1];
                    v0 = 0.5f * v0 * (1.0f + erff(v0 * 0.70710678118654752f));
                    v1 = 0.5f * v1 * (1.0f + erff(v1 * 0.70710678118654752f));
                    *(__half2*)&hidh[(long)row * 512 + col] = __floats2half2_rn(v0, v1);
                }
            }
        }
    }
}

// ---------------- fc2: K=512 GEMM, residual from ywin (window row), scatter out ----------------
__global__ void __launch_bounds__(256, 2)
gemm_fc2(const __half* __restrict__ A, const __half* __restrict__ Bt,
         const float* __restrict__ bias, float* __restrict__ C,
         const float* __restrict__ ywin) {
    __shared__ __half As[3][128][24];
    __shared__ __half Bs[3][128][24];

    const int tid = threadIdx.x;
    const int lane = tid & 31, wid = tid >> 5;
    const int wm = (wid & 1) * 64;
    const int wn = (wid >> 1) * 32;
    const int m0 = blockIdx.x * 128;
    const int g = lane >> 2, tg = lane & 3;

    const int fr = tid >> 1;
    const int fc = (tid & 1) * 8;

    float acc[4][4][4];
    #pragma unroll
    for (int i = 0; i < 4; i++)
        #pragma unroll
        for (int j = 0; j < 4; j++)
            #pragma unroll
            for (int r = 0; r < 4; r++) acc[i][j][r] = 0.f;

    const int a_row = (lane & 7) + ((lane >> 3) & 1) * 8;
    const int a_kc  = ((lane >> 4) & 1) * 8;
    const int b_row = (lane & 7) + ((lane >> 4) & 1) * 8;
    const int b_kc  = ((lane >> 3) & 1) * 8;

    #pragma unroll
    for (int s = 0; s < 2; s++) {
        cp16(smem_u32(&As[s][fr][fc]), &A[(long)(m0 + fr) * 512 + s * 16 + fc]);
        cp16(smem_u32(&Bs[s][fr][fc]), &Bt[(long)fr * 512 + s * 16 + fc]);
        cp_commit();
    }

    for (int it = 0; it < 32; it++) {
        cp_wait1();
        __syncthreads();
        {
            int s = it + 2;
            if (s < 32) {
                int bufn = s % 3;
                cp16(smem_u32(&As[bufn][fr][fc]), &A[(long)(m0 + fr) * 512 + s * 16 + fc]);
                cp16(smem_u32(&Bs[bufn][fr][fc]), &Bt[(long)fr * 512 + s * 16 + fc]);
            }
            cp_commit();
        }
        const int buf = it % 3;

        unsigned a_frag[4][4];
        unsigned b_frag[4][2];
        #pragma unroll
        for (int mi = 0; mi < 4; mi++)
            ldsm4(a_frag[mi], smem_u32(&As[buf][wm + mi * 16 + a_row][a_kc]));
        #pragma unroll
        for (int n2 = 0; n2 < 2; n2++) {
            unsigned r4[4];
            ldsm4(r4, smem_u32(&Bs[buf][wn + n2 * 16 + b_row][b_kc]));
            b_frag[2 * n2][0] = r4[0]; b_frag[2 * n2][1] = r4[1];
            b_frag[2 * n2 + 1][0] = r4[2]; b_frag[2 * n2 + 1][1] = r4[3];
        }
        #pragma unroll
        for (int mi = 0; mi < 4; mi++)
            #pragma unroll
            for (int ni = 0; ni < 4; ni++)
                mma_fp16(acc[mi][ni], a_frag[mi], b_frag[ni]);
    }

    #pragma unroll
    for (int mi = 0; mi < 4; mi++) {
        #pragma unroll
        for (int hf = 0; hf < 2; hf++) {
            int row = m0 + wm + mi * 16 + g + hf * 8;
            int bi  = row / (NWIN * NTOK);
            int t   = row % (NWIN * NTOK);
            int win = t / NTOK;
            int n   = t % NTOK;
            int hh2 = (win / 8) * WS + n / WS;
            int ww2 = (win % 8) * WS + n % WS;
            long drow = (long)bi * LSEQ + ((hh2 + SH) % HH) * WW + (ww2 + SH) % WW;
            #pragma unroll
            for (int ni = 0; ni < 4; ni++) {
                int col = wn + ni * 8 + 2 * tg;
                float v0 = acc[mi][ni][hf * 2 + 0] + bias[col];
                float v1 = acc[mi][ni][hf * 2 + 1] + bias[col + 1];
                float2 r2 = *(const float2*)&ywin[(long)row * CDIM + col];
                *(float2*)&C[drow * CDIM + col] = make_float2(r2.x + v0, r2.y + v1);
            }
        }
    }
}

// ============ tensor-core window attention v4 ============
#define ATT_TILE (64 * 40)
#define ATT_SM_Q 0
#define ATT_SM_K (4 * ATT_TILE * 2)
#define ATT_SM_V (8 * ATT_TILE * 2)
#define ATT_SM_B (12 * ATT_TILE * 2)
#define ATT_SM_L (ATT_SM_B + 49 * 50 * 2 + 28)
#define DSMEM_ATT (ATT_SM_L + 4 * 64 * 4)
__global__ void __launch_bounds__(512)
attn_mma(const __half* __restrict__ qkv,
         const __half* __restrict__ biasMh,
         __half* __restrict__ out) {
    extern __shared__ char dynA[];
    __half (*Qs)[64][40] = (__half(*)[64][40])(dynA + ATT_SM_Q);
    __half (*Ks)[64][40] = (__half(*)[64][40])(dynA + ATT_SM_K);
    __half (*Vs)[64][40] = (__half(*)[64][40])(dynA + ATT_SM_V);
    __half (*bias_s)[50] = (__half(*)[50])(dynA + ATT_SM_B);
    int (*lab)[64] = (int(*)[64])(dynA + ATT_SM_L);

    const int head = blockIdx.y;
    const int tid = threadIdx.x;
    const int gtid = tid & 127;
    const int grp = tid >> 7;
    const int wg = blockIdx.x * 4 + grp;
    const int lane = tid & 31;
    const int lwid = (tid >> 5) & 3;
    const int g = lane >> 2, tg = lane & 3;

    const int wi = wg & (NWIN - 1);
    const bool need_mask = ((wi >> 3) == 7) || ((wi & 7) == 7);

    for (int i = gtid; i < 15 * 40; i += 128)
        Vs[grp][49 + i / 40][i % 40] = __float2half(0.f);

    if (need_mask && gtid < 64) {
        int t = gtid < NTOK ? gtid : 0;
        int h = (wi / 8) * WS + t / WS;
        int w = (wi % 8) * WS + t % WS;
        int rh = (h < HH - WS) ? 0 : ((h < HH - SH) ? 1 : 2);
        int rw = (w < WW - WS) ? 0 : ((w < WW - SH) ? 1 : 2);
        lab[grp][gtid] = rh * 3 + rw;
    }

    for (int i = tid; i < NTOK * NTOK; i += 512) {
        int n = i / NTOK, m = i % NTOK;
        bias_s[n][m] = biasMh[head * NTOK * NTOK + i];
    }

    const __half2 scale2 = __float2half2_rn(0.1767766952966369f);
    for (int i = gtid; i < NTOK * 4; i += 128) {
        int r = i >> 2, c8 = (i & 3) * 8;
        long base = ((long)wg * NTOK + r) * 384 + c8 + head * 32;
        uint4 qv = *(const uint4*)&qkv[base];
        __half2* qh = (__half2*)&qv;
        #pragma unroll
        for (int j = 0; j < 4; j++) qh[j] = __hmul2(qh[j], scale2);
        *(uint4*)&Qs[grp][r][c8] = qv;
        *(uint4*)&Ks[grp][r][c8] = *(const uint4*)&qkv[base + 128];
        *(uint4*)&Vs[grp][r][c8] = *(const uint4*)&qkv[base + 256];
    }
    __syncthreads();

    const int a_row = (lane & 7) + ((lane >> 3) & 1) * 8;
    const int a_kc  = ((lane >> 4) & 1) * 8;
    const int b_row = (lane & 7) + ((lane >> 4) & 1) * 8;
    const int b_kc  = ((lane >> 3) & 1) * 8;
    const int t_row = (lane & 7) + ((lane >> 3) & 1) * 8;
    const int t_col = (lane >> 4) * 8;
    const int w16 = lwid * 16;

    // ---- S = Q K^T ----
    float sa[8][4];
    #pragma unroll
    for (int i = 0; i < 8; i++)
        #pragma unroll
        for (int r = 0; r < 4; r++) sa[i][r] = 0.f;

    #pragma unroll
    for (int kc = 0; kc < 2; kc++) {
        unsigned aq[4];
        ldsm4(aq, smem_u32(&Qs[grp][w16 + a_row][kc * 16 + a_kc]));
        #pragma unroll
        for (int nt = 0; nt < 4; nt++) {
            unsigned r4[4];
            ldsm4(r4, smem_u32(&Ks[grp][nt * 16 + b_row][kc * 16 + b_kc]));
            unsigned b0[2] = {r4[0], r4[1]};
            unsigned b1[2] = {r4[2], r4[3]};
            mma_fp16(sa[2 * nt], aq, b0);
            mma_fp16(sa[2 * nt + 1], aq, b1);
        }
    }

    // ---- bias (half2 pair loads) + mask (only boundary windows) ----
    const int rowA = w16 + g;
    const int rowB = w16 + g + 8;
    const int rA = rowA < NTOK ? rowA : 0;
    const int rB = rowB < NTOK ? rowB : 0;
    #pragma unroll
    for (int ni = 0; ni < 6; ni++) {
        float2 fA = __half22float2(*(__half2*)&bias_s[rA][8 * ni + 2 * tg]);
        float2 fB = __half22float2(*(__half2*)&bias_s[rB][8 * ni + 2 * tg]);
        sa[ni][0] += fA.x; sa[ni][1] += fA.y;
        sa[ni][2] += fB.x; sa[ni][3] += fB.y;
    }
    if (tg == 0) {
        sa[6][0] += __half2float(bias_s[rA][48]);
        sa[6][2] += __half2float(bias_s[rB][48]);
        sa[6][1] = -1e30f; sa[6][3] = -1e30f;
    } else {
        sa[6][0] = sa[6][1] = sa[6][2] = sa[6][3] = -1e30f;
    }
    sa[7][0] = sa[7][1] = sa[7][2] = sa[7][3] = -1e30f;

    if (need_mask) {
        const int labA = lab[grp][rA], labB = lab[grp][rB];
        #pragma unroll
        for (int ni = 0; ni < 7; ni++) {
            #pragma unroll
            for (int cc = 0; cc < 2; cc++) {
                int m = 8 * ni + 2 * tg + cc;
                if (m < NTOK) {
                    int lm = lab[grp][m];
                    if (lm != labA) sa[ni][cc] -= 100.f;
                    if (lm != labB) sa[ni][cc + 2] -= 100.f;
                }
            }
        }
    }

    // ---- softmax ----
    float mxA = -1e30f, mxB = -1e30f;
    #pragma unroll
    for (int ni = 0; ni < 8; ni++) {
        mxA = fmaxf(mxA, fmaxf(sa[ni][0], sa[ni][1]));
        mxB = fmaxf(mxB, fmaxf(sa[ni][2], sa[ni][3]));
    }
    #pragma unroll
    for (int o = 1; o <= 2; o <<= 1) {
        mxA = fmaxf(mxA, __shfl_xor_sync(0xffffffffu, mxA, o));
        mxB = fmaxf(mxB, __shfl_xor_sync(0xffffffffu, mxB, o));
    }
    float smA = 0.f, smB = 0.f;
    #pragma unroll
    for (int ni = 0; ni < 8; ni++) {
        sa[ni][0] = __expf(sa[ni][0] - mxA); smA += sa[ni][0];
        sa[ni][1] = __expf(sa[ni][1] - mxA); smA += sa[ni][1];
        sa[ni][2] = __expf(sa[ni][2] - mxB); smB += sa[ni][2];
        sa[ni][3] = __expf(sa[ni][3] - mxB); smB += sa[ni][3];
    }
    #pragma unroll
    for (int o = 1; o <= 2; o <<= 1) {
        smA += __shfl_xor_sync(0xffffffffu, smA, o);
        smB += __shfl_xor_sync(0xffffffffu, smB, o);
    }
    const float ivA = 1.0f / smA, ivB = 1.0f / smB;

    // ---- pack P ----
    unsigned ap[4][4];
    #pragma unroll
    for (int kc = 0; kc < 4; kc++) {
        ap[kc][0] = h2_as_u32(__floats2half2_rn(sa[2 * kc][0] * ivA, sa[2 * kc][1] * ivA));
        ap[kc][1] = h2_as_u32(__floats2half2_rn(sa[2 * kc][2] * ivB, sa[2 * kc][3] * ivB));
        ap[kc][2] = h2_as_u32(__floats2half2_rn(sa[2 * kc + 1][0] * ivA, sa[2 * kc + 1][1] * ivA));
        ap[kc][3] = h2_as_u32(__floats2half2_rn(sa[2 * kc + 1][2] * ivB, sa[2 * kc + 1][3] * ivB));
    }

    // ---- O = P V ----
    float oa[4][4];
    #pragma unroll
    for (int i = 0; i < 4; i++)
        #pragma unroll
        for (int r = 0; r < 4; r++) oa[i][r] = 0.f;

    #pragma unroll
    for (int kc = 0; kc < 4; kc++) {
        #pragma unroll
        for (int nt = 0; nt < 2; nt++) {
            unsigned r4[4];
            ldsm4t(r4, smem_u32(&Vs[grp][kc * 16 + t_row][nt * 16 + t_col]));
            unsigned b0[2] = {r4[0], r4[1]};
            unsigned b1[2] = {r4[2], r4[3]};
            mma_fp16(oa[2 * nt], ap[kc], b0);
            mma_fp16(oa[2 * nt + 1], ap[kc], b1);
        }
    }

    // ---- store ----
    #pragma unroll
    for (int ni = 0; ni < 4; ni++) {
        int d0 = 8 * ni + 2 * tg;
        if (rowA < NTOK)
            *(__half2*)&out[((long)wg * NTOK + rowA) * CDIM + head * 32 + d0] =
                __floats2half2_rn(oa[ni][0], oa[ni][1]);
        if (rowB < NTOK)
            *(__half2*)&out[((long)wg * NTOK + rowB) * CDIM + head * 32 + d0] =
                __floats2half2_rn(oa[ni][2], oa[ni][3]);
    }
}

// ---------------- launch ----------------
extern "C" void kernel_launch(void* const* d_in, const int* in_sizes, int n_in,
                              void* d_out, int out_size) {
    const float* x      = (const float*)d_in[0];
    const float* qkv_w  = (const float*)d_in[1];
    const float* qkv_b  = (const float*)d_in[2];
    const float* proj_w = (const float*)d_in[3];
    const float* proj_b = (const float*)d_in[4];
    const float* rpb    = (const float*)d_in[5];
    const float* n1g    = (const float*)d_in[6];
    const float* n1b    = (const float*)d_in[7];
    const float* n2g    = (const float*)d_in[8];
    const float* n2b    = (const float*)d_in[9];
    const float* fc1_w  = (const float*)d_in[10];
    const float* fc1_b  = (const float*)d_in[11];
    const float* fc2_w  = (const float*)d_in[12];
    const float* fc2_b  = (const float*)d_in[13];
    float* out = (float*)d_out;

    __half *qkvh, *atth, *hidh, *wqkv, *wproj, *wfc1, *wfc2, *biasMh;
    cudaGetSymbolAddress((void**)&qkvh, g_qkvh);
    cudaGetSymbolAddress((void**)&atth, g_atth);
    cudaGetSymbolAddress((void**)&hidh, g_hidh);
    cudaGetSymbolAddress((void**)&wqkv, g_wqkv);
    cudaGetSymbolAddress((void**)&wproj, g_wproj);
    cudaGetSymbolAddress((void**)&wfc1, g_wfc1);
    cudaGetSymbolAddress((void**)&wfc2, g_wfc2);
    cudaGetSymbolAddress((void**)&biasMh, g_biasMh);
    float* ywin = (float*)qkvh;   // reuse qkv scratch after attention

    static bool attr_set = false;
    if (!attr_set) {
        cudaFuncSetAttribute(ln_gemm<3, true, false>,
                             cudaFuncAttributeMaxDynamicSharedMemorySize, DSMEM_LNGEMM);
        cudaFuncSetAttribute(proj_ln_fc1,
                             cudaFuncAttributeMaxDynamicSharedMemorySize, DSMEM_PLF);
        cudaFuncSetAttribute(attn_mma,
                             cudaFuncAttributeMaxDynamicSharedMemorySize, DSMEM_ATT);
        attr_set = true;
    }

    convert_all<<<768, 256>>>(qkv_w, proj_w, fc1_w, fc2_w, wqkv, wproj, wfc1, wfc2);
    bias_pre<<<(NHEAD * NTOK * NTOK + 255) / 256, 256>>>(rpb, biasMh);

    ln_gemm<3, true, false><<<MROWS / 128, 256, DSMEM_LNGEMM>>>(
        x, wqkv, qkv_b, n1g, n1b, qkvh);
    attn_mma<<<dim3(BIMG * NWIN / 4, NHEAD), 512, DSMEM_ATT>>>(qkvh, biasMh, atth);
    proj_ln_fc1<<<MROWS / 128, 256, DSMEM_PLF>>>(
        atth, wproj, proj_b, x, n2g, n2b, wfc1, fc1_b, ywin, hidh);
    gemm_fc2<<<MROWS / 128, 256>>>(hidh, wfc2, fc2_b, out, ywin);
}

// round 15
// speedup vs baseline: 6.8773x; 1.0932x over previous
#include <cuda_runtime.h>
#include <cuda_fp16.h>
#include <cstdint>
#include <math.h>

#define HH 56
#define WW 56
#define WS 7
#define SH 3
#define NHEAD 4
#define HD 32
#define CDIM 128
#define NTOK 49
#define NWIN 64
#define BIMG 64
#define MROWS (BIMG * NWIN * NTOK)   // 200704
#define LSEQ (HH * WW)
#define EPS 1e-5f

// ---------------- scratch ----------------
__device__ __half g_qkvh[(size_t)MROWS * 3 * CDIM];
__device__ __half g_atth[(size_t)MROWS * CDIM];
__device__ __half g_wqkv[384 * 128];
__device__ __half g_wproj[128 * 128];
__device__ __half g_wfc1[512 * 128];
__device__ __half g_wfc2[128 * 512];
__device__ __half g_biasMh[NHEAD * NTOK * NTOK];

// ---------------- ptx helpers ----------------
__device__ __forceinline__ unsigned smem_u32(const void* p) {
    return (unsigned)__cvta_generic_to_shared(p);
}
__device__ __forceinline__ unsigned h2_as_u32(__half2 h) {
    return *(unsigned*)&h;
}
__device__ __forceinline__ void cp16(unsigned dst, const void* src) {
    asm volatile("cp.async.cg.shared.global [%0], [%1], 16;" :: "r"(dst), "l"(src));
}
__device__ __forceinline__ void cp_commit() { asm volatile("cp.async.commit_group;"); }
__device__ __forceinline__ void cp_wait0() { asm volatile("cp.async.wait_group 0;"); }

__device__ __forceinline__ void ldsm4(unsigned* r, unsigned addr) {
    asm volatile("ldmatrix.sync.aligned.m8n8.x4.shared.b16 {%0,%1,%2,%3}, [%4];"
                 : "=r"(r[0]), "=r"(r[1]), "=r"(r[2]), "=r"(r[3]) : "r"(addr));
}
__device__ __forceinline__ void ldsm4t(unsigned* r, unsigned addr) {
    asm volatile("ldmatrix.sync.aligned.m8n8.x4.trans.shared.b16 {%0,%1,%2,%3}, [%4];"
                 : "=r"(r[0]), "=r"(r[1]), "=r"(r[2]), "=r"(r[3]) : "r"(addr));
}
__device__ __forceinline__ void mma_fp16(float* d, const unsigned* a, const unsigned* b) {
    asm volatile(
        "mma.sync.aligned.m16n8k16.row.col.f32.f16.f16.f32 "
        "{%0,%1,%2,%3}, {%4,%5,%6,%7}, {%8,%9}, {%0,%1,%2,%3};\n"
        : "+f"(d[0]), "+f"(d[1]), "+f"(d[2]), "+f"(d[3])
        : "r"(a[0]), "r"(a[1]), "r"(a[2]), "r"(a[3]), "r"(b[0]), "r"(b[1]));
}

// ---------------- fused weight convert + transpose ----------------
__global__ void convert_all(const float* __restrict__ qkv_w, const float* __restrict__ proj_w,
                            const float* __restrict__ fc1_w, const float* __restrict__ fc2_w,
                            __half* __restrict__ wqkv, __half* __restrict__ wproj,
                            __half* __restrict__ wfc1, __half* __restrict__ wfc2) {
    int i = blockIdx.x * 256 + threadIdx.x;
    if (i < 49152) {
        int k = i / 384, n = i % 384;
        wqkv[n * 128 + k] = __float2half(qkv_w[i]);
    } else if (i < 65536) {
        int j = i - 49152;
        int k = j / 128, n = j % 128;
        wproj[n * 128 + k] = __float2half(proj_w[j]);
    } else if (i < 131072) {
        int j = i - 65536;
        int k = j / 512, n = j % 512;
        wfc1[n * 128 + k] = __float2half(fc1_w[j]);
    } else if (i < 196608) {
        int j = i - 131072;
        int k = j / 128, n = j % 128;
        wfc2[n * 512 + k] = __float2half(fc2_w[j]);
    }
}

// ---------------- relative-position bias precompute (half) ----------------
__global__ void bias_pre(const float* __restrict__ rpb, __half* __restrict__ biasMh) {
    int i = blockIdx.x * 256 + threadIdx.x;
    if (i < NHEAD * NTOK * NTOK) {
        int h = i / (NTOK * NTOK);
        int r = i % (NTOK * NTOK);
        int n = r / NTOK, m = r % NTOK;
        int ridx = (n / WS - m / WS + WS - 1) * (2 * WS - 1) + (n % WS - m % WS + WS - 1);
        biasMh[i] = __float2half(rpb[ridx * NHEAD + h]);
    }
}

// ============ fused LN1 + roll/partition + QKV GEMM ============
#define DSMEM_LNGEMM (34816 * 2)
__global__ void __launch_bounds__(256, 2)
ln_gemm(const float* __restrict__ X, const __half* __restrict__ Bt,
        const float* __restrict__ bias, const float* __restrict__ lng,
        const float* __restrict__ lnb, __half* __restrict__ C) {
    extern __shared__ char dyn[];
    __half (*As)[136] = (__half(*)[136])dyn;
    __half (*Bs)[136] = (__half(*)[136])(dyn + 34816);
    float (*stage)[128] = (float(*)[128])(dyn + 34816);

    const int tid = threadIdx.x;
    const int lane = tid & 31, wid = tid >> 5;
    const int m0 = blockIdx.x * 128;

    for (int rs = 0; rs < 128; rs += 32) {
        #pragma unroll
        for (int t = 0; t < 4; t++) {
            int i = tid + t * 256;
            int row = i >> 5;
            int c4 = (i & 31) * 4;
            int R = m0 + rs + row;
            int bi = R / (NWIN * NTOK);
            int tt = R % (NWIN * NTOK);
            int win = tt / NTOK, n = tt % NTOK;
            int hh = (win / 8) * WS + n / WS;
            int ww = (win % 8) * WS + n % WS;
            long srow = (long)bi * LSEQ + ((hh + SH) % HH) * WW + (ww + SH) % WW;
            *(float4*)&stage[row][c4] = *(const float4*)&X[srow * CDIM + c4];
        }
        __syncthreads();
        #pragma unroll
        for (int rr = 0; rr < 4; rr++) {
            int row = wid * 4 + rr;
            float v[4];
            #pragma unroll
            for (int t = 0; t < 4; t++) v[t] = stage[row][lane + t * 32];
            float s = v[0] + v[1] + v[2] + v[3];
            float s2 = v[0] * v[0] + v[1] * v[1] + v[2] * v[2] + v[3] * v[3];
            #pragma unroll
            for (int o = 16; o; o >>= 1) {
                s += __shfl_xor_sync(0xffffffffu, s, o);
                s2 += __shfl_xor_sync(0xffffffffu, s2, o);
            }
            float mu = s * (1.f / 128.f);
            float inv = rsqrtf(s2 * (1.f / 128.f) - mu * mu + EPS);
            #pragma unroll
            for (int t = 0; t < 4; t++) {
                int c = lane + t * 32;
                As[rs + row][c] = __float2half((v[t] - mu) * inv * lng[c] + lnb[c]);
            }
        }
        __syncthreads();
    }

    const int a_row = (lane & 7) + ((lane >> 3) & 1) * 8;
    const int a_kc  = ((lane >> 4) & 1) * 8;
    const int b_row = (lane & 7) + ((lane >> 4) & 1) * 8;
    const int b_kc  = ((lane >> 3) & 1) * 8;
    const int wm = (wid & 1) * 64;
    const int wn = (wid >> 1) * 32;
    const int g = lane >> 2, tg = lane & 3;

    for (int c = 0; c < 3; c++) {
        #pragma unroll
        for (int t = 0; t < 8; t++) {
            int i = tid + t * 256;
            int row = i >> 4;
            int col = (i & 15) * 8;
            cp16(smem_u32(&Bs[row][col]), &Bt[(long)(c * 128 + row) * CDIM + col]);
        }
        cp_commit();
        cp_wait0();
        __syncthreads();

        float acc[4][4][4];
        #pragma unroll
        for (int i = 0; i < 4; i++)
            #pragma unroll
            for (int j = 0; j < 4; j++)
                #pragma unroll
                for (int r = 0; r < 4; r++) acc[i][j][r] = 0.f;

        #pragma unroll
        for (int it = 0; it < 8; it++) {
            const int k0 = it * 16;
            unsigned a_frag[4][4], b_frag[4][2];
            #pragma unroll
            for (int mi = 0; mi < 4; mi++)
                ldsm4(a_frag[mi], smem_u32(&As[wm + mi * 16 + a_row][k0 + a_kc]));
            #pragma unroll
            for (int n2 = 0; n2 < 2; n2++) {
                unsigned r4[4];
                ldsm4(r4, smem_u32(&Bs[wn + n2 * 16 + b_row][k0 + b_kc]));
                b_frag[2 * n2][0] = r4[0]; b_frag[2 * n2][1] = r4[1];
                b_frag[2 * n2 + 1][0] = r4[2]; b_frag[2 * n2 + 1][1] = r4[3];
            }
            #pragma unroll
            for (int mi = 0; mi < 4; mi++)
                #pragma unroll
                for (int ni = 0; ni < 4; ni++)
                    mma_fp16(acc[mi][ni], a_frag[mi], b_frag[ni]);
        }
        __syncthreads();

        #pragma unroll
        for (int mi = 0; mi < 4; mi++) {
            #pragma unroll
            for (int hf = 0; hf < 2; hf++) {
                int row = m0 + wm + mi * 16 + g + hf * 8;
                #pragma unroll
                for (int ni = 0; ni < 4; ni++) {
                    int col = c * 128 + wn + ni * 8 + 2 * tg;
                    float v0 = acc[mi][ni][hf * 2 + 0] + bias[col];
                    float v1 = acc[mi][ni][hf * 2 + 1] + bias[col + 1];
                    *(__half2*)&C[(long)row * 384 + col] = __floats2half2_rn(v0, v1);
                }
            }
        }
    }
}

// ============ MEGA: proj + residual + LN2 + fc1(GELU) + fc2 + residual + scatter ============
#define DSMEM_MEGA (34816 * 3 + 4096)
__global__ void __launch_bounds__(256)
mega_mlp(const __half* __restrict__ atth, const __half* __restrict__ wproj,
         const float* __restrict__ pbias, const float* __restrict__ x,
         const float* __restrict__ lng, const float* __restrict__ lnb,
         const __half* __restrict__ wfc1, const float* __restrict__ f1bias,
         const __half* __restrict__ wfc2, const float* __restrict__ f2bias,
         float* __restrict__ out) {
    extern __shared__ char dyn[];
    __half (*As)[136] = (__half(*)[136])dyn;
    __half (*Bs)[136] = (__half(*)[136])(dyn + 34816);
    __half (*Hs)[136] = (__half(*)[136])(dyn + 69632);
    float (*redS)[128] = (float(*)[128])(dyn + 104448);
    float (*redQ)[128] = (float(*)[128])(dyn + 104448 + 2048);

    const int tid = threadIdx.x;
    const int lane = tid & 31, wid = tid >> 5;
    const int m0 = blockIdx.x * 128;

    const int a_row = (lane & 7) + ((lane >> 3) & 1) * 8;
    const int a_kc  = ((lane >> 4) & 1) * 8;
    const int b_row = (lane & 7) + ((lane >> 4) & 1) * 8;
    const int b_kc  = ((lane >> 3) & 1) * 8;
    const int wm = (wid & 1) * 64;
    const int wn = (wid >> 1) * 32;
    const int g = lane >> 2, tg = lane & 3;

    // ---- stage 1: proj GEMM ----
    #pragma unroll
    for (int t = 0; t < 8; t++) {
        int i = tid + t * 256;
        int row = i >> 4;
        int col = (i & 15) * 8;
        cp16(smem_u32(&As[row][col]), &atth[(long)(m0 + row) * CDIM + col]);
        cp16(smem_u32(&Bs[row][col]), &wproj[row * CDIM + col]);
    }
    cp_commit();
    cp_wait0();
    __syncthreads();

    float acc[4][4][4];
    #pragma unroll
    for (int i = 0; i < 4; i++)
        #pragma unroll
        for (int j = 0; j < 4; j++)
            #pragma unroll
            for (int r = 0; r < 4; r++) acc[i][j][r] = 0.f;

    #pragma unroll
    for (int it = 0; it < 8; it++) {
        const int k0 = it * 16;
        unsigned a_frag[4][4], b_frag[4][2];
        #pragma unroll
        for (int mi = 0; mi < 4; mi++)
            ldsm4(a_frag[mi], smem_u32(&As[wm + mi * 16 + a_row][k0 + a_kc]));
        #pragma unroll
        for (int n2 = 0; n2 < 2; n2++) {
            unsigned r4[4];
            ldsm4(r4, smem_u32(&Bs[wn + n2 * 16 + b_row][k0 + b_kc]));
            b_frag[2 * n2][0] = r4[0]; b_frag[2 * n2][1] = r4[1];
            b_frag[2 * n2 + 1][0] = r4[2]; b_frag[2 * n2 + 1][1] = r4[3];
        }
        #pragma unroll
        for (int mi = 0; mi < 4; mi++)
            #pragma unroll
            for (int ni = 0; ni < 4; ni++)
                mma_fp16(acc[mi][ni], a_frag[mi], b_frag[ni]);
    }
    __syncthreads();

    // ---- stage 2: y = acc + pbias + x[gather]; LN partial sums ----
    #pragma unroll
    for (int mi = 0; mi < 4; mi++) {
        #pragma unroll
        for (int hf = 0; hf < 2; hf++) {
            int lrow = wm + mi * 16 + g + hf * 8;
            int R = m0 + lrow;
            int bi = R / (NWIN * NTOK);
            int tt = R % (NWIN * NTOK);
            int win = tt / NTOK, n = tt % NTOK;
            int hh = (win / 8) * WS + n / WS;
            int ww = (win % 8) * WS + n % WS;
            long srow = (long)bi * LSEQ + ((hh + SH) % HH) * WW + (ww + SH) % WW;

            float s = 0.f, s2 = 0.f;
            #pragma unroll
            for (int ni = 0; ni < 4; ni++) {
                int col = wn + ni * 8 + 2 * tg;
                float2 xr = *(const float2*)&x[srow * CDIM + col];
                float v0 = acc[mi][ni][hf * 2 + 0] + pbias[col] + xr.x;
                float v1 = acc[mi][ni][hf * 2 + 1] + pbias[col + 1] + xr.y;
                acc[mi][ni][hf * 2 + 0] = v0;
                acc[mi][ni][hf * 2 + 1] = v1;
                s += v0 + v1;
                s2 += v0 * v0 + v1 * v1;
            }
            s += __shfl_xor_sync(0xffffffffu, s, 1);
            s += __shfl_xor_sync(0xffffffffu, s, 2);
            s2 += __shfl_xor_sync(0xffffffffu, s2, 1);
            s2 += __shfl_xor_sync(0xffffffffu, s2, 2);
            if (tg == 0) {
                redS[wid >> 1][lrow] = s;
                redQ[wid >> 1][lrow] = s2;
            }
        }
    }
    __syncthreads();

    // ---- stage 3: LN'd -> As; acc becomes out accumulator (y + fc2 bias) ----
    #pragma unroll
    for (int mi = 0; mi < 4; mi++) {
        #pragma unroll
        for (int hf = 0; hf < 2; hf++) {
            int lrow = wm + mi * 16 + g + hf * 8;
            float s = redS[0][lrow] + redS[1][lrow] + redS[2][lrow] + redS[3][lrow];
            float s2 = redQ[0][lrow] + redQ[1][lrow] + redQ[2][lrow] + redQ[3][lrow];
            float mu = s * (1.f / 128.f);
            float inv = rsqrtf(s2 * (1.f / 128.f) - mu * mu + EPS);
            #pragma unroll
            for (int ni = 0; ni < 4; ni++) {
                int col = wn + ni * 8 + 2 * tg;
                float y0 = acc[mi][ni][hf * 2 + 0];
                float y1 = acc[mi][ni][hf * 2 + 1];
                float v0 = (y0 - mu) * inv * lng[col] + lnb[col];
                float v1 = (y1 - mu) * inv * lng[col + 1] + lnb[col + 1];
                *(__half2*)&As[lrow][col] = __floats2half2_rn(v0, v1);
                acc[mi][ni][hf * 2 + 0] = y0 + f2bias[col];
                acc[mi][ni][hf * 2 + 1] = y1 + f2bias[col + 1];
            }
        }
    }
    __syncthreads();

    // ---- stage 4: 4 chunks of fc1(GELU) -> Hs -> fc2 accumulate into acc ----
    for (int c = 0; c < 4; c++) {
        #pragma unroll
        for (int t = 0; t < 8; t++) {
            int i = tid + t * 256;
            int row = i >> 4;
            int col = (i & 15) * 8;
            cp16(smem_u32(&Bs[row][col]), &wfc1[(long)(c * 128 + row) * CDIM + col]);
        }
        cp_commit();
        cp_wait0();
        __syncthreads();

        float fa[4][4][4];
        #pragma unroll
        for (int i = 0; i < 4; i++)
            #pragma unroll
            for (int j = 0; j < 4; j++)
                #pragma unroll
                for (int r = 0; r < 4; r++) fa[i][j][r] = 0.f;

        #pragma unroll
        for (int it = 0; it < 8; it++) {
            const int k0 = it * 16;
            unsigned a_frag[4][4], b_frag[4][2];
            #pragma unroll
            for (int mi = 0; mi < 4; mi++)
                ldsm4(a_frag[mi], smem_u32(&As[wm + mi * 16 + a_row][k0 + a_kc]));
            #pragma unroll
            for (int n2 = 0; n2 < 2; n2++) {
                unsigned r4[4];
                ldsm4(r4, smem_u32(&Bs[wn + n2 * 16 + b_row][k0 + b_kc]));
                b_frag[2 * n2][0] = r4[0]; b_frag[2 * n2][1] = r4[1];
                b_frag[2 * n2 + 1][0] = r4[2]; b_frag[2 * n2 + 1][1] = r4[3];
            }
            #pragma unroll
            for (int mi = 0; mi < 4; mi++)
                #pragma unroll
                for (int ni = 0; ni < 4; ni++)
                    mma_fp16(fa[mi][ni], a_frag[mi], b_frag[ni]);
        }
        __syncthreads();

        #pragma unroll
        for (int t = 0; t < 8; t++) {
            int i = tid + t * 256;
            int row = i >> 4;
            int col = (i & 15) * 8;
            cp16(smem_u32(&Bs[row][col]), &wfc2[(long)row * 512 + c * 128 + col]);
        }
        cp_commit();

        #pragma unroll
        for (int mi = 0; mi < 4; mi++) {
            #pragma unroll
            for (int hf = 0; hf < 2; hf++) {
                int lrow = wm + mi * 16 + g + hf * 8;
                #pragma unroll
                for (int ni = 0; ni < 4; ni++) {
                    int col = c * 128 + wn + ni * 8 + 2 * tg;
                    float v0 = fa[mi][ni][hf * 2 + 0] + f1bias[col];
                    float v1 = fa[mi][ni][hf * 2 + 1] + f1bias[col + 1];
                    v0 = 0.5f * v0 * (1.0f + erff(v0 * 0.70710678118654752f));
                    v1 = 0.5f * v1 * (1.0f + erff(v1 * 0.70710678118654752f));
                    *(__half2*)&Hs[lrow][(col & 127)] = __floats2half2_rn(v0, v1);
                }
            }
        }
        cp_wait0();
        __syncthreads();

        #pragma unroll
        for (int it = 0; it < 8; it++) {
            const int k0 = it * 16;
            unsigned a_frag[4][4], b_frag[4][2];
            #pragma unroll
            for (int mi = 0; mi < 4; mi++)
                ldsm4(a_frag[mi], smem_u32(&Hs[wm + mi * 16 + a_row][k0 + a_kc]));
            #pragma unroll
            for (int n2 = 0; n2 < 2; n2++) {
                unsigned r4[4];
                ldsm4(r4, smem_u32(&Bs[wn + n2 * 16 + b_row][k0 + b_kc]));
                b_frag[2 * n2][0] = r4[0]; b_frag[2 * n2][1] = r4[1];
                b_frag[2 * n2 + 1][0] = r4[2]; b_frag[2 * n2 + 1][1] = r4[3];
            }
            #pragma unroll
            for (int mi = 0; mi < 4; mi++)
                #pragma unroll
                for (int ni = 0; ni < 4; ni++)
                    mma_fp16(acc[mi][ni], a_frag[mi], b_frag[ni]);
        }
        __syncthreads();
    }

    // ---- stage 5: scatter out ----
    #pragma unroll
    for (int mi = 0; mi < 4; mi++) {
        #pragma unroll
        for (int hf = 0; hf < 2; hf++) {
            int R = m0 + wm + mi * 16 + g + hf * 8;
            int bi = R / (NWIN * NTOK);
            int tt = R % (NWIN * NTOK);
            int win = tt / NTOK, n = tt % NTOK;
            int hh = (win / 8) * WS + n / WS;
            int ww = (win % 8) * WS + n % WS;
            long drow = (long)bi * LSEQ + ((hh + SH) % HH) * WW + (ww + SH) % WW;
            #pragma unroll
            for (int ni = 0; ni < 4; ni++) {
                int col = wn + ni * 8 + 2 * tg;
                *(float2*)&out[drow * CDIM + col] =
                    make_float2(acc[mi][ni][hf * 2 + 0], acc[mi][ni][hf * 2 + 1]);
            }
        }
    }
}

// ============ tensor-core window attention ============
#define ATT_TILE (64 * 40)
#define ATT_SM_Q 0
#define ATT_SM_K (4 * ATT_TILE * 2)
#define ATT_SM_V (8 * ATT_TILE * 2)
#define ATT_SM_B (12 * ATT_TILE * 2)
#define ATT_SM_L (ATT_SM_B + 49 * 50 * 2 + 28)
#define DSMEM_ATT (ATT_SM_L + 4 * 64 * 4)
__global__ void __launch_bounds__(512)
attn_mma(const __half* __restrict__ qkv,
         const __half* __restrict__ biasMh,
         __half* __restrict__ out) {
    extern __shared__ char dynA[];
    __half (*Qs)[64][40] = (__half(*)[64][40])(dynA + ATT_SM_Q);
    __half (*Ks)[64][40] = (__half(*)[64][40])(dynA + ATT_SM_K);
    __half (*Vs)[64][40] = (__half(*)[64][40])(dynA + ATT_SM_V);
    __half (*bias_s)[50] = (__half(*)[50])(dynA + ATT_SM_B);
    int (*lab)[64] = (int(*)[64])(dynA + ATT_SM_L);

    const int head = blockIdx.y;
    const int tid = threadIdx.x;
    const int gtid = tid & 127;
    const int grp = tid >> 7;
    const int wg = blockIdx.x * 4 + grp;
    const int lane = tid & 31;
    const int lwid = (tid >> 5) & 3;
    const int g = lane >> 2, tg = lane & 3;

    const int wi = wg & (NWIN - 1);
    const bool need_mask = ((wi >> 3) == 7) || ((wi & 7) == 7);

    for (int i = gtid; i < 15 * 40; i += 128)
        Vs[grp][49 + i / 40][i % 40] = __float2half(0.f);

    if (need_mask && gtid < 64) {
        int t = gtid < NTOK ? gtid : 0;
        int h = (wi / 8) * WS + t / WS;
        int w = (wi % 8) * WS + t % WS;
        int rh = (h < HH - WS) ? 0 : ((h < HH - SH) ? 1 : 2);
        int rw = (w < WW - WS) ? 0 : ((w < WW - SH) ? 1 : 2);
        lab[grp][gtid] = rh * 3 + rw;
    }

    for (int i = tid; i < NTOK * NTOK; i += 512) {
        int n = i / NTOK, m = i % NTOK;
        bias_s[n][m] = biasMh[head * NTOK * NTOK + i];
    }

    const __half2 scale2 = __float2half2_rn(0.1767766952966369f);
    for (int i = gtid; i < NTOK * 4; i += 128) {
        int r = i >> 2, c8 = (i & 3) * 8;
        long base = ((long)wg * NTOK + r) * 384 + c8 + head * 32;
        uint4 qv = *(const uint4*)&qkv[base];
        __half2* qh = (__half2*)&qv;
        #pragma unroll
        for (int j = 0; j < 4; j++) qh[j] = __hmul2(qh[j], scale2);
        *(uint4*)&Qs[grp][r][c8] = qv;
        *(uint4*)&Ks[grp][r][c8] = *(const uint4*)&qkv[base + 128];
        *(uint4*)&Vs[grp][r][c8] = *(const uint4*)&qkv[base + 256];
    }
    __syncthreads();

    const int a_row = (lane & 7) + ((lane >> 3) & 1) * 8;
    const int a_kc  = ((lane >> 4) & 1) * 8;
    const int b_row = (lane & 7) + ((lane >> 4) & 1) * 8;
    const int b_kc  = ((lane >> 3) & 1) * 8;
    const int t_row = (lane & 7) + ((lane >> 3) & 1) * 8;
    const int t_col = (lane >> 4) * 8;
    const int w16 = lwid * 16;

    float sa[8][4];
    #pragma unroll
    for (int i = 0; i < 8; i++)
        #pragma unroll
        for (int r = 0; r < 4; r++) sa[i][r] = 0.f;

    #pragma unroll
    for (int kc = 0; kc < 2; kc++) {
        unsigned aq[4];
        ldsm4(aq, smem_u32(&Qs[grp][w16 + a_row][kc * 16 + a_kc]));
        #pragma unroll
        for (int nt = 0; nt < 4; nt++) {
            unsigned r4[4];
            ldsm4(r4, smem_u32(&Ks[grp][nt * 16 + b_row][kc * 16 + b_kc]));
            unsigned b0[2] = {r4[0], r4[1]};
            unsigned b1[2] = {r4[2], r4[3]};
            mma_fp16(sa[2 * nt], aq, b0);
            mma_fp16(sa[2 * nt + 1], aq, b1);
        }
    }

    const int rowA = w16 + g;
    const int rowB = w16 + g + 8;
    const int rA = rowA < NTOK ? rowA : 0;
    const int rB = rowB < NTOK ? rowB : 0;
    #pragma unroll
    for (int ni = 0; ni < 6; ni++) {
        float2 fA = __half22float2(*(__half2*)&bias_s[rA][8 * ni + 2 * tg]);
        float2 fB = __half22float2(*(__half2*)&bias_s[rB][8 * ni + 2 * tg]);
        sa[ni][0] += fA.x; sa[ni][1] += fA.y;
        sa[ni][2] += fB.x; sa[ni][3] += fB.y;
    }
    if (tg == 0) {
        sa[6][0] += __half2float(bias_s[rA][48]);
        sa[6][2] += __half2float(bias_s[rB][48]);
        sa[6][1] = -1e30f; sa[6][3] = -1e30f;
    } else {
        sa[6][0] = sa[6][1] = sa[6][2] = sa[6][3] = -1e30f;
    }
    sa[7][0] = sa[7][1] = sa[7][2] = sa[7][3] = -1e30f;

    if (need_mask) {
        const int labA = lab[grp][rA], labB = lab[grp][rB];
        #pragma unroll
        for (int ni = 0; ni < 7; ni++) {
            #pragma unroll
            for (int cc = 0; cc < 2; cc++) {
                int m = 8 * ni + 2 * tg + cc;
                if (m < NTOK) {
                    int lm = lab[grp][m];
                    if (lm != labA) sa[ni][cc] -= 100.f;
                    if (lm != labB) sa[ni][cc + 2] -= 100.f;
                }
            }
        }
    }

    float mxA = -1e30f, mxB = -1e30f;
    #pragma unroll
    for (int ni = 0; ni < 8; ni++) {
        mxA = fmaxf(mxA, fmaxf(sa[ni][0], sa[ni][1]));
        mxB = fmaxf(mxB, fmaxf(sa[ni][2], sa[ni][3]));
    }
    #pragma unroll
    for (int o = 1; o <= 2; o <<= 1) {
        mxA = fmaxf(mxA, __shfl_xor_sync(0xffffffffu, mxA, o));
        mxB = fmaxf(mxB, __shfl_xor_sync(0xffffffffu, mxB, o));
    }
    float smA = 0.f, smB = 0.f;
    #pragma unroll
    for (int ni = 0; ni < 8; ni++) {
        sa[ni][0] = __expf(sa[ni][0] - mxA); smA += sa[ni][0];
        sa[ni][1] = __expf(sa[ni][1] - mxA); smA += sa[ni][1];
        sa[ni][2] = __expf(sa[ni][2] - mxB); smB += sa[ni][2];
        sa[ni][3] = __expf(sa[ni][3] - mxB); smB += sa[ni][3];
    }
    #pragma unroll
    for (int o = 1; o <= 2; o <<= 1) {
        smA += __shfl_xor_sync(0xffffffffu, smA, o);
        smB += __shfl_xor_sync(0xffffffffu, smB, o);
    }
    const float ivA = 1.0f / smA, ivB = 1.0f / smB;

    unsigned ap[4][4];
    #pragma unroll
    for (int kc = 0; kc < 4; kc++) {
        ap[kc][0] = h2_as_u32(__floats2half2_rn(sa[2 * kc][0] * ivA, sa[2 * kc][1] * ivA));
        ap[kc][1] = h2_as_u32(__floats2half2_rn(sa[2 * kc][2] * ivB, sa[2 * kc][3] * ivB));
        ap[kc][2] = h2_as_u32(__floats2half2_rn(sa[2 * kc + 1][0] * ivA, sa[2 * kc + 1][1] * ivA));
        ap[kc][3] = h2_as_u32(__floats2half2_rn(sa[2 * kc + 1][2] * ivB, sa[2 * kc + 1][3] * ivB));
    }

    float oa[4][4];
    #pragma unroll
    for (int i = 0; i < 4; i++)
        #pragma unroll
        for (int r = 0; r < 4; r++) oa[i][r] = 0.f;

    #pragma unroll
    for (int kc = 0; kc < 4; kc++) {
        #pragma unroll
        for (int nt = 0; nt < 2; nt++) {
            unsigned r4[4];
            ldsm4t(r4, smem_u32(&Vs[grp][kc * 16 + t_row][nt * 16 + t_col]));
            unsigned b0[2] = {r4[0], r4[1]};
            unsigned b1[2] = {r4[2], r4[3]};
            mma_fp16(oa[2 * nt], ap[kc], b0);
            mma_fp16(oa[2 * nt + 1], ap[kc], b1);
        }
    }

    #pragma unroll
    for (int ni = 0; ni < 4; ni++) {
        int d0 = 8 * ni + 2 * tg;
        if (rowA < NTOK)
            *(__half2*)&out[((long)wg * NTOK + rowA) * CDIM + head * 32 + d0] =
                __floats2half2_rn(oa[ni][0], oa[ni][1]);
        if (rowB < NTOK)
            *(__half2*)&out[((long)wg * NTOK + rowB) * CDIM + head * 32 + d0] =
                __floats2half2_rn(oa[ni][2], oa[ni][3]);
    }
}

// ---------------- launch ----------------
extern "C" void kernel_launch(void* const* d_in, const int* in_sizes, int n_in,
                              void* d_out, int out_size) {
    const float* x      = (const float*)d_in[0];
    const float* qkv_w  = (const float*)d_in[1];
    const float* qkv_b  = (const float*)d_in[2];
    const float* proj_w = (const float*)d_in[3];
    const float* proj_b = (const float*)d_in[4];
    const float* rpb    = (const float*)d_in[5];
    const float* n1g    = (const float*)d_in[6];
    const float* n1b    = (const float*)d_in[7];
    const float* n2g    = (const float*)d_in[8];
    const float* n2b    = (const float*)d_in[9];
    const float* fc1_w  = (const float*)d_in[10];
    const float* fc1_b  = (const float*)d_in[11];
    const float* fc2_w  = (const float*)d_in[12];
    const float* fc2_b  = (const float*)d_in[13];
    float* out = (float*)d_out;

    __half *qkvh, *atth, *wqkv, *wproj, *wfc1, *wfc2, *biasMh;
    cudaGetSymbolAddress((void**)&qkvh, g_qkvh);
    cudaGetSymbolAddress((void**)&atth, g_atth);
    cudaGetSymbolAddress((void**)&wqkv, g_wqkv);
    cudaGetSymbolAddress((void**)&wproj, g_wproj);
    cudaGetSymbolAddress((void**)&wfc1, g_wfc1);
    cudaGetSymbolAddress((void**)&wfc2, g_wfc2);
    cudaGetSymbolAddress((void**)&biasMh, g_biasMh);

    cudaFuncSetAttribute(ln_gemm,
                         cudaFuncAttributeMaxDynamicSharedMemorySize, DSMEM_LNGEMM);
    cudaFuncSetAttribute(mega_mlp,
                         cudaFuncAttributeMaxDynamicSharedMemorySize, DSMEM_MEGA);
    cudaFuncSetAttribute(attn_mma,
                         cudaFuncAttributeMaxDynamicSharedMemorySize, DSMEM_ATT);

    convert_all<<<768, 256>>>(qkv_w, proj_w, fc1_w, fc2_w, wqkv, wproj, wfc1, wfc2);
    bias_pre<<<(NHEAD * NTOK * NTOK + 255) / 256, 256>>>(rpb, biasMh);

    ln_gemm<<<MROWS / 128, 256, DSMEM_LNGEMM>>>(x, wqkv, qkv_b, n1g, n1b, qkvh);
    attn_mma<<<dim3(BIMG * NWIN / 4, NHEAD), 512, DSMEM_ATT>>>(qkvh, biasMh, atth);
    mega_mlp<<<MROWS / 128, 256, DSMEM_MEGA>>>(
        atth, wproj, proj_b, x, n2g, n2b, wfc1, fc1_b, wfc2, fc2_b, out);
}